// round 1
// baseline (speedup 1.0000x reference)
#include <cuda_runtime.h>
#include <math.h>
#include <stdint.h>

// ---------------- problem constants ----------------
#define BATCH 2
#define SEQ   1024
#define HDIM  2048
#define NHEAD 16
#define NKVH  4
#define HEADD 128
#define FFN   4096
#define NEXP  8
#define NTOK  (BATCH*SEQ)          // 2048
#define LNEPS 1e-5f

// ---------------- device scratch (static, allowed) ----------------
__device__ float g_xln1[NTOK*HDIM];
__device__ float g_q   [NTOK*NHEAD*HEADD];
__device__ float g_k   [NTOK*NKVH*HEADD];
__device__ float g_v   [NTOK*NKVH*HEADD];
__device__ float g_attn[NTOK*NHEAD*HEADD];
__device__ float g_h   [NTOK*HDIM];
__device__ float g_xln2[NTOK*HDIM];
__device__ int   g_e01 [NTOK*2];
__device__ float g_w01 [NTOK*2];
__device__ int   g_pos01[NTOK*2];
__device__ int   g_counts[NEXP];
__device__ int   g_offsets[NEXP];
__device__ int   g_toklist[2*NTOK];
__device__ int   g_slot01[NTOK*2];
__device__ float g_h1[2*NTOK*FFN];   // 64 MB
__device__ float g_h3[2*NTOK*FFN];   // 64 MB
__device__ float g_eo[2*NTOK*HDIM];  // 32 MB

// ---------------- helpers ----------------
__device__ __forceinline__ float to_tf32(float x){
    uint32_t u; asm("cvt.rna.tf32.f32 %0, %1;" : "=r"(u) : "f"(x));
    return __uint_as_float(u);
}

__device__ __forceinline__ void mma_tf32(float* c, const uint32_t* a, const uint32_t* b){
    asm volatile(
      "mma.sync.aligned.m16n8k8.row.col.f32.tf32.tf32.f32 "
      "{%0,%1,%2,%3}, {%4,%5,%6,%7}, {%8,%9}, {%0,%1,%2,%3};\n"
      : "+f"(c[0]), "+f"(c[1]), "+f"(c[2]), "+f"(c[3])
      : "r"(a[0]), "r"(a[1]), "r"(a[2]), "r"(a[3]), "r"(b[0]), "r"(b[1]));
}

__device__ __forceinline__ float block_sum_256(float v){
    __shared__ float red[8];
    __shared__ float total;
    #pragma unroll
    for (int o = 16; o; o >>= 1) v += __shfl_xor_sync(0xffffffffu, v, o);
    if ((threadIdx.x & 31) == 0) red[threadIdx.x >> 5] = v;
    __syncthreads();
    if (threadIdx.x == 0){
        float s = 0.f;
        #pragma unroll
        for (int i = 0; i < 8; i++) s += red[i];
        total = s;
    }
    __syncthreads();
    float r = total;
    __syncthreads();   // safe for back-to-back reuse
    return r;
}

// ---------------- LayerNorm (one block per row, 256 thr) ----------------
__global__ __launch_bounds__(256)
void ln_kernel(const float* __restrict__ x, const float* __restrict__ w,
               const float* __restrict__ b, float* __restrict__ y){
    long long row = blockIdx.x;
    const float* xr = x + row * HDIM;
    float v[8]; float s = 0.f;
    #pragma unroll
    for (int i = 0; i < 8; i++){ v[i] = xr[threadIdx.x + 256*i]; s += v[i]; }
    float mean = block_sum_256(s) * (1.f/HDIM);
    float ss = 0.f;
    #pragma unroll
    for (int i = 0; i < 8; i++){ float d = v[i]-mean; ss += d*d; }
    float var = block_sum_256(ss) * (1.f/HDIM);
    float rstd = rsqrtf(var + LNEPS);
    #pragma unroll
    for (int i = 0; i < 8; i++){
        int c = threadIdx.x + 256*i;
        y[row*HDIM + c] = (v[i]-mean)*rstd*w[c] + b[c];
    }
}

// ---------------- generic tf32 tensor-core GEMM ----------------
// C[M,N] = A_rows @ B (+bias) (+resid).  A rows may be gathered (rowidx) and
// the M range / output-row base may come from per-expert counts/offsets.
// BM=128 BN=128 BK=32, 256 threads, 8 warps (2x4), warp tile 64x32.
__global__ __launch_bounds__(256)
void gemm_tf32(const float* __restrict__ A, int lda,
               const float* __restrict__ Bbase,
               float* __restrict__ C,
               const float* __restrict__ bias,
               const float* __restrict__ resid,
               int M, int N, int K,
               const int* __restrict__ rowidx,
               const int* __restrict__ counts,
               const int* __restrict__ offsets,
               long long bStride)
{
    __shared__ float As[128][36];   // +4 pad: conflict-free frag loads
    __shared__ float Bs[32][136];   // +8 pad: conflict-free frag loads

    int e = blockIdx.z;
    const float* Bp = Bbase + (long long)e * bStride;
    int rowStart = 0, Mm = M;
    if (counts){ Mm = counts[e]; rowStart = offsets[e]; }
    int mbase = blockIdx.y * 128;
    if (mbase >= Mm) return;
    int nbase = blockIdx.x * 128;

    int tid  = threadIdx.x;
    int lane = tid & 31, wid = tid >> 5;
    int warpM = wid >> 2, warpN = wid & 3;
    int g = lane >> 2, t4 = lane & 3;

    // A load mapping: 32 rows x 8 float4, 4 row-groups
    int ar  = tid >> 3;       // 0..31
    int ac4 = tid & 7;        // 0..7
    const float* aptr[4]; bool aval[4];
    #pragma unroll
    for (int i = 0; i < 4; i++){
        int gr = mbase + ar + 32*i;
        bool valid = (gr < Mm);
        int arow = 0;
        if (valid) arow = rowidx ? rowidx[rowStart + gr] : (rowStart + gr);
        aval[i] = valid;
        aptr[i] = A + (long long)arow * lda + ac4*4;
    }
    int br  = tid >> 5;       // 0..7 (warp id)
    int bc4 = tid & 31;
    int bcol = nbase + bc4*4;

    float acc[16][4];
    #pragma unroll
    for (int i = 0; i < 16; i++)
        #pragma unroll
        for (int j = 0; j < 4; j++) acc[i][j] = 0.f;

    int nk = K >> 5;
    for (int kt = 0; kt < nk; ++kt){
        #pragma unroll
        for (int i = 0; i < 4; i++){
            float4 v4 = make_float4(0.f,0.f,0.f,0.f);
            if (aval[i]) v4 = *(const float4*)(aptr[i] + kt*32);
            int row = ar + 32*i;
            As[row][ac4*4+0] = to_tf32(v4.x);
            As[row][ac4*4+1] = to_tf32(v4.y);
            As[row][ac4*4+2] = to_tf32(v4.z);
            As[row][ac4*4+3] = to_tf32(v4.w);
        }
        #pragma unroll
        for (int i = 0; i < 4; i++){
            int row = br + 8*i;
            float4 v4 = *(const float4*)(Bp + (long long)(kt*32 + row)*N + bcol);
            Bs[row][bc4*4+0] = to_tf32(v4.x);
            Bs[row][bc4*4+1] = to_tf32(v4.y);
            Bs[row][bc4*4+2] = to_tf32(v4.z);
            Bs[row][bc4*4+3] = to_tf32(v4.w);
        }
        __syncthreads();
        #pragma unroll
        for (int ks = 0; ks < 4; ++ks){
            int k0 = ks*8;
            uint32_t af[4][4], bf[4][2];
            #pragma unroll
            for (int ma = 0; ma < 4; ma++){
                int r = warpM*64 + ma*16;
                af[ma][0] = __float_as_uint(As[r+g  ][k0+t4  ]);
                af[ma][1] = __float_as_uint(As[r+g+8][k0+t4  ]);
                af[ma][2] = __float_as_uint(As[r+g  ][k0+t4+4]);
                af[ma][3] = __float_as_uint(As[r+g+8][k0+t4+4]);
            }
            #pragma unroll
            for (int na = 0; na < 4; na++){
                int c = warpN*32 + na*8 + g;
                bf[na][0] = __float_as_uint(Bs[k0+t4  ][c]);
                bf[na][1] = __float_as_uint(Bs[k0+t4+4][c]);
            }
            #pragma unroll
            for (int ma = 0; ma < 4; ma++)
                #pragma unroll
                for (int na = 0; na < 4; na++)
                    mma_tf32(acc[ma*4+na], af[ma], bf[na]);
        }
        __syncthreads();
    }

    #pragma unroll
    for (int ma = 0; ma < 4; ma++){
        #pragma unroll
        for (int na = 0; na < 4; na++){
            float* a4 = acc[ma*4+na];
            #pragma unroll
            for (int cr = 0; cr < 4; cr++){
                int lrow = warpM*64 + ma*16 + g + ((cr >= 2) ? 8 : 0);
                int lcol = warpN*32 + na*8 + 2*t4 + (cr & 1);
                int gr = mbase + lrow;
                if (gr < Mm){
                    long long orow = rowStart + gr;
                    int gc = nbase + lcol;
                    float v = a4[cr];
                    if (bias)  v += bias[gc];
                    if (resid) v += resid[orow*(long long)N + gc];
                    C[orow*(long long)N + gc] = v;
                }
            }
        }
    }
}

// ---------------- RoPE (in place on q,k) ----------------
__global__ __launch_bounds__(256)
void rope_kernel(float* __restrict__ q, float* __restrict__ k,
                 const int* __restrict__ pos_ids){
    int idx = blockIdx.x*256 + threadIdx.x;
    const int total = NTOK*(NHEAD+NKVH)*64;
    if (idx >= total) return;
    int j    = idx & 63;
    int rest = idx >> 6;
    int head = rest % (NHEAD+NKVH);
    int t    = rest / (NHEAD+NKVH);
    float* p;
    if (head < NHEAD) p = q + ((long long)t*NHEAD + head)*HEADD;
    else              p = k + ((long long)t*NKVH + (head-NHEAD))*HEADD;
    // inv_freq = 1e6^(-j/64), computed in double then rounded (matches fp32 pow to ulp)
    double inv = exp((double)j * -0.21586735246819178); // ln(1e6)/64
    float th = (float)pos_ids[t] * (float)inv;
    float sn, cs; sincosf(th, &sn, &cs);
    float x0 = p[j], x1 = p[j+64];
    p[j]    = x0*cs - x1*sn;
    p[j+64] = x1*cs + x0*sn;
}

// ---------------- flash attention (scalar fp32, causal GQA) ----------------
// grid (qtile=16, bh=32), 256 threads, dynamic smem ~122KB
__global__ __launch_bounds__(256)
void flash_kernel(const float* __restrict__ Q, const float* __restrict__ Kx,
                  const float* __restrict__ Vx, const int* __restrict__ amask,
                  float* __restrict__ O)
{
    extern __shared__ float sm[];
    float* Qs   = sm;                // [128][68] (d-major, transposed)
    float* Ks   = Qs + 128*68;       // [128][68]
    float* Vs   = Ks + 128*68;       // [64][132]
    float* Ps   = Vs + 64*132;       // [64][68]
    float* mrow = Ps + 64*68;        // 64
    float* lrow = mrow + 64;         // 64
    float* srow = lrow + 64;         // 64
    int*   mk   = (int*)(srow + 64); // 64

    int qt = blockIdx.x;
    int bh = blockIdx.y;
    int b  = bh >> 4, h = bh & 15;
    int kvh = h >> 2;                // GQA repeat = 4
    int tid = threadIdx.x;
    int ty  = tid >> 4, tx = tid & 15;

    for (int e = tid; e < 64*128; e += 256){
        int qq = e >> 7, d = e & 127;
        int sq = qt*64 + qq;
        Qs[d*68 + qq] = Q[(((long long)(b*SEQ + sq))*NHEAD + h)*HEADD + d];
    }
    if (tid < 64){ mrow[tid] = -1e30f; lrow[tid] = 0.f; }
    float o[4][8];
    #pragma unroll
    for (int i = 0; i < 4; i++)
        #pragma unroll
        for (int j = 0; j < 8; j++) o[i][j] = 0.f;

    const float iscale = 0.08838834764831843f; // 1/sqrt(128)

    for (int kt = 0; kt <= qt; ++kt){
        for (int e = tid; e < 64*128; e += 256){
            int kk = e >> 7, d = e & 127;
            int sk = kt*64 + kk;
            long long base = (((long long)(b*SEQ + sk))*NKVH + kvh)*HEADD + d;
            Ks[d*68 + kk]  = Kx[base];
            Vs[kk*132 + d] = Vx[base];
        }
        if (tid < 64) mk[tid] = amask[b*SEQ + kt*64 + tid];
        __syncthreads();

        // 64x64 score tile: thread (ty,tx) does 4x4
        float sacc[4][4];
        #pragma unroll
        for (int i = 0; i < 4; i++)
            #pragma unroll
            for (int j = 0; j < 4; j++) sacc[i][j] = 0.f;
        for (int d = 0; d < 128; ++d){
            float4 a4 = *(float4*)&Qs[d*68 + ty*4];
            float4 b4 = *(float4*)&Ks[d*68 + tx*4];
            float a[4] = {a4.x, a4.y, a4.z, a4.w};
            float bb[4] = {b4.x, b4.y, b4.z, b4.w};
            #pragma unroll
            for (int i = 0; i < 4; i++)
                #pragma unroll
                for (int j = 0; j < 4; j++) sacc[i][j] += a[i]*bb[j];
        }
        #pragma unroll
        for (int i = 0; i < 4; i++){
            int sq = qt*64 + ty*4 + i;
            #pragma unroll
            for (int j = 0; j < 4; j++){
                int sk = kt*64 + tx*4 + j;
                float vv = sacc[i][j]*iscale;
                if (sk > sq || mk[tx*4+j] == 0) vv = -1e30f;
                Ps[(ty*4+i)*68 + tx*4 + j] = vv;
            }
        }
        __syncthreads();

        // online softmax row update
        if (tid < 64){
            int r = tid;
            float mo = mrow[r], mx = mo;
            #pragma unroll 8
            for (int kk = 0; kk < 64; kk++) mx = fmaxf(mx, Ps[r*68+kk]);
            float sc = __expf(mo - mx);
            float s = 0.f;
            #pragma unroll 8
            for (int kk = 0; kk < 64; kk++){
                float p = __expf(Ps[r*68+kk] - mx);
                Ps[r*68+kk] = p; s += p;
            }
            lrow[r] = lrow[r]*sc + s;
            mrow[r] = mx;
            srow[r] = sc;
        }
        __syncthreads();

        // P @ V accumulate: thread (ty,tx): 4 q-rows x 8 d-cols
        #pragma unroll
        for (int i = 0; i < 4; i++){
            float sc = srow[ty*4+i];
            #pragma unroll
            for (int j = 0; j < 8; j++) o[i][j] *= sc;
        }
        for (int kk = 0; kk < 64; kk++){
            float4 v0 = *(float4*)&Vs[kk*132 + tx*8];
            float4 v1 = *(float4*)&Vs[kk*132 + tx*8 + 4];
            #pragma unroll
            for (int i = 0; i < 4; i++){
                float p = Ps[(ty*4+i)*68 + kk];
                o[i][0] += p*v0.x; o[i][1] += p*v0.y;
                o[i][2] += p*v0.z; o[i][3] += p*v0.w;
                o[i][4] += p*v1.x; o[i][5] += p*v1.y;
                o[i][6] += p*v1.z; o[i][7] += p*v1.w;
            }
        }
        __syncthreads();
    }

    #pragma unroll
    for (int i = 0; i < 4; i++){
        int sq = qt*64 + ty*4 + i;
        float inv = 1.f / lrow[ty*4+i];
        long long base = (((long long)(b*SEQ + sq))*NHEAD + h)*HEADD + tx*8;
        #pragma unroll
        for (int j = 0; j < 8; j++) O[base + j] = o[i][j]*inv;
    }
}

// ---------------- gate + top2 ----------------
__global__ __launch_bounds__(256)
void gate_kernel(const float* __restrict__ x2, const float* __restrict__ gw,
                 int* __restrict__ e01, float* __restrict__ w01){
    long long t = blockIdx.x;
    const float* xr = x2 + t*HDIM;
    float part[NEXP];
    #pragma unroll
    for (int e = 0; e < NEXP; e++) part[e] = 0.f;
    for (int hh = threadIdx.x; hh < HDIM; hh += 256){
        float xv = xr[hh];
        const float* gp = gw + (long long)hh*NEXP;
        #pragma unroll
        for (int e = 0; e < NEXP; e++) part[e] += xv*gp[e];
    }
    __shared__ float red[8][NEXP];
    #pragma unroll
    for (int e = 0; e < NEXP; e++){
        float v = part[e];
        #pragma unroll
        for (int o = 16; o; o >>= 1) v += __shfl_xor_sync(0xffffffffu, v, o);
        if ((threadIdx.x & 31) == 0) red[threadIdx.x >> 5][e] = v;
    }
    __syncthreads();
    if (threadIdx.x == 0){
        float lg[NEXP];
        #pragma unroll
        for (int e = 0; e < NEXP; e++){
            float s = 0.f;
            #pragma unroll
            for (int w8 = 0; w8 < 8; w8++) s += red[w8][e];
            lg[e] = s;
        }
        int b0 = 0;
        #pragma unroll
        for (int e = 1; e < NEXP; e++) if (lg[e] > lg[b0]) b0 = e;
        int b1 = -1;
        #pragma unroll
        for (int e = 0; e < NEXP; e++)
            if (e != b0 && (b1 < 0 || lg[e] > lg[b1])) b1 = e;
        float t0 = 1.f / (1.f + expf(lg[b1] - lg[b0]));
        e01[2*t] = b0; e01[2*t+1] = b1;
        w01[2*t] = t0; w01[2*t+1] = 1.f - t0;
    }
}

// ---------------- routing ----------------
__global__ void route_count_kernel(const int* __restrict__ e01,
                                   int* __restrict__ counts, int* __restrict__ pos01){
    int t = blockIdx.x*blockDim.x + threadIdx.x;
    if (t < NTOK){
        pos01[2*t]   = atomicAdd(&counts[e01[2*t]],   1);
        pos01[2*t+1] = atomicAdd(&counts[e01[2*t+1]], 1);
    }
}
__global__ void route_offset_kernel(const int* __restrict__ counts, int* __restrict__ offsets){
    if (threadIdx.x == 0 && blockIdx.x == 0){
        int s = 0;
        for (int e = 0; e < NEXP; e++){ offsets[e] = s; s += counts[e]; }
    }
}
__global__ void route_scatter_kernel(const int* __restrict__ e01, const int* __restrict__ pos01,
                                     const int* __restrict__ offsets,
                                     int* __restrict__ toklist, int* __restrict__ slot01){
    int t = blockIdx.x*blockDim.x + threadIdx.x;
    if (t < NTOK){
        #pragma unroll
        for (int j = 0; j < 2; j++){
            int sl = offsets[e01[2*t+j]] + pos01[2*t+j];
            toklist[sl] = t;
            slot01[2*t+j] = sl;
        }
    }
}

// ---------------- silu(h1)*h3 (in place into h1) ----------------
__global__ __launch_bounds__(256)
void silu_mul_kernel(float* __restrict__ h1, const float* __restrict__ h3){
    long long n = (long long)2*NTOK*FFN;
    for (long long i = blockIdx.x*256LL + threadIdx.x; i < n; i += gridDim.x*256LL){
        float v = h1[i];
        h1[i] = v / (1.f + expf(-v)) * h3[i];
    }
}

// ---------------- final combine ----------------
__global__ __launch_bounds__(256)
void combine_kernel(const float* __restrict__ h, const float* __restrict__ eo,
                    const int* __restrict__ slot01, const float* __restrict__ w01,
                    float* __restrict__ out){
    long long idx = blockIdx.x*256LL + threadIdx.x;
    if (idx >= (long long)NTOK*HDIM) return;
    int t = (int)(idx >> 11);
    int c = (int)(idx & 2047);
    float v = h[idx];
    v += w01[2*t]   * eo[(long long)slot01[2*t]  *HDIM + c];
    v += w01[2*t+1] * eo[(long long)slot01[2*t+1]*HDIM + c];
    out[idx] = v;
}

// ---------------- launch ----------------
extern "C" void kernel_launch(void* const* d_in, const int* in_sizes, int n_in,
                              void* d_out, int out_size){
    const float* hidden = (const float*)d_in[0];
    const int*   amask  = (const int*)  d_in[1];
    const int*   posids = (const int*)  d_in[2];
    const float* ln1w = (const float*)d_in[3];
    const float* ln1b = (const float*)d_in[4];
    const float* ln2w = (const float*)d_in[5];
    const float* ln2b = (const float*)d_in[6];
    const float* wq = (const float*)d_in[7];
    const float* bq = (const float*)d_in[8];
    const float* wk = (const float*)d_in[9];
    const float* bk = (const float*)d_in[10];
    const float* wv = (const float*)d_in[11];
    const float* bv = (const float*)d_in[12];
    const float* wo = (const float*)d_in[13];
    const float* bo = (const float*)d_in[14];
    const float* gatew = (const float*)d_in[15];
    const float* w1 = (const float*)d_in[16];
    const float* w2 = (const float*)d_in[17];
    const float* w3 = (const float*)d_in[18];
    float* out = (float*)d_out;

    float *xln1, *q, *k, *v, *attn, *h, *xln2, *w01, *h1, *h3, *eo;
    int *e01, *pos01, *counts, *offsets, *toklist, *slot01;
    cudaGetSymbolAddress((void**)&xln1, g_xln1);
    cudaGetSymbolAddress((void**)&q, g_q);
    cudaGetSymbolAddress((void**)&k, g_k);
    cudaGetSymbolAddress((void**)&v, g_v);
    cudaGetSymbolAddress((void**)&attn, g_attn);
    cudaGetSymbolAddress((void**)&h, g_h);
    cudaGetSymbolAddress((void**)&xln2, g_xln2);
    cudaGetSymbolAddress((void**)&e01, g_e01);
    cudaGetSymbolAddress((void**)&w01, g_w01);
    cudaGetSymbolAddress((void**)&pos01, g_pos01);
    cudaGetSymbolAddress((void**)&counts, g_counts);
    cudaGetSymbolAddress((void**)&offsets, g_offsets);
    cudaGetSymbolAddress((void**)&toklist, g_toklist);
    cudaGetSymbolAddress((void**)&slot01, g_slot01);
    cudaGetSymbolAddress((void**)&h1, g_h1);
    cudaGetSymbolAddress((void**)&h3, g_h3);
    cudaGetSymbolAddress((void**)&eo, g_eo);

    const int FLASH_SMEM = (128*68*2 + 64*132 + 64*68 + 64*4) * 4;
    cudaFuncSetAttribute(flash_kernel, cudaFuncAttributeMaxDynamicSharedMemorySize, FLASH_SMEM);

    // 1) LN1
    ln_kernel<<<NTOK, 256>>>(hidden, ln1w, ln1b, xln1);
    // 2) QKV projections
    gemm_tf32<<<dim3(NHEAD*HEADD/128, NTOK/128, 1), 256>>>(
        xln1, HDIM, wq, q, bq, nullptr, NTOK, NHEAD*HEADD, HDIM, nullptr, nullptr, nullptr, 0);
    gemm_tf32<<<dim3(NKVH*HEADD/128, NTOK/128, 1), 256>>>(
        xln1, HDIM, wk, k, bk, nullptr, NTOK, NKVH*HEADD, HDIM, nullptr, nullptr, nullptr, 0);
    gemm_tf32<<<dim3(NKVH*HEADD/128, NTOK/128, 1), 256>>>(
        xln1, HDIM, wv, v, bv, nullptr, NTOK, NKVH*HEADD, HDIM, nullptr, nullptr, nullptr, 0);
    // 3) RoPE
    {
        int total = NTOK*(NHEAD+NKVH)*64;
        rope_kernel<<<(total+255)/256, 256>>>(q, k, posids);
    }
    // 4) causal flash attention
    flash_kernel<<<dim3(SEQ/64, BATCH*NHEAD), 256, FLASH_SMEM>>>(q, k, v, amask, attn);
    // 5) O projection + residual
    gemm_tf32<<<dim3(HDIM/128, NTOK/128, 1), 256>>>(
        attn, NHEAD*HEADD, wo, h, bo, hidden, NTOK, HDIM, NHEAD*HEADD, nullptr, nullptr, nullptr, 0);
    // 6) LN2
    ln_kernel<<<NTOK, 256>>>(h, ln2w, ln2b, xln2);
    // 7) gate + top2
    gate_kernel<<<NTOK, 256>>>(xln2, gatew, e01, w01);
    // 8) routing
    cudaMemsetAsync(counts, 0, NEXP*sizeof(int));
    route_count_kernel<<<(NTOK+255)/256, 256>>>(e01, counts, pos01);
    route_offset_kernel<<<1, 32>>>(counts, offsets);
    route_scatter_kernel<<<(NTOK+255)/256, 256>>>(e01, pos01, offsets, toklist, slot01);
    // 9) expert GEMMs: h1 = X@w1[e], h3 = X@w3[e]  (gathered rows, early-exit grid)
    gemm_tf32<<<dim3(FFN/128, NTOK/128, NEXP), 256>>>(
        xln2, HDIM, w1, h1, nullptr, nullptr, NTOK, FFN, HDIM,
        toklist, counts, offsets, (long long)HDIM*FFN);
    gemm_tf32<<<dim3(FFN/128, NTOK/128, NEXP), 256>>>(
        xln2, HDIM, w3, h3, nullptr, nullptr, NTOK, FFN, HDIM,
        toklist, counts, offsets, (long long)HDIM*FFN);
    // 10) act = silu(h1)*h3
    silu_mul_kernel<<<16384, 256>>>(h1, h3);
    // 11) eo = act @ w2[e]
    gemm_tf32<<<dim3(HDIM/128, NTOK/128, NEXP), 256>>>(
        h1, FFN, w2, eo, nullptr, nullptr, NTOK, HDIM, FFN,
        nullptr, counts, offsets, (long long)FFN*HDIM);
    // 12) out = h + sum(top2 weights * expert outputs)
    combine_kernel<<<(int)(((long long)NTOK*HDIM + 255)/256), 256>>>(h, eo, slot01, w01, out);
}

// round 2
// speedup vs baseline: 1.0460x; 1.0460x over previous
#include <cuda_runtime.h>
#include <math.h>
#include <stdint.h>

// ---------------- problem constants ----------------
#define BATCH 2
#define SEQ   1024
#define HDIM  2048
#define NHEAD 16
#define NKVH  4
#define HEADD 128
#define FFN   4096
#define NEXP  8
#define NTOK  (BATCH*SEQ)          // 2048
#define QKVN  (NHEAD*HEADD + 2*NKVH*HEADD)   // 3072
#define LNEPS 1e-5f

// ---------------- device scratch (static, allowed) ----------------
__device__ float g_xln1[NTOK*HDIM];
__device__ float g_qkv [NTOK*QKVN];      // packed q(2048) | k(512) | v(512)
__device__ float g_attn[NTOK*NHEAD*HEADD];
__device__ float g_h   [NTOK*HDIM];
__device__ float g_xln2[NTOK*HDIM];
__device__ int   g_e01 [NTOK*2];
__device__ float g_w01 [NTOK*2];
__device__ int   g_pos01[NTOK*2];
__device__ int   g_counts[NEXP];
__device__ int   g_offsets[NEXP];
__device__ int   g_toklist[2*NTOK];
__device__ int   g_slot01[NTOK*2];
__device__ float g_h1[2*NTOK*FFN];   // 64 MB
__device__ float g_h3[2*NTOK*FFN];   // 64 MB
__device__ float g_eo[2*NTOK*HDIM];  // 32 MB

// ---------------- helpers ----------------
__device__ __forceinline__ uint32_t tf32u(float x){
    uint32_t u; asm("cvt.rna.tf32.f32 %0, %1;" : "=r"(u) : "f"(x));
    return u;
}

__device__ __forceinline__ void mma_tf32(float* c, const uint32_t* a, const uint32_t* b){
    asm volatile(
      "mma.sync.aligned.m16n8k8.row.col.f32.tf32.tf32.f32 "
      "{%0,%1,%2,%3}, {%4,%5,%6,%7}, {%8,%9}, {%0,%1,%2,%3};\n"
      : "+f"(c[0]), "+f"(c[1]), "+f"(c[2]), "+f"(c[3])
      : "r"(a[0]), "r"(a[1]), "r"(a[2]), "r"(a[3]), "r"(b[0]), "r"(b[1]));
}

__device__ __forceinline__ void cpa16(float* smem, const float* gmem, bool pred){
    uint32_t s = (uint32_t)__cvta_generic_to_shared(smem);
    int sz = pred ? 16 : 0;
    asm volatile("cp.async.cg.shared.global [%0], [%1], 16, %2;\n"
                 :: "r"(s), "l"(gmem), "r"(sz));
}
#define CP_COMMIT() asm volatile("cp.async.commit_group;\n")
template<int N> __device__ __forceinline__ void cp_wait(){
    asm volatile("cp.async.wait_group %0;\n" :: "n"(N));
}

__device__ __forceinline__ float block_sum_256(float v){
    __shared__ float red[8];
    __shared__ float total;
    #pragma unroll
    for (int o = 16; o; o >>= 1) v += __shfl_xor_sync(0xffffffffu, v, o);
    if ((threadIdx.x & 31) == 0) red[threadIdx.x >> 5] = v;
    __syncthreads();
    if (threadIdx.x == 0){
        float s = 0.f;
        #pragma unroll
        for (int i = 0; i < 8; i++) s += red[i];
        total = s;
    }
    __syncthreads();
    float r = total;
    __syncthreads();
    return r;
}

// ---------------- LayerNorm ----------------
__global__ __launch_bounds__(256)
void ln_kernel(const float* __restrict__ x, const float* __restrict__ w,
               const float* __restrict__ b, float* __restrict__ y){
    long long row = blockIdx.x;
    const float* xr = x + row * HDIM;
    float v[8]; float s = 0.f;
    #pragma unroll
    for (int i = 0; i < 8; i++){ v[i] = xr[threadIdx.x + 256*i]; s += v[i]; }
    float mean = block_sum_256(s) * (1.f/HDIM);
    float ss = 0.f;
    #pragma unroll
    for (int i = 0; i < 8; i++){ float d = v[i]-mean; ss += d*d; }
    float var = block_sum_256(ss) * (1.f/HDIM);
    float rstd = rsqrtf(var + LNEPS);
    #pragma unroll
    for (int i = 0; i < 8; i++){
        int c = threadIdx.x + 256*i;
        y[row*HDIM + c] = (v[i]-mean)*rstd*w[c] + b[c];
    }
}

// ---------------- segmented, pipelined tf32 GEMM ----------------
// Up to 3 column segments, each with its own B / bias / C. A rows optionally
// gathered (rowidx) with per-expert M ranges (counts/offsets).
struct GemmSegs {
    int end[3];            // cumulative column boundaries
    const float* B[3];
    int ldb[3];
    const float* bias[3];
    float* C[3];
    int ldc[3];
};

#define BM 128
#define BN 128
#define BK 32

__global__ __launch_bounds__(256, 2)
void gemm_pipe(const float* __restrict__ A, int lda,
               GemmSegs segs,
               const float* __restrict__ resid,
               int M, int K,
               const int* __restrict__ rowidx,
               const int* __restrict__ counts,
               const int* __restrict__ offsets,
               long long bStride)
{
    __shared__ float As[2][BM][36];   // 36-float rows: 16B-aligned + conflict-free
    __shared__ float Bs[2][BK][136];

    int e = blockIdx.z;
    int rowStart = 0, Mm = M;
    if (counts){ Mm = counts[e]; rowStart = offsets[e]; }
    int mbase = blockIdx.y * BM;
    if (mbase >= Mm) return;
    int nbase = blockIdx.x * BN;

    // segment select
    int s = 0;
    if (nbase >= segs.end[0]) s = 1;
    if (nbase >= segs.end[1]) s = 2;
    int segStart = (s == 0) ? 0 : segs.end[s-1];
    int ln = nbase - segStart;
    const float* Bp   = segs.B[s] + (long long)e * bStride + ln;
    int          ldb  = segs.ldb[s];
    const float* bias = segs.bias[s] ? segs.bias[s] + ln : nullptr;
    float*       C    = segs.C[s] + ln;
    int          ldc  = segs.ldc[s];

    int tid  = threadIdx.x;
    int lane = tid & 31, wid = tid >> 5;
    int warpM = wid >> 2, warpN = wid & 3;
    int g = lane >> 2, t4 = lane & 3;

    // A load: thread covers rows ar+32*i, 8 float4 per row spread over threads
    int ar  = tid >> 3;       // 0..31
    int ac4 = tid & 7;        // 0..7
    const float* aptr[4]; bool aval[4];
    #pragma unroll
    for (int i = 0; i < 4; i++){
        int gr = mbase + ar + 32*i;
        bool valid = (gr < Mm);
        int arow = 0;
        if (valid) arow = rowidx ? rowidx[rowStart + gr] : (rowStart + gr);
        aval[i] = valid;
        aptr[i] = A + (long long)arow * lda + ac4*4;
    }
    // B load: rows br+8*i (0..31), col4 bc4 (0..31)
    int br  = tid >> 5;
    int bc4 = tid & 31;

    float acc[16][4];
    #pragma unroll
    for (int i = 0; i < 16; i++)
        #pragma unroll
        for (int j = 0; j < 4; j++) acc[i][j] = 0.f;

    int nk = K >> 5;

    // ---- prologue: stage 0 = tile 0 ----
    #pragma unroll
    for (int i = 0; i < 4; i++)
        cpa16(&As[0][ar + 32*i][ac4*4], aptr[i], aval[i]);
    #pragma unroll
    for (int i = 0; i < 4; i++){
        int row = br + 8*i;
        cpa16(&Bs[0][row][bc4*4], Bp + (long long)row*ldb + bc4*4, true);
    }
    CP_COMMIT();

    for (int kt = 0; kt < nk; ++kt){
        int cur = kt & 1;
        if (kt + 1 < nk){
            int nxt = cur ^ 1;
            #pragma unroll
            for (int i = 0; i < 4; i++)
                cpa16(&As[nxt][ar + 32*i][ac4*4], aptr[i] + (kt+1)*32, aval[i]);
            #pragma unroll
            for (int i = 0; i < 4; i++){
                int row = br + 8*i;
                cpa16(&Bs[nxt][row][bc4*4],
                      Bp + (long long)((kt+1)*32 + row)*ldb + bc4*4, true);
            }
            CP_COMMIT();
            cp_wait<1>();
        } else {
            cp_wait<0>();
        }
        __syncthreads();

        #pragma unroll
        for (int ks = 0; ks < 4; ++ks){
            int k0 = ks*8;
            uint32_t af[4][4], bf[4][2];
            #pragma unroll
            for (int ma = 0; ma < 4; ma++){
                int r = warpM*64 + ma*16;
                af[ma][0] = tf32u(As[cur][r+g  ][k0+t4  ]);
                af[ma][1] = tf32u(As[cur][r+g+8][k0+t4  ]);
                af[ma][2] = tf32u(As[cur][r+g  ][k0+t4+4]);
                af[ma][3] = tf32u(As[cur][r+g+8][k0+t4+4]);
            }
            #pragma unroll
            for (int na = 0; na < 4; na++){
                int c = warpN*32 + na*8 + g;
                bf[na][0] = tf32u(Bs[cur][k0+t4  ][c]);
                bf[na][1] = tf32u(Bs[cur][k0+t4+4][c]);
            }
            #pragma unroll
            for (int ma = 0; ma < 4; ma++)
                #pragma unroll
                for (int na = 0; na < 4; na++)
                    mma_tf32(acc[ma*4+na], af[ma], bf[na]);
        }
        __syncthreads();
    }

    #pragma unroll
    for (int ma = 0; ma < 4; ma++){
        #pragma unroll
        for (int na = 0; na < 4; na++){
            float* a4 = acc[ma*4+na];
            #pragma unroll
            for (int cr = 0; cr < 4; cr++){
                int lrow = warpM*64 + ma*16 + g + ((cr >= 2) ? 8 : 0);
                int lcol = warpN*32 + na*8 + 2*t4 + (cr & 1);
                int gr = mbase + lrow;
                if (gr < Mm){
                    long long orow = rowStart + gr;
                    float v = a4[cr];
                    if (bias)  v += bias[lcol];
                    if (resid) v += resid[orow*(long long)ldc + nbase + lcol];
                    C[orow*(long long)ldc + lcol] = v;
                }
            }
        }
    }
}

// ---------------- RoPE (in place on packed qkv) ----------------
__global__ __launch_bounds__(256)
void rope_kernel(float* __restrict__ qkv, const int* __restrict__ pos_ids){
    int idx = blockIdx.x*256 + threadIdx.x;
    const int total = NTOK*(NHEAD+NKVH)*64;
    if (idx >= total) return;
    int j    = idx & 63;
    int rest = idx >> 6;
    int head = rest % (NHEAD+NKVH);
    int t    = rest / (NHEAD+NKVH);
    float* p;
    if (head < NHEAD) p = qkv + (long long)t*QKVN + head*HEADD;
    else              p = qkv + (long long)t*QKVN + NHEAD*HEADD + (head-NHEAD)*HEADD;
    double inv = exp((double)j * -0.21586735246819178); // -ln(1e6)/64
    float th = (float)pos_ids[t] * (float)inv;
    float sn, cs; sincosf(th, &sn, &cs);
    float x0 = p[j], x1 = p[j+64];
    p[j]    = x0*cs - x1*sn;
    p[j+64] = x1*cs + x0*sn;
}

// ---------------- flash attention (scalar fp32, causal GQA) ----------------
__global__ __launch_bounds__(256)
void flash_kernel(const float* __restrict__ qkv, const int* __restrict__ amask,
                  float* __restrict__ O)
{
    extern __shared__ float sm[];
    float* Qs   = sm;                // [128][68] (d-major)
    float* Ks   = Qs + 128*68;       // [128][68]
    float* Vs   = Ks + 128*68;       // [64][132]
    float* Ps   = Vs + 64*132;       // [64][68]
    float* mrow = Ps + 64*68;
    float* lrow = mrow + 64;
    float* srow = lrow + 64;
    int*   mk   = (int*)(srow + 64);

    int qt = blockIdx.x;
    int bh = blockIdx.y;
    int b  = bh >> 4, h = bh & 15;
    int kvh = h >> 2;
    int tid = threadIdx.x;
    int ty  = tid >> 4, tx = tid & 15;

    for (int e = tid; e < 64*128; e += 256){
        int qq = e >> 7, d = e & 127;
        int sq = qt*64 + qq;
        Qs[d*68 + qq] = qkv[(long long)(b*SEQ + sq)*QKVN + h*HEADD + d];
    }
    if (tid < 64){ mrow[tid] = -1e30f; lrow[tid] = 0.f; }
    float o[4][8];
    #pragma unroll
    for (int i = 0; i < 4; i++)
        #pragma unroll
        for (int j = 0; j < 8; j++) o[i][j] = 0.f;

    const float iscale = 0.08838834764831843f; // 1/sqrt(128)

    for (int kt = 0; kt <= qt; ++kt){
        for (int e = tid; e < 64*128; e += 256){
            int kk = e >> 7, d = e & 127;
            int sk = kt*64 + kk;
            long long base = (long long)(b*SEQ + sk)*QKVN + NHEAD*HEADD + kvh*HEADD;
            Ks[d*68 + kk]  = qkv[base + d];
            Vs[kk*132 + d] = qkv[base + NKVH*HEADD + d];
        }
        if (tid < 64) mk[tid] = amask[b*SEQ + kt*64 + tid];
        __syncthreads();

        float sacc[4][4];
        #pragma unroll
        for (int i = 0; i < 4; i++)
            #pragma unroll
            for (int j = 0; j < 4; j++) sacc[i][j] = 0.f;
        for (int d = 0; d < 128; ++d){
            float4 a4 = *(float4*)&Qs[d*68 + ty*4];
            float4 b4 = *(float4*)&Ks[d*68 + tx*4];
            float a[4] = {a4.x, a4.y, a4.z, a4.w};
            float bb[4] = {b4.x, b4.y, b4.z, b4.w};
            #pragma unroll
            for (int i = 0; i < 4; i++)
                #pragma unroll
                for (int j = 0; j < 4; j++) sacc[i][j] += a[i]*bb[j];
        }
        #pragma unroll
        for (int i = 0; i < 4; i++){
            int sq = qt*64 + ty*4 + i;
            #pragma unroll
            for (int j = 0; j < 4; j++){
                int sk = kt*64 + tx*4 + j;
                float vv = sacc[i][j]*iscale;
                if (sk > sq || mk[tx*4+j] == 0) vv = -1e30f;
                Ps[(ty*4+i)*68 + tx*4 + j] = vv;
            }
        }
        __syncthreads();

        if (tid < 64){
            int r = tid;
            float mo = mrow[r], mx = mo;
            #pragma unroll 8
            for (int kk = 0; kk < 64; kk++) mx = fmaxf(mx, Ps[r*68+kk]);
            float sc = __expf(mo - mx);
            float s = 0.f;
            #pragma unroll 8
            for (int kk = 0; kk < 64; kk++){
                float p = __expf(Ps[r*68+kk] - mx);
                Ps[r*68+kk] = p; s += p;
            }
            lrow[r] = lrow[r]*sc + s;
            mrow[r] = mx;
            srow[r] = sc;
        }
        __syncthreads();

        #pragma unroll
        for (int i = 0; i < 4; i++){
            float sc = srow[ty*4+i];
            #pragma unroll
            for (int j = 0; j < 8; j++) o[i][j] *= sc;
        }
        for (int kk = 0; kk < 64; kk++){
            float4 v0 = *(float4*)&Vs[kk*132 + tx*8];
            float4 v1 = *(float4*)&Vs[kk*132 + tx*8 + 4];
            #pragma unroll
            for (int i = 0; i < 4; i++){
                float p = Ps[(ty*4+i)*68 + kk];
                o[i][0] += p*v0.x; o[i][1] += p*v0.y;
                o[i][2] += p*v0.z; o[i][3] += p*v0.w;
                o[i][4] += p*v1.x; o[i][5] += p*v1.y;
                o[i][6] += p*v1.z; o[i][7] += p*v1.w;
            }
        }
        __syncthreads();
    }

    #pragma unroll
    for (int i = 0; i < 4; i++){
        int sq = qt*64 + ty*4 + i;
        float inv = 1.f / lrow[ty*4+i];
        long long base = (((long long)(b*SEQ + sq))*NHEAD + h)*HEADD + tx*8;
        #pragma unroll
        for (int j = 0; j < 8; j++) O[base + j] = o[i][j]*inv;
    }
}

// ---------------- gate + top2 ----------------
__global__ __launch_bounds__(256)
void gate_kernel(const float* __restrict__ x2, const float* __restrict__ gw,
                 int* __restrict__ e01, float* __restrict__ w01){
    long long t = blockIdx.x;
    const float* xr = x2 + t*HDIM;
    float part[NEXP];
    #pragma unroll
    for (int e = 0; e < NEXP; e++) part[e] = 0.f;
    for (int hh = threadIdx.x; hh < HDIM; hh += 256){
        float xv = xr[hh];
        const float* gp = gw + (long long)hh*NEXP;
        #pragma unroll
        for (int e = 0; e < NEXP; e++) part[e] += xv*gp[e];
    }
    __shared__ float red[8][NEXP];
    #pragma unroll
    for (int e = 0; e < NEXP; e++){
        float v = part[e];
        #pragma unroll
        for (int o = 16; o; o >>= 1) v += __shfl_xor_sync(0xffffffffu, v, o);
        if ((threadIdx.x & 31) == 0) red[threadIdx.x >> 5][e] = v;
    }
    __syncthreads();
    if (threadIdx.x == 0){
        float lg[NEXP];
        #pragma unroll
        for (int e = 0; e < NEXP; e++){
            float s = 0.f;
            #pragma unroll
            for (int w8 = 0; w8 < 8; w8++) s += red[w8][e];
            lg[e] = s;
        }
        int b0 = 0;
        #pragma unroll
        for (int e = 1; e < NEXP; e++) if (lg[e] > lg[b0]) b0 = e;
        int b1 = -1;
        #pragma unroll
        for (int e = 0; e < NEXP; e++)
            if (e != b0 && (b1 < 0 || lg[e] > lg[b1])) b1 = e;
        float t0 = 1.f / (1.f + expf(lg[b1] - lg[b0]));
        e01[2*t] = b0; e01[2*t+1] = b1;
        w01[2*t] = t0; w01[2*t+1] = 1.f - t0;
    }
}

// ---------------- routing ----------------
__global__ void route_count_kernel(const int* __restrict__ e01,
                                   int* __restrict__ counts, int* __restrict__ pos01){
    int t = blockIdx.x*blockDim.x + threadIdx.x;
    if (t < NTOK){
        pos01[2*t]   = atomicAdd(&counts[e01[2*t]],   1);
        pos01[2*t+1] = atomicAdd(&counts[e01[2*t+1]], 1);
    }
}
__global__ void route_offset_kernel(const int* __restrict__ counts, int* __restrict__ offsets){
    if (threadIdx.x == 0 && blockIdx.x == 0){
        int s = 0;
        for (int e = 0; e < NEXP; e++){ offsets[e] = s; s += counts[e]; }
    }
}
__global__ void route_scatter_kernel(const int* __restrict__ e01, const int* __restrict__ pos01,
                                     const int* __restrict__ offsets,
                                     int* __restrict__ toklist, int* __restrict__ slot01){
    int t = blockIdx.x*blockDim.x + threadIdx.x;
    if (t < NTOK){
        #pragma unroll
        for (int j = 0; j < 2; j++){
            int sl = offsets[e01[2*t+j]] + pos01[2*t+j];
            toklist[sl] = t;
            slot01[2*t+j] = sl;
        }
    }
}

// ---------------- silu(h1)*h3 (in place into h1) ----------------
__global__ __launch_bounds__(256)
void silu_mul_kernel(float* __restrict__ h1, const float* __restrict__ h3){
    long long n = (long long)2*NTOK*FFN;
    for (long long i = blockIdx.x*256LL + threadIdx.x; i < n; i += gridDim.x*256LL){
        float v = h1[i];
        h1[i] = v / (1.f + expf(-v)) * h3[i];
    }
}

// ---------------- final combine ----------------
__global__ __launch_bounds__(256)
void combine_kernel(const float* __restrict__ h, const float* __restrict__ eo,
                    const int* __restrict__ slot01, const float* __restrict__ w01,
                    float* __restrict__ out){
    long long idx = blockIdx.x*256LL + threadIdx.x;
    if (idx >= (long long)NTOK*HDIM) return;
    int t = (int)(idx >> 11);
    int c = (int)(idx & 2047);
    float v = h[idx];
    v += w01[2*t]   * eo[(long long)slot01[2*t]  *HDIM + c];
    v += w01[2*t+1] * eo[(long long)slot01[2*t+1]*HDIM + c];
    out[idx] = v;
}

// ---------------- launch ----------------
extern "C" void kernel_launch(void* const* d_in, const int* in_sizes, int n_in,
                              void* d_out, int out_size){
    const float* hidden = (const float*)d_in[0];
    const int*   amask  = (const int*)  d_in[1];
    const int*   posids = (const int*)  d_in[2];
    const float* ln1w = (const float*)d_in[3];
    const float* ln1b = (const float*)d_in[4];
    const float* ln2w = (const float*)d_in[5];
    const float* ln2b = (const float*)d_in[6];
    const float* wq = (const float*)d_in[7];
    const float* bq = (const float*)d_in[8];
    const float* wk = (const float*)d_in[9];
    const float* bk = (const float*)d_in[10];
    const float* wv = (const float*)d_in[11];
    const float* bv = (const float*)d_in[12];
    const float* wo = (const float*)d_in[13];
    const float* bo = (const float*)d_in[14];
    const float* gatew = (const float*)d_in[15];
    const float* w1 = (const float*)d_in[16];
    const float* w2 = (const float*)d_in[17];
    const float* w3 = (const float*)d_in[18];
    float* out = (float*)d_out;

    float *xln1, *qkv, *attn, *h, *xln2, *w01, *h1, *h3, *eo;
    int *e01, *pos01, *counts, *offsets, *toklist, *slot01;
    cudaGetSymbolAddress((void**)&xln1, g_xln1);
    cudaGetSymbolAddress((void**)&qkv, g_qkv);
    cudaGetSymbolAddress((void**)&attn, g_attn);
    cudaGetSymbolAddress((void**)&h, g_h);
    cudaGetSymbolAddress((void**)&xln2, g_xln2);
    cudaGetSymbolAddress((void**)&e01, g_e01);
    cudaGetSymbolAddress((void**)&w01, g_w01);
    cudaGetSymbolAddress((void**)&pos01, g_pos01);
    cudaGetSymbolAddress((void**)&counts, g_counts);
    cudaGetSymbolAddress((void**)&offsets, g_offsets);
    cudaGetSymbolAddress((void**)&toklist, g_toklist);
    cudaGetSymbolAddress((void**)&slot01, g_slot01);
    cudaGetSymbolAddress((void**)&h1, g_h1);
    cudaGetSymbolAddress((void**)&h3, g_h3);
    cudaGetSymbolAddress((void**)&eo, g_eo);

    const int FLASH_SMEM = (128*68*2 + 64*132 + 64*68 + 64*4) * 4;
    cudaFuncSetAttribute(flash_kernel, cudaFuncAttributeMaxDynamicSharedMemorySize, FLASH_SMEM);

    // 1) LN1
    ln_kernel<<<NTOK, 256>>>(hidden, ln1w, ln1b, xln1);

    // 2) fused QKV projection (N = 3072, packed output)
    {
        GemmSegs sg;
        sg.end[0] = NHEAD*HEADD; sg.end[1] = NHEAD*HEADD + NKVH*HEADD; sg.end[2] = QKVN;
        sg.B[0] = wq;  sg.B[1] = wk;  sg.B[2] = wv;
        sg.ldb[0] = NHEAD*HEADD; sg.ldb[1] = NKVH*HEADD; sg.ldb[2] = NKVH*HEADD;
        sg.bias[0] = bq; sg.bias[1] = bk; sg.bias[2] = bv;
        sg.C[0] = qkv; sg.C[1] = qkv + NHEAD*HEADD; sg.C[2] = qkv + NHEAD*HEADD + NKVH*HEADD;
        sg.ldc[0] = QKVN; sg.ldc[1] = QKVN; sg.ldc[2] = QKVN;
        gemm_pipe<<<dim3(QKVN/BN, NTOK/BM, 1), 256>>>(
            xln1, HDIM, sg, nullptr, NTOK, HDIM, nullptr, nullptr, nullptr, 0);
    }

    // 3) RoPE
    {
        int total = NTOK*(NHEAD+NKVH)*64;
        rope_kernel<<<(total+255)/256, 256>>>(qkv, posids);
    }

    // 4) causal flash attention
    flash_kernel<<<dim3(SEQ/64, BATCH*NHEAD), 256, FLASH_SMEM>>>(qkv, amask, attn);

    // 5) O projection + residual
    {
        GemmSegs sg;
        sg.end[0] = HDIM; sg.end[1] = HDIM; sg.end[2] = HDIM;
        sg.B[0] = wo; sg.B[1] = wo; sg.B[2] = wo;
        sg.ldb[0] = HDIM; sg.ldb[1] = HDIM; sg.ldb[2] = HDIM;
        sg.bias[0] = bo; sg.bias[1] = bo; sg.bias[2] = bo;
        sg.C[0] = h; sg.C[1] = h; sg.C[2] = h;
        sg.ldc[0] = HDIM; sg.ldc[1] = HDIM; sg.ldc[2] = HDIM;
        gemm_pipe<<<dim3(HDIM/BN, NTOK/BM, 1), 256>>>(
            attn, NHEAD*HEADD, sg, hidden, NTOK, NHEAD*HEADD, nullptr, nullptr, nullptr, 0);
    }

    // 6) LN2
    ln_kernel<<<NTOK, 256>>>(h, ln2w, ln2b, xln2);
    // 7) gate + top2
    gate_kernel<<<NTOK, 256>>>(xln2, gatew, e01, w01);
    // 8) routing
    cudaMemsetAsync(counts, 0, NEXP*sizeof(int));
    route_count_kernel<<<(NTOK+255)/256, 256>>>(e01, counts, pos01);
    route_offset_kernel<<<1, 32>>>(counts, offsets);
    route_scatter_kernel<<<(NTOK+255)/256, 256>>>(e01, pos01, offsets, toklist, slot01);

    // 9) fused expert up-projections: [h1 | h3] = X @ [w1 | w3]
    {
        GemmSegs sg;
        sg.end[0] = FFN; sg.end[1] = 2*FFN; sg.end[2] = 2*FFN;
        sg.B[0] = w1; sg.B[1] = w3; sg.B[2] = w3;
        sg.ldb[0] = FFN; sg.ldb[1] = FFN; sg.ldb[2] = FFN;
        sg.bias[0] = nullptr; sg.bias[1] = nullptr; sg.bias[2] = nullptr;
        sg.C[0] = h1; sg.C[1] = h3; sg.C[2] = h3;
        sg.ldc[0] = FFN; sg.ldc[1] = FFN; sg.ldc[2] = FFN;
        gemm_pipe<<<dim3(2*FFN/BN, NTOK/BM, NEXP), 256>>>(
            xln2, HDIM, sg, nullptr, NTOK, HDIM,
            toklist, counts, offsets, (long long)HDIM*FFN);
    }

    // 10) act = silu(h1)*h3
    silu_mul_kernel<<<16384, 256>>>(h1, h3);

    // 11) eo = act @ w2[e]
    {
        GemmSegs sg;
        sg.end[0] = HDIM; sg.end[1] = HDIM; sg.end[2] = HDIM;
        sg.B[0] = w2; sg.B[1] = w2; sg.B[2] = w2;
        sg.ldb[0] = HDIM; sg.ldb[1] = HDIM; sg.ldb[2] = HDIM;
        sg.bias[0] = nullptr; sg.bias[1] = nullptr; sg.bias[2] = nullptr;
        sg.C[0] = eo; sg.C[1] = eo; sg.C[2] = eo;
        sg.ldc[0] = HDIM; sg.ldc[1] = HDIM; sg.ldc[2] = HDIM;
        gemm_pipe<<<dim3(HDIM/BN, NTOK/BM, NEXP), 256>>>(
            h1, FFN, sg, nullptr, NTOK, FFN,
            nullptr, counts, offsets, (long long)FFN*HDIM);
    }

    // 12) out = h + sum(top2 weights * expert outputs)
    combine_kernel<<<(int)(((long long)NTOK*HDIM + 255)/256), 256>>>(h, eo, slot01, w01, out);
}

// round 3
// speedup vs baseline: 1.1550x; 1.1043x over previous
#include <cuda_runtime.h>
#include <math.h>
#include <stdint.h>

// ---------------- problem constants ----------------
#define BATCH 2
#define SEQ   1024
#define HDIM  2048
#define NHEAD 16
#define NKVH  4
#define HEADD 128
#define FFN   4096
#define NEXP  8
#define NTOK  (BATCH*SEQ)          // 2048
#define QKVN  (NHEAD*HEADD + 2*NKVH*HEADD)   // 3072
#define LNEPS 1e-5f

// ---------------- device scratch (static, allowed) ----------------
__device__ float g_xln1[NTOK*HDIM];
__device__ float g_qkv [NTOK*QKVN];      // packed q(2048) | k(512) | v(512)
__device__ float g_attn[NTOK*NHEAD*HEADD];
__device__ float g_h   [NTOK*HDIM];
__device__ float g_xln2[NTOK*HDIM];
__device__ int   g_e01 [NTOK*2];
__device__ float g_w01 [NTOK*2];
__device__ int   g_pos01[NTOK*2];
__device__ int   g_counts[NEXP];
__device__ int   g_offsets[NEXP];
__device__ int   g_toklist[2*NTOK];
__device__ int   g_slot01[NTOK*2];
__device__ float g_h1[2*NTOK*FFN];
__device__ float g_h3[2*NTOK*FFN];
__device__ float g_eo[2*NTOK*HDIM];

// ---------------- helpers ----------------
__device__ __forceinline__ uint32_t tf32u(float x){
    uint32_t u; asm("cvt.rna.tf32.f32 %0, %1;" : "=r"(u) : "f"(x));
    return u;
}
__device__ __forceinline__ float tf32f(float x){
    return __uint_as_float(tf32u(x));
}

__device__ __forceinline__ void mma_tf32(float* c, const uint32_t* a, const uint32_t* b){
    asm volatile(
      "mma.sync.aligned.m16n8k8.row.col.f32.tf32.tf32.f32 "
      "{%0,%1,%2,%3}, {%4,%5,%6,%7}, {%8,%9}, {%0,%1,%2,%3};\n"
      : "+f"(c[0]), "+f"(c[1]), "+f"(c[2]), "+f"(c[3])
      : "r"(a[0]), "r"(a[1]), "r"(a[2]), "r"(a[3]), "r"(b[0]), "r"(b[1]));
}

__device__ __forceinline__ void cpa16(float* smem, const float* gmem, bool pred){
    uint32_t s = (uint32_t)__cvta_generic_to_shared(smem);
    int sz = pred ? 16 : 0;
    asm volatile("cp.async.cg.shared.global [%0], [%1], 16, %2;\n"
                 :: "r"(s), "l"(gmem), "r"(sz));
}
#define CP_COMMIT() asm volatile("cp.async.commit_group;\n")
template<int N> __device__ __forceinline__ void cp_wait(){
    asm volatile("cp.async.wait_group %0;\n" :: "n"(N));
}

__device__ __forceinline__ float block_sum_256(float v){
    __shared__ float red[8];
    __shared__ float total;
    #pragma unroll
    for (int o = 16; o; o >>= 1) v += __shfl_xor_sync(0xffffffffu, v, o);
    if ((threadIdx.x & 31) == 0) red[threadIdx.x >> 5] = v;
    __syncthreads();
    if (threadIdx.x == 0){
        float s = 0.f;
        #pragma unroll
        for (int i = 0; i < 8; i++) s += red[i];
        total = s;
    }
    __syncthreads();
    float r = total;
    __syncthreads();
    return r;
}

// ---------------- LayerNorm ----------------
__global__ __launch_bounds__(256)
void ln_kernel(const float* __restrict__ x, const float* __restrict__ w,
               const float* __restrict__ b, float* __restrict__ y){
    long long row = blockIdx.x;
    const float* xr = x + row * HDIM;
    float v[8]; float s = 0.f;
    #pragma unroll
    for (int i = 0; i < 8; i++){ v[i] = xr[threadIdx.x + 256*i]; s += v[i]; }
    float mean = block_sum_256(s) * (1.f/HDIM);
    float ss = 0.f;
    #pragma unroll
    for (int i = 0; i < 8; i++){ float d = v[i]-mean; ss += d*d; }
    float var = block_sum_256(ss) * (1.f/HDIM);
    float rstd = rsqrtf(var + LNEPS);
    #pragma unroll
    for (int i = 0; i < 8; i++){
        int c = threadIdx.x + 256*i;
        y[row*HDIM + c] = (v[i]-mean)*rstd*w[c] + b[c];
    }
}

// ---------------- segmented, 3-stage pipelined tf32 GEMM ----------------
struct GemmSegs {
    int end[3];
    const float* B[3];
    int ldb[3];
    const float* bias[3];
    float* C[3];
    int ldc[3];
};

#define BM 128
#define BN 128
#define BK 32
// dynamic smem layout (floats)
#define AS_STG   (128*36)
#define BS_STG   (32*136)
#define BS_BASE  (3*AS_STG)
#define GEMM_SMEM_FLOATS (BS_BASE + 3*BS_STG)
#define GEMM_SMEM_BYTES  (GEMM_SMEM_FLOATS*4)

__global__ __launch_bounds__(256, 2)
void gemm_pipe(const float* __restrict__ A, int lda,
               GemmSegs segs,
               const float* __restrict__ resid,
               int M, int K,
               const int* __restrict__ rowidx,
               const int* __restrict__ counts,
               const int* __restrict__ offsets,
               long long bStride)
{
    extern __shared__ float dynsm[];
#define ASM(st, r, c) dynsm[(st)*AS_STG + (r)*36 + (c)]
#define BSM(st, r, c) dynsm[BS_BASE + (st)*BS_STG + (r)*136 + (c)]

    int e = blockIdx.z;
    int rowStart = 0, Mm = M;
    if (counts){ Mm = counts[e]; rowStart = offsets[e]; }
    int mbase = blockIdx.y * BM;
    if (mbase >= Mm) return;
    int nbase = blockIdx.x * BN;

    int s = 0;
    if (nbase >= segs.end[0]) s = 1;
    if (nbase >= segs.end[1]) s = 2;
    int segStart = (s == 0) ? 0 : segs.end[s-1];
    int ln = nbase - segStart;
    const float* Bp   = segs.B[s] + (long long)e * bStride + ln;
    int          ldb  = segs.ldb[s];
    const float* bias = segs.bias[s] ? segs.bias[s] + ln : nullptr;
    float*       C    = segs.C[s] + ln;
    int          ldc  = segs.ldc[s];

    int tid  = threadIdx.x;
    int lane = tid & 31, wid = tid >> 5;
    int warpM = wid >> 2, warpN = wid & 3;
    int g = lane >> 2, t4 = lane & 3;

    int ar  = tid >> 3;       // 0..31
    int ac4 = tid & 7;        // 0..7
    const float* aptr[4]; bool aval[4];
    #pragma unroll
    for (int i = 0; i < 4; i++){
        int gr = mbase + ar + 32*i;
        bool valid = (gr < Mm);
        int arow = 0;
        if (valid) arow = rowidx ? rowidx[rowStart + gr] : (rowStart + gr);
        aval[i] = valid;
        aptr[i] = A + (long long)arow * lda + ac4*4;
    }
    int br  = tid >> 5;
    int bc4 = tid & 31;

    float acc[16][4];
    #pragma unroll
    for (int i = 0; i < 16; i++)
        #pragma unroll
        for (int j = 0; j < 4; j++) acc[i][j] = 0.f;

    int nk = K >> 5;

#define GEMM_ISSUE(KT, ST) do {                                           \
        _Pragma("unroll")                                                 \
        for (int i = 0; i < 4; i++)                                       \
            cpa16(&ASM(ST, ar + 32*i, ac4*4), aptr[i] + (KT)*32, aval[i]);\
        _Pragma("unroll")                                                 \
        for (int i = 0; i < 4; i++){                                      \
            int row = br + 8*i;                                           \
            cpa16(&BSM(ST, row, bc4*4),                                   \
                  Bp + (long long)((KT)*32 + row)*ldb + bc4*4, true);     \
        }                                                                 \
    } while(0)

    // prologue: tiles 0, 1
    GEMM_ISSUE(0, 0); CP_COMMIT();
    GEMM_ISSUE(1, 1); CP_COMMIT();

    int cur = 0;
    for (int kt = 0; kt < nk; ++kt){
        if (kt + 1 < nk) cp_wait<1>(); else cp_wait<0>();
        __syncthreads();
        if (kt + 2 < nk){
            int nxt = cur + 2; if (nxt >= 3) nxt -= 3;
            GEMM_ISSUE(kt+2, nxt); CP_COMMIT();
        }

        #pragma unroll
        for (int ks = 0; ks < 4; ++ks){
            int k0 = ks*8;
            uint32_t af[4][4], bf[4][2];
            #pragma unroll
            for (int ma = 0; ma < 4; ma++){
                int r = warpM*64 + ma*16;
                af[ma][0] = tf32u(ASM(cur, r+g  , k0+t4  ));
                af[ma][1] = tf32u(ASM(cur, r+g+8, k0+t4  ));
                af[ma][2] = tf32u(ASM(cur, r+g  , k0+t4+4));
                af[ma][3] = tf32u(ASM(cur, r+g+8, k0+t4+4));
            }
            #pragma unroll
            for (int na = 0; na < 4; na++){
                int c = warpN*32 + na*8 + g;
                bf[na][0] = tf32u(BSM(cur, k0+t4  , c));
                bf[na][1] = tf32u(BSM(cur, k0+t4+4, c));
            }
            #pragma unroll
            for (int ma = 0; ma < 4; ma++)
                #pragma unroll
                for (int na = 0; na < 4; na++)
                    mma_tf32(acc[ma*4+na], af[ma], bf[na]);
        }
        cur = cur + 1; if (cur >= 3) cur -= 3;
    }

    #pragma unroll
    for (int ma = 0; ma < 4; ma++){
        #pragma unroll
        for (int na = 0; na < 4; na++){
            float* a4 = acc[ma*4+na];
            #pragma unroll
            for (int cr = 0; cr < 4; cr++){
                int lrow = warpM*64 + ma*16 + g + ((cr >= 2) ? 8 : 0);
                int lcol = warpN*32 + na*8 + 2*t4 + (cr & 1);
                int gr = mbase + lrow;
                if (gr < Mm){
                    long long orow = rowStart + gr;
                    float v = a4[cr];
                    if (bias)  v += bias[lcol];
                    if (resid) v += resid[orow*(long long)ldc + nbase + lcol];
                    C[orow*(long long)ldc + lcol] = v;
                }
            }
        }
    }
#undef ASM
#undef BSM
#undef GEMM_ISSUE
}

// ---------------- RoPE (in place on packed qkv) ----------------
__global__ __launch_bounds__(256)
void rope_kernel(float* __restrict__ qkv, const int* __restrict__ pos_ids){
    int idx = blockIdx.x*256 + threadIdx.x;
    const int total = NTOK*(NHEAD+NKVH)*64;
    if (idx >= total) return;
    int j    = idx & 63;
    int rest = idx >> 6;
    int head = rest % (NHEAD+NKVH);
    int t    = rest / (NHEAD+NKVH);
    float* p;
    if (head < NHEAD) p = qkv + (long long)t*QKVN + head*HEADD;
    else              p = qkv + (long long)t*QKVN + NHEAD*HEADD + (head-NHEAD)*HEADD;
    double inv = exp((double)j * -0.21586735246819178); // -ln(1e6)/64
    float th = (float)pos_ids[t] * (float)inv;
    float sn, cs; sincosf(th, &sn, &cs);
    float x0 = p[j], x1 = p[j+64];
    p[j]    = x0*cs - x1*sn;
    p[j+64] = x1*cs + x0*sn;
}

// ---------------- tensor-core flash attention (tf32, causal GQA) ----------------
// q-tile 64, k-tile 64. 8 warps. smem rows: Qs/Ks stride 132, Vs 136, Ps 68.
#define FL_QS   0
#define FL_KS   (FL_QS + 64*132)
#define FL_VS   (FL_KS + 64*132)
#define FL_PS   (FL_VS + 64*136)
#define FL_MROW (FL_PS + 64*68)
#define FL_LROW (FL_MROW + 64)
#define FL_SROW (FL_LROW + 64)
#define FL_MK   (FL_SROW + 64)
#define FL_SMEM_FLOATS (FL_MK + 64)
#define FL_SMEM_BYTES  (FL_SMEM_FLOATS*4)

__global__ __launch_bounds__(256)
void flash_kernel(const float* __restrict__ qkv, const int* __restrict__ amask,
                  float* __restrict__ O)
{
    extern __shared__ float sm[];
    float* Qs = sm + FL_QS;
    float* Ks = sm + FL_KS;
    float* Vs = sm + FL_VS;
    float* Ps = sm + FL_PS;
    float* mrow = sm + FL_MROW;
    float* lrow = sm + FL_LROW;
    float* srow = sm + FL_SROW;
    int*   mk   = (int*)(sm + FL_MK);

    int qt = blockIdx.x;
    int bh = blockIdx.y;
    int b  = bh >> 4, h = bh & 15;
    int kvh = h >> 2;
    int tid = threadIdx.x;
    int lane = tid & 31, wid = tid >> 5;
    int g = lane >> 2, t4 = lane & 3;
    int mS = wid & 3;        // 16-row slab
    int nH = wid >> 2;       // S: 32-col half ; PV: 64-col half

    // load Q tile (rows qt*64.., tf32 at store)
    for (int e4 = tid; e4 < 64*32; e4 += 256){
        int row = e4 >> 5; int d4 = (e4 & 31)*4;
        const float* src = &qkv[(long long)(b*SEQ + qt*64 + row)*QKVN + h*HEADD + d4];
        float4 v = *(const float4*)src;
        Qs[row*132 + d4 + 0] = tf32f(v.x);
        Qs[row*132 + d4 + 1] = tf32f(v.y);
        Qs[row*132 + d4 + 2] = tf32f(v.z);
        Qs[row*132 + d4 + 3] = tf32f(v.w);
    }
    if (tid < 64){ mrow[tid] = -1e30f; lrow[tid] = 0.f; }

    float oacc[8][4];
    #pragma unroll
    for (int i = 0; i < 8; i++)
        #pragma unroll
        for (int j = 0; j < 4; j++) oacc[i][j] = 0.f;

    const float iscale = 0.08838834764831843f; // 1/sqrt(128)

    for (int kt = 0; kt <= qt; ++kt){
        __syncthreads();   // prev PV done (and Q load on first iter)
        // load K, V tiles (row-major token x d, tf32)
        for (int e4 = tid; e4 < 64*32; e4 += 256){
            int kk = e4 >> 5; int d4 = (e4 & 31)*4;
            long long base = (long long)(b*SEQ + kt*64 + kk)*QKVN + NHEAD*HEADD + kvh*HEADD;
            float4 kv4 = *(const float4*)&qkv[base + d4];
            Ks[kk*132 + d4 + 0] = tf32f(kv4.x);
            Ks[kk*132 + d4 + 1] = tf32f(kv4.y);
            Ks[kk*132 + d4 + 2] = tf32f(kv4.z);
            Ks[kk*132 + d4 + 3] = tf32f(kv4.w);
            float4 vv4 = *(const float4*)&qkv[base + NKVH*HEADD + d4];
            Vs[kk*136 + d4 + 0] = tf32f(vv4.x);
            Vs[kk*136 + d4 + 1] = tf32f(vv4.y);
            Vs[kk*136 + d4 + 2] = tf32f(vv4.z);
            Vs[kk*136 + d4 + 3] = tf32f(vv4.w);
        }
        if (tid < 64) mk[tid] = amask[b*SEQ + kt*64 + tid];
        __syncthreads();

        // S = Q @ K^T : warp computes 16x32 (rows 16*mS, cols 32*nH)
        float sacc[4][4];
        #pragma unroll
        for (int i = 0; i < 4; i++)
            #pragma unroll
            for (int j = 0; j < 4; j++) sacc[i][j] = 0.f;
        #pragma unroll
        for (int ks = 0; ks < 16; ++ks){
            int k0 = ks*8;
            uint32_t a[4];
            int r = 16*mS;
            a[0] = __float_as_uint(Qs[(r+g  )*132 + k0+t4  ]);
            a[1] = __float_as_uint(Qs[(r+g+8)*132 + k0+t4  ]);
            a[2] = __float_as_uint(Qs[(r+g  )*132 + k0+t4+4]);
            a[3] = __float_as_uint(Qs[(r+g+8)*132 + k0+t4+4]);
            #pragma unroll
            for (int j = 0; j < 4; j++){
                int c = 32*nH + 8*j + g;
                uint32_t bfr[2];
                bfr[0] = __float_as_uint(Ks[c*132 + k0+t4  ]);
                bfr[1] = __float_as_uint(Ks[c*132 + k0+t4+4]);
                mma_tf32(sacc[j], a, bfr);
            }
        }
        // write S to Ps (fp32) with scale + mask
        #pragma unroll
        for (int j = 0; j < 4; j++){
            #pragma unroll
            for (int cr = 0; cr < 4; cr++){
                int row = 16*mS + g + ((cr >= 2) ? 8 : 0);
                int col = 32*nH + 8*j + 2*t4 + (cr & 1);
                int sq = qt*64 + row, sk = kt*64 + col;
                float vv = sacc[j][cr]*iscale;
                if (sk > sq || mk[col] == 0) vv = -1e30f;
                Ps[row*68 + col] = vv;
            }
        }
        __syncthreads();

        // online softmax per row; write probs back as tf32 bits
        if (tid < 64){
            int r = tid;
            float mo = mrow[r], mx = mo;
            #pragma unroll 8
            for (int kk = 0; kk < 64; kk++) mx = fmaxf(mx, Ps[r*68+kk]);
            float sc = __expf(mo - mx);
            float ssum = 0.f;
            #pragma unroll 8
            for (int kk = 0; kk < 64; kk++){
                float p = __expf(Ps[r*68+kk] - mx);
                ssum += p;
                Ps[r*68+kk] = tf32f(p);
            }
            lrow[r] = lrow[r]*sc + ssum;
            mrow[r] = mx;
            srow[r] = sc;
        }
        __syncthreads();

        // rescale O accumulators, then O += P @ V (warp: rows 16*mS, cols 64*nH)
        {
            float sc0 = srow[16*mS + g];
            float sc1 = srow[16*mS + g + 8];
            #pragma unroll
            for (int j = 0; j < 8; j++){
                oacc[j][0] *= sc0; oacc[j][1] *= sc0;
                oacc[j][2] *= sc1; oacc[j][3] *= sc1;
            }
        }
        #pragma unroll
        for (int ks = 0; ks < 8; ++ks){
            int k0 = ks*8;
            uint32_t a[4];
            int r = 16*mS;
            a[0] = __float_as_uint(Ps[(r+g  )*68 + k0+t4  ]);
            a[1] = __float_as_uint(Ps[(r+g+8)*68 + k0+t4  ]);
            a[2] = __float_as_uint(Ps[(r+g  )*68 + k0+t4+4]);
            a[3] = __float_as_uint(Ps[(r+g+8)*68 + k0+t4+4]);
            #pragma unroll
            for (int j = 0; j < 8; j++){
                int c = 64*nH + 8*j + g;
                uint32_t bfr[2];
                bfr[0] = __float_as_uint(Vs[(k0+t4  )*136 + c]);
                bfr[1] = __float_as_uint(Vs[(k0+t4+4)*136 + c]);
                mma_tf32(oacc[j], a, bfr);
            }
        }
    }

    // epilogue: normalize by lrow, write out
    #pragma unroll
    for (int j = 0; j < 8; j++){
        #pragma unroll
        for (int cr = 0; cr < 4; cr++){
            int row = 16*mS + g + ((cr >= 2) ? 8 : 0);
            int col = 64*nH + 8*j + 2*t4 + (cr & 1);
            int sq = qt*64 + row;
            float inv = 1.f / lrow[row];
            O[(((long long)(b*SEQ + sq))*NHEAD + h)*HEADD + col] = oacc[j][cr]*inv;
        }
    }
}

// ---------------- gate + top2 ----------------
__global__ __launch_bounds__(256)
void gate_kernel(const float* __restrict__ x2, const float* __restrict__ gw,
                 int* __restrict__ e01, float* __restrict__ w01){
    long long t = blockIdx.x;
    const float* xr = x2 + t*HDIM;
    float part[NEXP];
    #pragma unroll
    for (int e = 0; e < NEXP; e++) part[e] = 0.f;
    for (int hh = threadIdx.x; hh < HDIM; hh += 256){
        float xv = xr[hh];
        const float* gp = gw + (long long)hh*NEXP;
        #pragma unroll
        for (int e = 0; e < NEXP; e++) part[e] += xv*gp[e];
    }
    __shared__ float red[8][NEXP];
    #pragma unroll
    for (int e = 0; e < NEXP; e++){
        float v = part[e];
        #pragma unroll
        for (int o = 16; o; o >>= 1) v += __shfl_xor_sync(0xffffffffu, v, o);
        if ((threadIdx.x & 31) == 0) red[threadIdx.x >> 5][e] = v;
    }
    __syncthreads();
    if (threadIdx.x == 0){
        float lg[NEXP];
        #pragma unroll
        for (int e = 0; e < NEXP; e++){
            float s = 0.f;
            #pragma unroll
            for (int w8 = 0; w8 < 8; w8++) s += red[w8][e];
            lg[e] = s;
        }
        int b0 = 0;
        #pragma unroll
        for (int e = 1; e < NEXP; e++) if (lg[e] > lg[b0]) b0 = e;
        int b1 = -1;
        #pragma unroll
        for (int e = 0; e < NEXP; e++)
            if (e != b0 && (b1 < 0 || lg[e] > lg[b1])) b1 = e;
        float t0 = 1.f / (1.f + expf(lg[b1] - lg[b0]));
        e01[2*t] = b0; e01[2*t+1] = b1;
        w01[2*t] = t0; w01[2*t+1] = 1.f - t0;
    }
}

// ---------------- routing ----------------
__global__ void route_count_kernel(const int* __restrict__ e01,
                                   int* __restrict__ counts, int* __restrict__ pos01){
    int t = blockIdx.x*blockDim.x + threadIdx.x;
    if (t < NTOK){
        pos01[2*t]   = atomicAdd(&counts[e01[2*t]],   1);
        pos01[2*t+1] = atomicAdd(&counts[e01[2*t+1]], 1);
    }
}
__global__ void route_offset_kernel(const int* __restrict__ counts, int* __restrict__ offsets){
    if (threadIdx.x == 0 && blockIdx.x == 0){
        int s = 0;
        for (int e = 0; e < NEXP; e++){ offsets[e] = s; s += counts[e]; }
    }
}
__global__ void route_scatter_kernel(const int* __restrict__ e01, const int* __restrict__ pos01,
                                     const int* __restrict__ offsets,
                                     int* __restrict__ toklist, int* __restrict__ slot01){
    int t = blockIdx.x*blockDim.x + threadIdx.x;
    if (t < NTOK){
        #pragma unroll
        for (int j = 0; j < 2; j++){
            int sl = offsets[e01[2*t+j]] + pos01[2*t+j];
            toklist[sl] = t;
            slot01[2*t+j] = sl;
        }
    }
}

// ---------------- silu(h1)*h3 (in place into h1) ----------------
__global__ __launch_bounds__(256)
void silu_mul_kernel(float* __restrict__ h1, const float* __restrict__ h3){
    long long n = (long long)2*NTOK*FFN;
    for (long long i = blockIdx.x*256LL + threadIdx.x; i < n; i += gridDim.x*256LL){
        float v = h1[i];
        h1[i] = v / (1.f + expf(-v)) * h3[i];
    }
}

// ---------------- final combine ----------------
__global__ __launch_bounds__(256)
void combine_kernel(const float* __restrict__ h, const float* __restrict__ eo,
                    const int* __restrict__ slot01, const float* __restrict__ w01,
                    float* __restrict__ out){
    long long idx = blockIdx.x*256LL + threadIdx.x;
    if (idx >= (long long)NTOK*HDIM) return;
    int t = (int)(idx >> 11);
    int c = (int)(idx & 2047);
    float v = h[idx];
    v += w01[2*t]   * eo[(long long)slot01[2*t]  *HDIM + c];
    v += w01[2*t+1] * eo[(long long)slot01[2*t+1]*HDIM + c];
    out[idx] = v;
}

// ---------------- launch ----------------
extern "C" void kernel_launch(void* const* d_in, const int* in_sizes, int n_in,
                              void* d_out, int out_size){
    const float* hidden = (const float*)d_in[0];
    const int*   amask  = (const int*)  d_in[1];
    const int*   posids = (const int*)  d_in[2];
    const float* ln1w = (const float*)d_in[3];
    const float* ln1b = (const float*)d_in[4];
    const float* ln2w = (const float*)d_in[5];
    const float* ln2b = (const float*)d_in[6];
    const float* wq = (const float*)d_in[7];
    const float* bq = (const float*)d_in[8];
    const float* wk = (const float*)d_in[9];
    const float* bk = (const float*)d_in[10];
    const float* wv = (const float*)d_in[11];
    const float* bv = (const float*)d_in[12];
    const float* wo = (const float*)d_in[13];
    const float* bo = (const float*)d_in[14];
    const float* gatew = (const float*)d_in[15];
    const float* w1 = (const float*)d_in[16];
    const float* w2 = (const float*)d_in[17];
    const float* w3 = (const float*)d_in[18];
    float* out = (float*)d_out;

    float *xln1, *qkv, *attn, *h, *xln2, *w01, *h1, *h3, *eo;
    int *e01, *pos01, *counts, *offsets, *toklist, *slot01;
    cudaGetSymbolAddress((void**)&xln1, g_xln1);
    cudaGetSymbolAddress((void**)&qkv, g_qkv);
    cudaGetSymbolAddress((void**)&attn, g_attn);
    cudaGetSymbolAddress((void**)&h, g_h);
    cudaGetSymbolAddress((void**)&xln2, g_xln2);
    cudaGetSymbolAddress((void**)&e01, g_e01);
    cudaGetSymbolAddress((void**)&w01, g_w01);
    cudaGetSymbolAddress((void**)&pos01, g_pos01);
    cudaGetSymbolAddress((void**)&counts, g_counts);
    cudaGetSymbolAddress((void**)&offsets, g_offsets);
    cudaGetSymbolAddress((void**)&toklist, g_toklist);
    cudaGetSymbolAddress((void**)&slot01, g_slot01);
    cudaGetSymbolAddress((void**)&h1, g_h1);
    cudaGetSymbolAddress((void**)&h3, g_h3);
    cudaGetSymbolAddress((void**)&eo, g_eo);

    cudaFuncSetAttribute(flash_kernel, cudaFuncAttributeMaxDynamicSharedMemorySize, FL_SMEM_BYTES);
    cudaFuncSetAttribute(gemm_pipe,   cudaFuncAttributeMaxDynamicSharedMemorySize, GEMM_SMEM_BYTES);

    // 1) LN1
    ln_kernel<<<NTOK, 256>>>(hidden, ln1w, ln1b, xln1);

    // 2) fused QKV projection
    {
        GemmSegs sg;
        sg.end[0] = NHEAD*HEADD; sg.end[1] = NHEAD*HEADD + NKVH*HEADD; sg.end[2] = QKVN;
        sg.B[0] = wq;  sg.B[1] = wk;  sg.B[2] = wv;
        sg.ldb[0] = NHEAD*HEADD; sg.ldb[1] = NKVH*HEADD; sg.ldb[2] = NKVH*HEADD;
        sg.bias[0] = bq; sg.bias[1] = bk; sg.bias[2] = bv;
        sg.C[0] = qkv; sg.C[1] = qkv + NHEAD*HEADD; sg.C[2] = qkv + NHEAD*HEADD + NKVH*HEADD;
        sg.ldc[0] = QKVN; sg.ldc[1] = QKVN; sg.ldc[2] = QKVN;
        gemm_pipe<<<dim3(QKVN/BN, NTOK/BM, 1), 256, GEMM_SMEM_BYTES>>>(
            xln1, HDIM, sg, nullptr, NTOK, HDIM, nullptr, nullptr, nullptr, 0);
    }

    // 3) RoPE
    {
        int total = NTOK*(NHEAD+NKVH)*64;
        rope_kernel<<<(total+255)/256, 256>>>(qkv, posids);
    }

    // 4) tensor-core causal flash attention
    flash_kernel<<<dim3(SEQ/64, BATCH*NHEAD), 256, FL_SMEM_BYTES>>>(qkv, amask, attn);

    // 5) O projection + residual
    {
        GemmSegs sg;
        sg.end[0] = HDIM; sg.end[1] = HDIM; sg.end[2] = HDIM;
        sg.B[0] = wo; sg.B[1] = wo; sg.B[2] = wo;
        sg.ldb[0] = HDIM; sg.ldb[1] = HDIM; sg.ldb[2] = HDIM;
        sg.bias[0] = bo; sg.bias[1] = bo; sg.bias[2] = bo;
        sg.C[0] = h; sg.C[1] = h; sg.C[2] = h;
        sg.ldc[0] = HDIM; sg.ldc[1] = HDIM; sg.ldc[2] = HDIM;
        gemm_pipe<<<dim3(HDIM/BN, NTOK/BM, 1), 256, GEMM_SMEM_BYTES>>>(
            attn, NHEAD*HEADD, sg, hidden, NTOK, NHEAD*HEADD, nullptr, nullptr, nullptr, 0);
    }

    // 6) LN2
    ln_kernel<<<NTOK, 256>>>(h, ln2w, ln2b, xln2);
    // 7) gate + top2
    gate_kernel<<<NTOK, 256>>>(xln2, gatew, e01, w01);
    // 8) routing
    cudaMemsetAsync(counts, 0, NEXP*sizeof(int));
    route_count_kernel<<<(NTOK+255)/256, 256>>>(e01, counts, pos01);
    route_offset_kernel<<<1, 32>>>(counts, offsets);
    route_scatter_kernel<<<(NTOK+255)/256, 256>>>(e01, pos01, offsets, toklist, slot01);

    // 9) fused expert up-projections: [h1 | h3] = X @ [w1 | w3]
    {
        GemmSegs sg;
        sg.end[0] = FFN; sg.end[1] = 2*FFN; sg.end[2] = 2*FFN;
        sg.B[0] = w1; sg.B[1] = w3; sg.B[2] = w3;
        sg.ldb[0] = FFN; sg.ldb[1] = FFN; sg.ldb[2] = FFN;
        sg.bias[0] = nullptr; sg.bias[1] = nullptr; sg.bias[2] = nullptr;
        sg.C[0] = h1; sg.C[1] = h3; sg.C[2] = h3;
        sg.ldc[0] = FFN; sg.ldc[1] = FFN; sg.ldc[2] = FFN;
        gemm_pipe<<<dim3(2*FFN/BN, NTOK/BM, NEXP), 256, GEMM_SMEM_BYTES>>>(
            xln2, HDIM, sg, nullptr, NTOK, HDIM,
            toklist, counts, offsets, (long long)HDIM*FFN);
    }

    // 10) act = silu(h1)*h3
    silu_mul_kernel<<<16384, 256>>>(h1, h3);

    // 11) eo = act @ w2[e]
    {
        GemmSegs sg;
        sg.end[0] = HDIM; sg.end[1] = HDIM; sg.end[2] = HDIM;
        sg.B[0] = w2; sg.B[1] = w2; sg.B[2] = w2;
        sg.ldb[0] = HDIM; sg.ldb[1] = HDIM; sg.ldb[2] = HDIM;
        sg.bias[0] = nullptr; sg.bias[1] = nullptr; sg.bias[2] = nullptr;
        sg.C[0] = eo; sg.C[1] = eo; sg.C[2] = eo;
        sg.ldc[0] = HDIM; sg.ldc[1] = HDIM; sg.ldc[2] = HDIM;
        gemm_pipe<<<dim3(HDIM/BN, NTOK/BM, NEXP), 256, GEMM_SMEM_BYTES>>>(
            h1, FFN, sg, nullptr, NTOK, FFN,
            nullptr, counts, offsets, (long long)FFN*HDIM);
    }

    // 12) out = h + sum(top2 weights * expert outputs)
    combine_kernel<<<(int)(((long long)NTOK*HDIM + 255)/256), 256>>>(h, eo, slot01, w01, out);
}

// round 5
// speedup vs baseline: 1.2829x; 1.1107x over previous
#include <cuda_runtime.h>
#include <math.h>
#include <stdint.h>

// ---------------- problem constants ----------------
#define BATCH 2
#define SEQ   1024
#define HDIM  2048
#define NHEAD 16
#define NKVH  4
#define HEADD 128
#define FFN   4096
#define NEXP  8
#define NTOK  (BATCH*SEQ)          // 2048
#define QKVN  (NHEAD*HEADD + 2*NKVH*HEADD)   // 3072
#define LNEPS 1e-5f

// ---------------- device scratch (static, allowed) ----------------
__device__ float g_xln1[NTOK*HDIM];
__device__ float g_qkv [NTOK*QKVN];      // packed q(2048) | k(512) | v(512)
__device__ float g_attn[NTOK*NHEAD*HEADD];
__device__ float g_h   [NTOK*HDIM];
__device__ float g_xln2[NTOK*HDIM];      // raw fp32 (gate)
__device__ float g_xln2r[NTOK*HDIM];     // tf32-rounded (GEMM A)
__device__ int   g_e01 [NTOK*2];
__device__ float g_w01 [NTOK*2];
__device__ int   g_pos01[NTOK*2];
__device__ int   g_counts[NEXP];
__device__ int   g_offsets[NEXP];
__device__ int   g_toklist[2*NTOK];
__device__ int   g_slot01[NTOK*2];
__device__ float g_h1[2*NTOK*FFN];
__device__ float g_h3[2*NTOK*FFN];
__device__ float g_eo[2*NTOK*HDIM];

// ---------------- helpers ----------------
__device__ __forceinline__ uint32_t tf32u(float x){
    uint32_t u; asm("cvt.rna.tf32.f32 %0, %1;" : "=r"(u) : "f"(x));
    return u;
}
__device__ __forceinline__ float tf32f(float x){
    return __uint_as_float(tf32u(x));
}

__device__ __forceinline__ void mma_tf32(float* c, const uint32_t* a, const uint32_t* b){
    asm volatile(
      "mma.sync.aligned.m16n8k8.row.col.f32.tf32.tf32.f32 "
      "{%0,%1,%2,%3}, {%4,%5,%6,%7}, {%8,%9}, {%0,%1,%2,%3};\n"
      : "+f"(c[0]), "+f"(c[1]), "+f"(c[2]), "+f"(c[3])
      : "r"(a[0]), "r"(a[1]), "r"(a[2]), "r"(a[3]), "r"(b[0]), "r"(b[1]));
}

__device__ __forceinline__ void cpa16(float* smem, const float* gmem, bool pred){
    uint32_t s = (uint32_t)__cvta_generic_to_shared(smem);
    int sz = pred ? 16 : 0;
    asm volatile("cp.async.cg.shared.global [%0], [%1], 16, %2;\n"
                 :: "r"(s), "l"(gmem), "r"(sz));
}
#define CP_COMMIT() asm volatile("cp.async.commit_group;\n")
template<int N> __device__ __forceinline__ void cp_wait(){
    asm volatile("cp.async.wait_group %0;\n" :: "n"(N));
}

__device__ __forceinline__ float block_sum_256(float v){
    __shared__ float red[8];
    __shared__ float total;
    #pragma unroll
    for (int o = 16; o; o >>= 1) v += __shfl_xor_sync(0xffffffffu, v, o);
    if ((threadIdx.x & 31) == 0) red[threadIdx.x >> 5] = v;
    __syncthreads();
    if (threadIdx.x == 0){
        float s = 0.f;
        #pragma unroll
        for (int i = 0; i < 8; i++) s += red[i];
        total = s;
    }
    __syncthreads();
    float r = total;
    __syncthreads();
    return r;
}

// ---------------- LayerNorm: optional raw + tf32-rounded outputs ----------------
__global__ __launch_bounds__(256)
void ln_kernel(const float* __restrict__ x, const float* __restrict__ w,
               const float* __restrict__ b,
               float* __restrict__ yraw, float* __restrict__ yrnd){
    long long row = blockIdx.x;
    const float* xr = x + row * HDIM;
    float v[8]; float s = 0.f;
    #pragma unroll
    for (int i = 0; i < 8; i++){ v[i] = xr[threadIdx.x + 256*i]; s += v[i]; }
    float mean = block_sum_256(s) * (1.f/HDIM);
    float ss = 0.f;
    #pragma unroll
    for (int i = 0; i < 8; i++){ float d = v[i]-mean; ss += d*d; }
    float var = block_sum_256(ss) * (1.f/HDIM);
    float rstd = rsqrtf(var + LNEPS);
    #pragma unroll
    for (int i = 0; i < 8; i++){
        int c = threadIdx.x + 256*i;
        float o = (v[i]-mean)*rstd*w[c] + b[c];
        if (yraw) yraw[row*HDIM + c] = o;
        yrnd[row*HDIM + c] = tf32f(o);
    }
}

// ---------------- segmented, 3-stage pipelined tf32 GEMM ----------------
// A operand MUST already be RNA-rounded to the tf32 grid (producers do this).
struct GemmSegs {
    int end[3];
    const float* B[3];
    int ldb[3];
    const float* bias[3];
    float* C[3];
    int ldc[3];
};

#define BM 128
#define BN 128
#define BK 32
#define AS_STG   (128*36)
#define BS_STG   (32*136)
#define BS_BASE  (3*AS_STG)
#define GEMM_SMEM_FLOATS (BS_BASE + 3*BS_STG)
#define GEMM_SMEM_BYTES  (GEMM_SMEM_FLOATS*4)

__global__ __launch_bounds__(256, 2)
void gemm_pipe(const float* __restrict__ A, int lda,
               GemmSegs segs,
               const float* __restrict__ resid,
               int M, int K,
               const int* __restrict__ rowidx,
               const int* __restrict__ counts,
               const int* __restrict__ offsets,
               long long bStride)
{
    extern __shared__ float dynsm[];
#define ASM(st, r, c) dynsm[(st)*AS_STG + (r)*36 + (c)]
#define BSM(st, r, c) dynsm[BS_BASE + (st)*BS_STG + (r)*136 + (c)]

    int e = blockIdx.z;
    int rowStart = 0, Mm = M;
    if (counts){ Mm = counts[e]; rowStart = offsets[e]; }
    int mbase = blockIdx.y * BM;
    if (mbase >= Mm) return;
    int nbase = blockIdx.x * BN;

    int s = 0;
    if (nbase >= segs.end[0]) s = 1;
    if (nbase >= segs.end[1]) s = 2;
    int segStart = (s == 0) ? 0 : segs.end[s-1];
    int ln = nbase - segStart;
    const float* Bp   = segs.B[s] + (long long)e * bStride + ln;
    int          ldb  = segs.ldb[s];
    const float* bias = segs.bias[s] ? segs.bias[s] + ln : nullptr;
    float*       C    = segs.C[s] + ln;
    int          ldc  = segs.ldc[s];

    int tid  = threadIdx.x;
    int lane = tid & 31, wid = tid >> 5;
    int warpM = wid >> 2, warpN = wid & 3;
    int g = lane >> 2, t4 = lane & 3;

    int ar  = tid >> 3;       // 0..31
    int ac4 = tid & 7;        // 0..7
    const float* aptr[4]; bool aval[4];
    #pragma unroll
    for (int i = 0; i < 4; i++){
        int gr = mbase + ar + 32*i;
        bool valid = (gr < Mm);
        int arow = 0;
        if (valid) arow = rowidx ? rowidx[rowStart + gr] : (rowStart + gr);
        aval[i] = valid;
        aptr[i] = A + (long long)arow * lda + ac4*4;
    }
    int br  = tid >> 5;
    int bc4 = tid & 31;

    float acc[16][4];
    #pragma unroll
    for (int i = 0; i < 16; i++)
        #pragma unroll
        for (int j = 0; j < 4; j++) acc[i][j] = 0.f;

    int nk = K >> 5;

#define GEMM_ISSUE(KT, ST) do {                                           \
        _Pragma("unroll")                                                 \
        for (int i = 0; i < 4; i++)                                       \
            cpa16(&ASM(ST, ar + 32*i, ac4*4), aptr[i] + (KT)*32, aval[i]);\
        _Pragma("unroll")                                                 \
        for (int i = 0; i < 4; i++){                                      \
            int row = br + 8*i;                                           \
            cpa16(&BSM(ST, row, bc4*4),                                   \
                  Bp + (long long)((KT)*32 + row)*ldb + bc4*4, true);     \
        }                                                                 \
    } while(0)

    GEMM_ISSUE(0, 0); CP_COMMIT();
    GEMM_ISSUE(1, 1); CP_COMMIT();

    int cur = 0;
    for (int kt = 0; kt < nk; ++kt){
        if (kt + 1 < nk) cp_wait<1>(); else cp_wait<0>();
        __syncthreads();
        if (kt + 2 < nk){
            int nxt = cur + 2; if (nxt >= 3) nxt -= 3;
            GEMM_ISSUE(kt+2, nxt); CP_COMMIT();
        }

        #pragma unroll
        for (int ks = 0; ks < 4; ++ks){
            int k0 = ks*8;
            uint32_t af[4][4], bf[4][2];
            #pragma unroll
            for (int ma = 0; ma < 4; ma++){
                int r = warpM*64 + ma*16;
                af[ma][0] = __float_as_uint(ASM(cur, r+g  , k0+t4  ));
                af[ma][1] = __float_as_uint(ASM(cur, r+g+8, k0+t4  ));
                af[ma][2] = __float_as_uint(ASM(cur, r+g  , k0+t4+4));
                af[ma][3] = __float_as_uint(ASM(cur, r+g+8, k0+t4+4));
            }
            #pragma unroll
            for (int na = 0; na < 4; na++){
                int c = warpN*32 + na*8 + g;
                bf[na][0] = tf32u(BSM(cur, k0+t4  , c));
                bf[na][1] = tf32u(BSM(cur, k0+t4+4, c));
            }
            #pragma unroll
            for (int ma = 0; ma < 4; ma++)
                #pragma unroll
                for (int na = 0; na < 4; na++)
                    mma_tf32(acc[ma*4+na], af[ma], bf[na]);
        }
        cur = cur + 1; if (cur >= 3) cur -= 3;
    }

    // epilogue: float2 stores (cols 2*t4, 2*t4+1 adjacent)
    #pragma unroll
    for (int ma = 0; ma < 4; ma++){
        #pragma unroll
        for (int na = 0; na < 4; na++){
            float* a4 = acc[ma*4+na];
            #pragma unroll
            for (int half = 0; half < 2; half++){
                int lrow = warpM*64 + ma*16 + g + (half ? 8 : 0);
                int lcol = warpN*32 + na*8 + 2*t4;
                int gr = mbase + lrow;
                if (gr < Mm){
                    long long orow = rowStart + gr;
                    float v0 = a4[half*2+0];
                    float v1 = a4[half*2+1];
                    if (bias){ v0 += bias[lcol]; v1 += bias[lcol+1]; }
                    if (resid){
                        const float* rp = &resid[orow*(long long)ldc + nbase + lcol];
                        v0 += rp[0]; v1 += rp[1];
                    }
                    float2 o2 = make_float2(v0, v1);
                    *(float2*)&C[orow*(long long)ldc + lcol] = o2;
                }
            }
        }
    }
#undef ASM
#undef BSM
#undef GEMM_ISSUE
}

// ---------------- RoPE (in place on packed qkv) ----------------
__global__ __launch_bounds__(256)
void rope_kernel(float* __restrict__ qkv, const int* __restrict__ pos_ids){
    int idx = blockIdx.x*256 + threadIdx.x;
    const int total = NTOK*(NHEAD+NKVH)*64;
    if (idx >= total) return;
    int j    = idx & 63;
    int rest = idx >> 6;
    int head = rest % (NHEAD+NKVH);
    int t    = rest / (NHEAD+NKVH);
    float* p;
    if (head < NHEAD) p = qkv + (long long)t*QKVN + head*HEADD;
    else              p = qkv + (long long)t*QKVN + NHEAD*HEADD + (head-NHEAD)*HEADD;
    double inv = exp((double)j * -0.21586735246819178); // -ln(1e6)/64
    float th = (float)pos_ids[t] * (float)inv;
    float sn, cs; sincosf(th, &sn, &cs);
    float x0 = p[j], x1 = p[j+64];
    p[j]    = x0*cs - x1*sn;
    p[j+64] = x1*cs + x0*sn;
}

// ---------------- tensor-core flash attention (tf32, causal GQA) ----------------
// q-tile 64, k-tile 32, 8 warps, 2 CTAs/SM.
#define FKT 32
#define FL_QS   0
#define FL_KS   (FL_QS + 64*132)
#define FL_VS   (FL_KS + FKT*132)
#define FL_PS   (FL_VS + FKT*136)
#define FL_MROW (FL_PS + 64*36)
#define FL_LROW (FL_MROW + 64)
#define FL_SROW (FL_LROW + 64)
#define FL_MK   (FL_SROW + 64)
#define FL_SMEM_FLOATS (FL_MK + FKT)
#define FL_SMEM_BYTES  (FL_SMEM_FLOATS*4)

__global__ __launch_bounds__(256, 2)
void flash_kernel(const float* __restrict__ qkv, const int* __restrict__ amask,
                  float* __restrict__ O)
{
    extern __shared__ float sm[];
    float* Qs = sm + FL_QS;
    float* Ks = sm + FL_KS;
    float* Vs = sm + FL_VS;
    float* Ps = sm + FL_PS;
    float* mrow = sm + FL_MROW;
    float* lrow = sm + FL_LROW;
    float* srow = sm + FL_SROW;
    int*   mk   = (int*)(sm + FL_MK);

    int qt = blockIdx.x;
    int bh = blockIdx.y;
    int b  = bh >> 4, h = bh & 15;
    int kvh = h >> 2;
    int tid = threadIdx.x;
    int lane = tid & 31, wid = tid >> 5;
    int g = lane >> 2, t4 = lane & 3;
    int mS = wid & 3;        // 16-row slab
    int nH = wid >> 2;       // S: 16-col half ; PV: 64-col half

    // load Q tile (tf32-rounded at store)
    for (int e4 = tid; e4 < 64*32; e4 += 256){
        int row = e4 >> 5; int d4 = (e4 & 31)*4;
        const float* src = &qkv[(long long)(b*SEQ + qt*64 + row)*QKVN + h*HEADD + d4];
        float4 v = *(const float4*)src;
        Qs[row*132 + d4 + 0] = tf32f(v.x);
        Qs[row*132 + d4 + 1] = tf32f(v.y);
        Qs[row*132 + d4 + 2] = tf32f(v.z);
        Qs[row*132 + d4 + 3] = tf32f(v.w);
    }
    if (tid < 64){ mrow[tid] = -1e30f; lrow[tid] = 0.f; }

    float oacc[8][4];
    #pragma unroll
    for (int i = 0; i < 8; i++)
        #pragma unroll
        for (int j = 0; j < 4; j++) oacc[i][j] = 0.f;

    const float iscale = 0.08838834764831843f; // 1/sqrt(128)

    int nkt = 2*qt + 2;   // k-tiles of 32 covering causal range
    for (int kt = 0; kt < nkt; ++kt){
        __syncthreads();   // prev PV done (and Q load on first iter)
        for (int e4 = tid; e4 < FKT*32; e4 += 256){
            int kk = e4 >> 5; int d4 = (e4 & 31)*4;
            long long base = (long long)(b*SEQ + kt*FKT + kk)*QKVN + NHEAD*HEADD + kvh*HEADD;
            float4 kv4 = *(const float4*)&qkv[base + d4];
            Ks[kk*132 + d4 + 0] = tf32f(kv4.x);
            Ks[kk*132 + d4 + 1] = tf32f(kv4.y);
            Ks[kk*132 + d4 + 2] = tf32f(kv4.z);
            Ks[kk*132 + d4 + 3] = tf32f(kv4.w);
            float4 vv4 = *(const float4*)&qkv[base + NKVH*HEADD + d4];
            Vs[kk*136 + d4 + 0] = tf32f(vv4.x);
            Vs[kk*136 + d4 + 1] = tf32f(vv4.y);
            Vs[kk*136 + d4 + 2] = tf32f(vv4.z);
            Vs[kk*136 + d4 + 3] = tf32f(vv4.w);
        }
        if (tid < FKT) mk[tid] = amask[b*SEQ + kt*FKT + tid];
        __syncthreads();

        // S = Q @ K^T : warp computes 16x16 (rows 16*mS, cols 16*nH)
        float sacc[2][4];
        #pragma unroll
        for (int i = 0; i < 2; i++)
            #pragma unroll
            for (int j = 0; j < 4; j++) sacc[i][j] = 0.f;
        #pragma unroll
        for (int ks = 0; ks < 16; ++ks){
            int k0 = ks*8;
            uint32_t a[4];
            int r = 16*mS;
            a[0] = __float_as_uint(Qs[(r+g  )*132 + k0+t4  ]);
            a[1] = __float_as_uint(Qs[(r+g+8)*132 + k0+t4  ]);
            a[2] = __float_as_uint(Qs[(r+g  )*132 + k0+t4+4]);
            a[3] = __float_as_uint(Qs[(r+g+8)*132 + k0+t4+4]);
            #pragma unroll
            for (int j = 0; j < 2; j++){
                int c = 16*nH + 8*j + g;
                uint32_t bfr[2];
                bfr[0] = __float_as_uint(Ks[c*132 + k0+t4  ]);
                bfr[1] = __float_as_uint(Ks[c*132 + k0+t4+4]);
                mma_tf32(sacc[j], a, bfr);
            }
        }
        // write S to Ps with scale + mask
        #pragma unroll
        for (int j = 0; j < 2; j++){
            #pragma unroll
            for (int cr = 0; cr < 4; cr++){
                int row = 16*mS + g + ((cr >= 2) ? 8 : 0);
                int col = 16*nH + 8*j + 2*t4 + (cr & 1);
                int sq = qt*64 + row, sk = kt*FKT + col;
                float vv = sacc[j][cr]*iscale;
                if (sk > sq || mk[col] == 0) vv = -1e30f;
                Ps[row*36 + col] = vv;
            }
        }
        __syncthreads();

        // online softmax per row (64 rows x 32 cols); probs stored tf32-rounded
        if (tid < 64){
            int r = tid;
            float mo = mrow[r], mx = mo;
            #pragma unroll 8
            for (int kk = 0; kk < FKT; kk++) mx = fmaxf(mx, Ps[r*36+kk]);
            float sc = __expf(mo - mx);
            float ssum = 0.f;
            #pragma unroll 8
            for (int kk = 0; kk < FKT; kk++){
                float p = __expf(Ps[r*36+kk] - mx);
                ssum += p;
                Ps[r*36+kk] = tf32f(p);
            }
            lrow[r] = lrow[r]*sc + ssum;
            mrow[r] = mx;
            srow[r] = sc;
        }
        __syncthreads();

        // rescale O accumulators, then O += P @ V (warp: rows 16*mS, cols 64*nH)
        {
            float sc0 = srow[16*mS + g];
            float sc1 = srow[16*mS + g + 8];
            #pragma unroll
            for (int j = 0; j < 8; j++){
                oacc[j][0] *= sc0; oacc[j][1] *= sc0;
                oacc[j][2] *= sc1; oacc[j][3] *= sc1;
            }
        }
        #pragma unroll
        for (int ks = 0; ks < 4; ++ks){
            int k0 = ks*8;
            uint32_t a[4];
            int r = 16*mS;
            a[0] = __float_as_uint(Ps[(r+g  )*36 + k0+t4  ]);
            a[1] = __float_as_uint(Ps[(r+g+8)*36 + k0+t4  ]);
            a[2] = __float_as_uint(Ps[(r+g  )*36 + k0+t4+4]);
            a[3] = __float_as_uint(Ps[(r+g+8)*36 + k0+t4+4]);
            #pragma unroll
            for (int j = 0; j < 8; j++){
                int c = 64*nH + 8*j + g;
                uint32_t bfr[2];
                bfr[0] = __float_as_uint(Vs[(k0+t4  )*136 + c]);
                bfr[1] = __float_as_uint(Vs[(k0+t4+4)*136 + c]);
                mma_tf32(oacc[j], a, bfr);
            }
        }
    }

    // epilogue: normalize, round to tf32 grid (attn is a GEMM-A operand), float2 stores
    #pragma unroll
    for (int j = 0; j < 8; j++){
        #pragma unroll
        for (int half = 0; half < 2; half++){
            int row = 16*mS + g + (half ? 8 : 0);
            int col = 64*nH + 8*j + 2*t4;
            int sq = qt*64 + row;
            float inv = 1.f / lrow[row];
            float2 o2 = make_float2(tf32f(oacc[j][half*2+0]*inv),
                                    tf32f(oacc[j][half*2+1]*inv));
            *(float2*)&O[(((long long)(b*SEQ + sq))*NHEAD + h)*HEADD + col] = o2;
        }
    }
}

// ---------------- gate + top2 (raw fp32 input — selection must match reference) ----------------
__global__ __launch_bounds__(256)
void gate_kernel(const float* __restrict__ x2, const float* __restrict__ gw,
                 int* __restrict__ e01, float* __restrict__ w01){
    long long t = blockIdx.x;
    const float* xr = x2 + t*HDIM;
    float part[NEXP];
    #pragma unroll
    for (int e = 0; e < NEXP; e++) part[e] = 0.f;
    for (int hh = threadIdx.x; hh < HDIM; hh += 256){
        float xv = xr[hh];
        const float* gp = gw + (long long)hh*NEXP;
        #pragma unroll
        for (int e = 0; e < NEXP; e++) part[e] += xv*gp[e];
    }
    __shared__ float red[8][NEXP];
    #pragma unroll
    for (int e = 0; e < NEXP; e++){
        float v = part[e];
        #pragma unroll
        for (int o = 16; o; o >>= 1) v += __shfl_xor_sync(0xffffffffu, v, o);
        if ((threadIdx.x & 31) == 0) red[threadIdx.x >> 5][e] = v;
    }
    __syncthreads();
    if (threadIdx.x == 0){
        float lg[NEXP];
        #pragma unroll
        for (int e = 0; e < NEXP; e++){
            float s = 0.f;
            #pragma unroll
            for (int w8 = 0; w8 < 8; w8++) s += red[w8][e];
            lg[e] = s;
        }
        int b0 = 0;
        #pragma unroll
        for (int e = 1; e < NEXP; e++) if (lg[e] > lg[b0]) b0 = e;
        int b1 = -1;
        #pragma unroll
        for (int e = 0; e < NEXP; e++)
            if (e != b0 && (b1 < 0 || lg[e] > lg[b1])) b1 = e;
        float t0 = 1.f / (1.f + expf(lg[b1] - lg[b0]));
        e01[2*t] = b0; e01[2*t+1] = b1;
        w01[2*t] = t0; w01[2*t+1] = 1.f - t0;
    }
}

// ---------------- routing ----------------
__global__ void route_count_kernel(const int* __restrict__ e01,
                                   int* __restrict__ counts, int* __restrict__ pos01){
    int t = blockIdx.x*blockDim.x + threadIdx.x;
    if (t < NTOK){
        pos01[2*t]   = atomicAdd(&counts[e01[2*t]],   1);
        pos01[2*t+1] = atomicAdd(&counts[e01[2*t+1]], 1);
    }
}
__global__ void route_offset_kernel(const int* __restrict__ counts, int* __restrict__ offsets){
    if (threadIdx.x == 0 && blockIdx.x == 0){
        int s = 0;
        for (int e = 0; e < NEXP; e++){ offsets[e] = s; s += counts[e]; }
    }
}
__global__ void route_scatter_kernel(const int* __restrict__ e01, const int* __restrict__ pos01,
                                     const int* __restrict__ offsets,
                                     int* __restrict__ toklist, int* __restrict__ slot01){
    int t = blockIdx.x*blockDim.x + threadIdx.x;
    if (t < NTOK){
        #pragma unroll
        for (int j = 0; j < 2; j++){
            int sl = offsets[e01[2*t+j]] + pos01[2*t+j];
            toklist[sl] = t;
            slot01[2*t+j] = sl;
        }
    }
}

// ---------------- silu(h1)*h3 (in place into h1, tf32-rounded) ----------------
__global__ __launch_bounds__(256)
void silu_mul_kernel(float* __restrict__ h1, const float* __restrict__ h3){
    long long n = (long long)2*NTOK*FFN;
    for (long long i = blockIdx.x*256LL + threadIdx.x; i < n; i += gridDim.x*256LL){
        float v = h1[i];
        h1[i] = tf32f(v / (1.f + expf(-v)) * h3[i]);
    }
}

// ---------------- final combine ----------------
__global__ __launch_bounds__(256)
void combine_kernel(const float* __restrict__ h, const float* __restrict__ eo,
                    const int* __restrict__ slot01, const float* __restrict__ w01,
                    float* __restrict__ out){
    long long idx = blockIdx.x*256LL + threadIdx.x;
    if (idx >= (long long)NTOK*HDIM) return;
    int t = (int)(idx >> 11);
    int c = (int)(idx & 2047);
    float v = h[idx];
    v += w01[2*t]   * eo[(long long)slot01[2*t]  *HDIM + c];
    v += w01[2*t+1] * eo[(long long)slot01[2*t+1]*HDIM + c];
    out[idx] = v;
}

// ---------------- launch ----------------
extern "C" void kernel_launch(void* const* d_in, const int* in_sizes, int n_in,
                              void* d_out, int out_size){
    const float* hidden = (const float*)d_in[0];
    const int*   amask  = (const int*)  d_in[1];
    const int*   posids = (const int*)  d_in[2];
    const float* ln1w = (const float*)d_in[3];
    const float* ln1b = (const float*)d_in[4];
    const float* ln2w = (const float*)d_in[5];
    const float* ln2b = (const float*)d_in[6];
    const float* wq = (const float*)d_in[7];
    const float* bq = (const float*)d_in[8];
    const float* wk = (const float*)d_in[9];
    const float* bk = (const float*)d_in[10];
    const float* wv = (const float*)d_in[11];
    const float* bv = (const float*)d_in[12];
    const float* wo = (const float*)d_in[13];
    const float* bo = (const float*)d_in[14];
    const float* gatew = (const float*)d_in[15];
    const float* w1 = (const float*)d_in[16];
    const float* w2 = (const float*)d_in[17];
    const float* w3 = (const float*)d_in[18];
    float* out = (float*)d_out;

    float *xln1, *qkv, *attn, *h, *xln2, *xln2r, *w01, *h1, *h3, *eo;
    int *e01, *pos01, *counts, *offsets, *toklist, *slot01;
    cudaGetSymbolAddress((void**)&xln1, g_xln1);
    cudaGetSymbolAddress((void**)&qkv, g_qkv);
    cudaGetSymbolAddress((void**)&attn, g_attn);
    cudaGetSymbolAddress((void**)&h, g_h);
    cudaGetSymbolAddress((void**)&xln2, g_xln2);
    cudaGetSymbolAddress((void**)&xln2r, g_xln2r);
    cudaGetSymbolAddress((void**)&e01, g_e01);
    cudaGetSymbolAddress((void**)&w01, g_w01);
    cudaGetSymbolAddress((void**)&pos01, g_pos01);
    cudaGetSymbolAddress((void**)&counts, g_counts);
    cudaGetSymbolAddress((void**)&offsets, g_offsets);
    cudaGetSymbolAddress((void**)&toklist, g_toklist);
    cudaGetSymbolAddress((void**)&slot01, g_slot01);
    cudaGetSymbolAddress((void**)&h1, g_h1);
    cudaGetSymbolAddress((void**)&h3, g_h3);
    cudaGetSymbolAddress((void**)&eo, g_eo);

    cudaFuncSetAttribute(flash_kernel, cudaFuncAttributeMaxDynamicSharedMemorySize, FL_SMEM_BYTES);
    cudaFuncSetAttribute(gemm_pipe,   cudaFuncAttributeMaxDynamicSharedMemorySize, GEMM_SMEM_BYTES);

    // 1) LN1 (rounded only — downstream is all-continuous)
    ln_kernel<<<NTOK, 256>>>(hidden, ln1w, ln1b, nullptr, xln1);

    // 2) fused QKV projection
    {
        GemmSegs sg;
        sg.end[0] = NHEAD*HEADD; sg.end[1] = NHEAD*HEADD + NKVH*HEADD; sg.end[2] = QKVN;
        sg.B[0] = wq;  sg.B[1] = wk;  sg.B[2] = wv;
        sg.ldb[0] = NHEAD*HEADD; sg.ldb[1] = NKVH*HEADD; sg.ldb[2] = NKVH*HEADD;
        sg.bias[0] = bq; sg.bias[1] = bk; sg.bias[2] = bv;
        sg.C[0] = qkv; sg.C[1] = qkv + NHEAD*HEADD; sg.C[2] = qkv + NHEAD*HEADD + NKVH*HEADD;
        sg.ldc[0] = QKVN; sg.ldc[1] = QKVN; sg.ldc[2] = QKVN;
        gemm_pipe<<<dim3(QKVN/BN, NTOK/BM, 1), 256, GEMM_SMEM_BYTES>>>(
            xln1, HDIM, sg, nullptr, NTOK, HDIM, nullptr, nullptr, nullptr, 0);
    }

    // 3) RoPE
    {
        int total = NTOK*(NHEAD+NKVH)*64;
        rope_kernel<<<(total+255)/256, 256>>>(qkv, posids);
    }

    // 4) tensor-core causal flash attention
    flash_kernel<<<dim3(SEQ/64, BATCH*NHEAD), 256, FL_SMEM_BYTES>>>(qkv, amask, attn);

    // 5) O projection + residual
    {
        GemmSegs sg;
        sg.end[0] = HDIM; sg.end[1] = HDIM; sg.end[2] = HDIM;
        sg.B[0] = wo; sg.B[1] = wo; sg.B[2] = wo;
        sg.ldb[0] = HDIM; sg.ldb[1] = HDIM; sg.ldb[2] = HDIM;
        sg.bias[0] = bo; sg.bias[1] = bo; sg.bias[2] = bo;
        sg.C[0] = h; sg.C[1] = h; sg.C[2] = h;
        sg.ldc[0] = HDIM; sg.ldc[1] = HDIM; sg.ldc[2] = HDIM;
        gemm_pipe<<<dim3(HDIM/BN, NTOK/BM, 1), 256, GEMM_SMEM_BYTES>>>(
            attn, NHEAD*HEADD, sg, hidden, NTOK, NHEAD*HEADD, nullptr, nullptr, nullptr, 0);
    }

    // 6) LN2: raw (gate) + rounded (GEMM A)
    ln_kernel<<<NTOK, 256>>>(h, ln2w, ln2b, xln2, xln2r);
    // 7) gate + top2 from RAW xln2 (expert selection must match fp32 reference)
    gate_kernel<<<NTOK, 256>>>(xln2, gatew, e01, w01);
    // 8) routing
    cudaMemsetAsync(counts, 0, NEXP*sizeof(int));
    route_count_kernel<<<(NTOK+255)/256, 256>>>(e01, counts, pos01);
    route_offset_kernel<<<1, 32>>>(counts, offsets);
    route_scatter_kernel<<<(NTOK+255)/256, 256>>>(e01, pos01, offsets, toklist, slot01);

    // 9) fused expert up-projections: [h1 | h3] = Xr @ [w1 | w3]
    {
        GemmSegs sg;
        sg.end[0] = FFN; sg.end[1] = 2*FFN; sg.end[2] = 2*FFN;
        sg.B[0] = w1; sg.B[1] = w3; sg.B[2] = w3;
        sg.ldb[0] = FFN; sg.ldb[1] = FFN; sg.ldb[2] = FFN;
        sg.bias[0] = nullptr; sg.bias[1] = nullptr; sg.bias[2] = nullptr;
        sg.C[0] = h1; sg.C[1] = h3; sg.C[2] = h3;
        sg.ldc[0] = FFN; sg.ldc[1] = FFN; sg.ldc[2] = FFN;
        gemm_pipe<<<dim3(2*FFN/BN, NTOK/BM, NEXP), 256, GEMM_SMEM_BYTES>>>(
            xln2r, HDIM, sg, nullptr, NTOK, HDIM,
            toklist, counts, offsets, (long long)HDIM*FFN);
    }

    // 10) act = silu(h1)*h3
    silu_mul_kernel<<<16384, 256>>>(h1, h3);

    // 11) eo = act @ w2[e]
    {
        GemmSegs sg;
        sg.end[0] = HDIM; sg.end[1] = HDIM; sg.end[2] = HDIM;
        sg.B[0] = w2; sg.B[1] = w2; sg.B[2] = w2;
        sg.ldb[0] = HDIM; sg.ldb[1] = HDIM; sg.ldb[2] = HDIM;
        sg.bias[0] = nullptr; sg.bias[1] = nullptr; sg.bias[2] = nullptr;
        sg.C[0] = eo; sg.C[1] = eo; sg.C[2] = eo;
        sg.ldc[0] = HDIM; sg.ldc[1] = HDIM; sg.ldc[2] = HDIM;
        gemm_pipe<<<dim3(HDIM/BN, NTOK/BM, NEXP), 256, GEMM_SMEM_BYTES>>>(
            h1, FFN, sg, nullptr, NTOK, FFN,
            nullptr, counts, offsets, (long long)FFN*HDIM);
    }

    // 12) out = h + sum(top2 weights * expert outputs)
    combine_kernel<<<(int)(((long long)NTOK*HDIM + 255)/256), 256>>>(h, eo, slot01, w01, out);
}

// round 6
// speedup vs baseline: 1.5220x; 1.1863x over previous
#include <cuda_runtime.h>
#include <cuda_fp16.h>
#include <math.h>
#include <stdint.h>

// ---------------- problem constants ----------------
#define BATCH 2
#define SEQ   1024
#define HDIM  2048
#define NHEAD 16
#define NKVH  4
#define HEADD 128
#define FFN   4096
#define NEXP  8
#define NTOK  (BATCH*SEQ)          // 2048
#define QKVN  (NHEAD*HEADD + 2*NKVH*HEADD)   // 3072
#define NSLOT (2*NTOK)             // 4096
#define LNEPS 1e-5f

// ---------------- device scratch ----------------
__device__ __half g_xln1h[NTOK*HDIM];
__device__ __half g_qkvh [NTOK*QKVN];
__device__ __half g_attnh[NTOK*NHEAD*HEADD];
__device__ float  g_h    [NTOK*HDIM];
__device__ float  g_xln2 [NTOK*HDIM];     // raw fp32 (gate)
__device__ __half g_xln2h[NTOK*HDIM];
__device__ float  g_h13  [NSLOT*2*FFN];   // 134 MB (h1|h3 per slot)
__device__ __half g_acth [NSLOT*FFN];     // 33 MB
__device__ float  g_eo   [NSLOT*HDIM];    // 33 MB
// transposed fp16 weights [N][K]
__device__ __half g_wqkvT[QKVN*HDIM];
__device__ __half g_woT  [HDIM*HDIM];
__device__ __half g_w13T [NEXP*2*FFN*HDIM];  // 268 MB
__device__ __half g_w2T  [NEXP*HDIM*FFN];    // 134 MB
__device__ float  g_bqkv [QKVN];
// routing
__device__ int   g_e01 [NTOK*2];
__device__ float g_w01 [NTOK*2];
__device__ int   g_pos01[NTOK*2];
__device__ int   g_counts[NEXP];
__device__ int   g_offsets[NEXP];
__device__ int   g_toklist[NSLOT];
__device__ int   g_slot01[NTOK*2];

// ---------------- helpers ----------------
__device__ __forceinline__ uint32_t tf32u(float x){
    uint32_t u; asm("cvt.rna.tf32.f32 %0, %1;" : "=r"(u) : "f"(x));
    return u;
}
__device__ __forceinline__ float tf32f(float x){ return __uint_as_float(tf32u(x)); }

__device__ __forceinline__ void mma_tf32(float* c, const uint32_t* a, const uint32_t* b){
    asm volatile(
      "mma.sync.aligned.m16n8k8.row.col.f32.tf32.tf32.f32 "
      "{%0,%1,%2,%3}, {%4,%5,%6,%7}, {%8,%9}, {%0,%1,%2,%3};\n"
      : "+f"(c[0]), "+f"(c[1]), "+f"(c[2]), "+f"(c[3])
      : "r"(a[0]), "r"(a[1]), "r"(a[2]), "r"(a[3]), "r"(b[0]), "r"(b[1]));
}
__device__ __forceinline__ void mma_f16(float* c, const uint32_t* a, const uint32_t* b){
    asm volatile(
      "mma.sync.aligned.m16n8k16.row.col.f32.f16.f16.f32 "
      "{%0,%1,%2,%3}, {%4,%5,%6,%7}, {%8,%9}, {%0,%1,%2,%3};\n"
      : "+f"(c[0]), "+f"(c[1]), "+f"(c[2]), "+f"(c[3])
      : "r"(a[0]), "r"(a[1]), "r"(a[2]), "r"(a[3]), "r"(b[0]), "r"(b[1]));
}

__device__ __forceinline__ void cpa16h(__half* smem, const __half* gmem, bool pred){
    uint32_t s = (uint32_t)__cvta_generic_to_shared(smem);
    int sz = pred ? 16 : 0;
    asm volatile("cp.async.cg.shared.global [%0], [%1], 16, %2;\n"
                 :: "r"(s), "l"(gmem), "r"(sz));
}
#define CP_COMMIT() asm volatile("cp.async.commit_group;\n")
template<int N> __device__ __forceinline__ void cp_wait(){
    asm volatile("cp.async.wait_group %0;\n" :: "n"(N));
}

__device__ __forceinline__ float block_sum_256(float v){
    __shared__ float red[8];
    __shared__ float total;
    #pragma unroll
    for (int o = 16; o; o >>= 1) v += __shfl_xor_sync(0xffffffffu, v, o);
    if ((threadIdx.x & 31) == 0) red[threadIdx.x >> 5] = v;
    __syncthreads();
    if (threadIdx.x == 0){
        float s = 0.f;
        #pragma unroll
        for (int i = 0; i < 8; i++) s += red[i];
        total = s;
    }
    __syncthreads();
    float r = total;
    __syncthreads();
    return r;
}

// ---------------- weight transpose + fp16 convert: dst[n][k] = (half)src[k][n] ----------------
__global__ __launch_bounds__(256)
void transcvt(const float* __restrict__ src, __half* __restrict__ dst,
              int K, int N, long long srcE, long long dstE){
    src += (long long)blockIdx.z * srcE;
    dst += (long long)blockIdx.z * dstE;
    __shared__ float t[32][33];
    int k0 = blockIdx.x*32, n0 = blockIdx.y*32;
    int tx = threadIdx.x & 31, ty = threadIdx.x >> 5;   // 32 x 8
    #pragma unroll
    for (int i = 0; i < 4; i++)
        t[ty+8*i][tx] = src[(long long)(k0+ty+8*i)*N + n0+tx];
    __syncthreads();
    #pragma unroll
    for (int i = 0; i < 4; i++)
        dst[(long long)(n0+ty+8*i)*K + k0+tx] = __float2half(t[tx][ty+8*i]);
}

__global__ void concat_bias(const float* bq, const float* bk, const float* bv, float* dst){
    int i = blockIdx.x*256 + threadIdx.x;
    if (i < NHEAD*HEADD) dst[i] = bq[i];
    else if (i < NHEAD*HEADD + NKVH*HEADD) dst[i] = bk[i - NHEAD*HEADD];
    else if (i < QKVN) dst[i] = bv[i - NHEAD*HEADD - NKVH*HEADD];
}

// ---------------- LayerNorm: optional raw float + fp16 outputs ----------------
__global__ __launch_bounds__(256)
void ln_kernel(const float* __restrict__ x, const float* __restrict__ w,
               const float* __restrict__ b,
               float* __restrict__ yraw, __half* __restrict__ yh){
    long long row = blockIdx.x;
    const float* xr = x + row * HDIM;
    float v[8]; float s = 0.f;
    #pragma unroll
    for (int i = 0; i < 8; i++){ v[i] = xr[threadIdx.x + 256*i]; s += v[i]; }
    float mean = block_sum_256(s) * (1.f/HDIM);
    float ss = 0.f;
    #pragma unroll
    for (int i = 0; i < 8; i++){ float d = v[i]-mean; ss += d*d; }
    float var = block_sum_256(ss) * (1.f/HDIM);
    float rstd = rsqrtf(var + LNEPS);
    #pragma unroll
    for (int i = 0; i < 8; i++){
        int c = threadIdx.x + 256*i;
        float o = (v[i]-mean)*rstd*w[c] + b[c];
        if (yraw) yraw[row*HDIM + c] = o;
        yh[row*HDIM + c] = __float2half(o);
    }
}

// ---------------- fp16 tensor-core GEMM, 3-stage cp.async ----------------
// C[M,N] = A[M,K](half) @ B[K,N] with B given TRANSPOSED as BT[N][K] (half).
// Block 128x256, BK=32, 8 warps (2x4), warp tile 64x64.
#define GA_STG (128*40)           // halves per A stage (row stride 40)
#define GB_STG (256*40)           // halves per B stage
#define GB_BASE (3*GA_STG)
#define GEMM_SMEM_BYTES ((GB_BASE + 3*GB_STG)*2)

__global__ __launch_bounds__(256)
void gemm_f16(const __half* __restrict__ A, int lda,
              const __half* __restrict__ BT, long long bStride,
              float* __restrict__ Cf, __half* __restrict__ Ch, int ldc,
              const float* __restrict__ bias, const float* __restrict__ resid,
              int M, int N, int K,
              const int* __restrict__ rowidx,
              const int* __restrict__ counts,
              const int* __restrict__ offsets)
{
    extern __shared__ __half hsm[];
#define ASH(st, r, c) hsm[(st)*GA_STG + (r)*40 + (c)]
#define BSH(st, n, c) hsm[GB_BASE + (st)*GB_STG + (n)*40 + (c)]

    int e = blockIdx.z;
    int rowStart = 0, Mm = M;
    if (counts){ Mm = counts[e]; rowStart = offsets[e]; }
    int mbase = blockIdx.y * 128;
    if (mbase >= Mm) return;
    int nbase = blockIdx.x * 256;
    const __half* Bp = BT + (long long)e * bStride;

    int tid  = threadIdx.x;
    int lane = tid & 31, wid = tid >> 5;
    int warpM = wid >> 2, warpN = wid & 3;
    int g = lane >> 2, t4 = lane & 3;

    // A loads: thread -> row ar=tid>>1, half-sel hsel=tid&1 (2 x 16B chunks)
    int ar = tid >> 1, hsel = tid & 1;
    bool aval = (mbase + ar < Mm);
    int arow = 0;
    if (aval) arow = rowidx ? rowidx[rowStart + mbase + ar] : (rowStart + mbase + ar);
    const __half* aptr = A + (long long)arow * lda + hsel*16;
    // B loads: thread -> rows (tid>>2)+64*i, chunk tid&3
    int bn0 = tid >> 2, bch = tid & 3;

    float acc[32][4];
    #pragma unroll
    for (int i = 0; i < 32; i++)
        #pragma unroll
        for (int j = 0; j < 4; j++) acc[i][j] = 0.f;

    int nk = K >> 5;

#define GEMM_ISSUE(KT, ST) do {                                             \
        cpa16h(&ASH(ST, ar, hsel*16),     aptr + (KT)*32,       aval);      \
        cpa16h(&ASH(ST, ar, hsel*16 + 8), aptr + (KT)*32 + 8,   aval);      \
        _Pragma("unroll")                                                   \
        for (int i = 0; i < 4; i++){                                        \
            int n = bn0 + 64*i;                                             \
            cpa16h(&BSH(ST, n, bch*8),                                      \
                   Bp + (long long)(nbase + n)*K + (KT)*32 + bch*8, true);  \
        }                                                                   \
    } while(0)

    GEMM_ISSUE(0, 0); CP_COMMIT();
    GEMM_ISSUE(1, 1); CP_COMMIT();

    int cur = 0;
    for (int kt = 0; kt < nk; ++kt){
        if (kt + 1 < nk) cp_wait<1>(); else cp_wait<0>();
        __syncthreads();
        if (kt + 2 < nk){
            int nxt = cur + 2; if (nxt >= 3) nxt -= 3;
            GEMM_ISSUE(kt+2, nxt); CP_COMMIT();
        }

        #pragma unroll
        for (int ks = 0; ks < 2; ++ks){
            int k0 = ks*16 + 2*t4;
            uint32_t af[4][4], bf[8][2];
            #pragma unroll
            for (int ma = 0; ma < 4; ma++){
                int r = warpM*64 + ma*16;
                af[ma][0] = *(const uint32_t*)&ASH(cur, r+g  , k0    );
                af[ma][1] = *(const uint32_t*)&ASH(cur, r+g+8, k0    );
                af[ma][2] = *(const uint32_t*)&ASH(cur, r+g  , k0 + 8);
                af[ma][3] = *(const uint32_t*)&ASH(cur, r+g+8, k0 + 8);
            }
            #pragma unroll
            for (int na = 0; na < 8; na++){
                int c = warpN*64 + na*8 + g;
                bf[na][0] = *(const uint32_t*)&BSH(cur, c, k0    );
                bf[na][1] = *(const uint32_t*)&BSH(cur, c, k0 + 8);
            }
            #pragma unroll
            for (int ma = 0; ma < 4; ma++)
                #pragma unroll
                for (int na = 0; na < 8; na++)
                    mma_f16(acc[ma*8+na], af[ma], bf[na]);
        }
        cur = cur + 1; if (cur >= 3) cur -= 3;
    }

    // epilogue
    #pragma unroll
    for (int ma = 0; ma < 4; ma++){
        #pragma unroll
        for (int na = 0; na < 8; na++){
            float* a4 = acc[ma*8+na];
            #pragma unroll
            for (int half_ = 0; half_ < 2; half_++){
                int lrow = warpM*64 + ma*16 + g + (half_ ? 8 : 0);
                int gcol = nbase + warpN*64 + na*8 + 2*t4;
                int gr = mbase + lrow;
                if (gr < Mm){
                    long long orow = rowStart + gr;
                    float v0 = a4[half_*2+0];
                    float v1 = a4[half_*2+1];
                    if (bias){ v0 += bias[gcol]; v1 += bias[gcol+1]; }
                    if (resid){
                        const float* rp = &resid[orow*(long long)ldc + gcol];
                        v0 += rp[0]; v1 += rp[1];
                    }
                    if (Cf){
                        *(float2*)&Cf[orow*(long long)ldc + gcol] = make_float2(v0, v1);
                    } else {
                        *(__half2*)&Ch[orow*(long long)ldc + gcol] = __floats2half2_rn(v0, v1);
                    }
                }
            }
        }
    }
#undef ASH
#undef BSH
#undef GEMM_ISSUE
}

// ---------------- RoPE (in place on packed half qkv) ----------------
__global__ __launch_bounds__(256)
void rope_kernel(__half* __restrict__ qkv, const int* __restrict__ pos_ids){
    int idx = blockIdx.x*256 + threadIdx.x;
    const int total = NTOK*(NHEAD+NKVH)*64;
    if (idx >= total) return;
    int j    = idx & 63;
    int rest = idx >> 6;
    int head = rest % (NHEAD+NKVH);
    int t    = rest / (NHEAD+NKVH);
    __half* p;
    if (head < NHEAD) p = qkv + (long long)t*QKVN + head*HEADD;
    else              p = qkv + (long long)t*QKVN + NHEAD*HEADD + (head-NHEAD)*HEADD;
    double inv = exp((double)j * -0.21586735246819178); // -ln(1e6)/64
    float th = (float)pos_ids[t] * (float)inv;
    float sn, cs; sincosf(th, &sn, &cs);
    float x0 = __half2float(p[j]), x1 = __half2float(p[j+64]);
    p[j]    = __float2half(x0*cs - x1*sn);
    p[j+64] = __float2half(x1*cs + x0*sn);
}

// ---------------- tensor-core flash attention (tf32 math, half I/O) ----------------
#define FKT 32
#define FL_QS   0
#define FL_KS   (FL_QS + 64*132)
#define FL_VS   (FL_KS + FKT*132)
#define FL_PS   (FL_VS + FKT*136)
#define FL_MROW (FL_PS + 64*36)
#define FL_LROW (FL_MROW + 64)
#define FL_SROW (FL_LROW + 64)
#define FL_MK   (FL_SROW + 64)
#define FL_SMEM_FLOATS (FL_MK + FKT)
#define FL_SMEM_BYTES  (FL_SMEM_FLOATS*4)

__global__ __launch_bounds__(256, 2)
void flash_kernel(const __half* __restrict__ qkv, const int* __restrict__ amask,
                  __half* __restrict__ O)
{
    extern __shared__ float sm[];
    float* Qs = sm + FL_QS;
    float* Ks = sm + FL_KS;
    float* Vs = sm + FL_VS;
    float* Ps = sm + FL_PS;
    float* mrow = sm + FL_MROW;
    float* lrow = sm + FL_LROW;
    float* srow = sm + FL_SROW;
    int*   mk   = (int*)(sm + FL_MK);

    int qt = blockIdx.x;
    int bh = blockIdx.y;
    int b  = bh >> 4, h = bh & 15;
    int kvh = h >> 2;
    int tid = threadIdx.x;
    int lane = tid & 31, wid = tid >> 5;
    int g = lane >> 2, t4 = lane & 3;
    int mS = wid & 3;
    int nH = wid >> 2;

    for (int e2 = tid; e2 < 64*64; e2 += 256){
        int row = e2 >> 6; int d2 = (e2 & 63)*2;
        __half2 v = *(const __half2*)&qkv[(long long)(b*SEQ + qt*64 + row)*QKVN + h*HEADD + d2];
        Qs[row*132 + d2    ] = __half2float(v.x);
        Qs[row*132 + d2 + 1] = __half2float(v.y);
    }
    if (tid < 64){ mrow[tid] = -1e30f; lrow[tid] = 0.f; }

    float oacc[8][4];
    #pragma unroll
    for (int i = 0; i < 8; i++)
        #pragma unroll
        for (int j = 0; j < 4; j++) oacc[i][j] = 0.f;

    const float iscale = 0.08838834764831843f;

    int nkt = 2*qt + 2;
    for (int kt = 0; kt < nkt; ++kt){
        __syncthreads();
        for (int e2 = tid; e2 < FKT*64; e2 += 256){
            int kk = e2 >> 6; int d2 = (e2 & 63)*2;
            long long base = (long long)(b*SEQ + kt*FKT + kk)*QKVN + NHEAD*HEADD + kvh*HEADD;
            __half2 kv2 = *(const __half2*)&qkv[base + d2];
            Ks[kk*132 + d2    ] = __half2float(kv2.x);
            Ks[kk*132 + d2 + 1] = __half2float(kv2.y);
            __half2 vv2 = *(const __half2*)&qkv[base + NKVH*HEADD + d2];
            Vs[kk*136 + d2    ] = __half2float(vv2.x);
            Vs[kk*136 + d2 + 1] = __half2float(vv2.y);
        }
        if (tid < FKT) mk[tid] = amask[b*SEQ + kt*FKT + tid];
        __syncthreads();

        float sacc[2][4];
        #pragma unroll
        for (int i = 0; i < 2; i++)
            #pragma unroll
            for (int j = 0; j < 4; j++) sacc[i][j] = 0.f;
        #pragma unroll
        for (int ks = 0; ks < 16; ++ks){
            int k0 = ks*8;
            uint32_t a[4];
            int r = 16*mS;
            a[0] = __float_as_uint(Qs[(r+g  )*132 + k0+t4  ]);
            a[1] = __float_as_uint(Qs[(r+g+8)*132 + k0+t4  ]);
            a[2] = __float_as_uint(Qs[(r+g  )*132 + k0+t4+4]);
            a[3] = __float_as_uint(Qs[(r+g+8)*132 + k0+t4+4]);
            #pragma unroll
            for (int j = 0; j < 2; j++){
                int c = 16*nH + 8*j + g;
                uint32_t bfr[2];
                bfr[0] = __float_as_uint(Ks[c*132 + k0+t4  ]);
                bfr[1] = __float_as_uint(Ks[c*132 + k0+t4+4]);
                mma_tf32(sacc[j], a, bfr);
            }
        }
        #pragma unroll
        for (int j = 0; j < 2; j++){
            #pragma unroll
            for (int cr = 0; cr < 4; cr++){
                int row = 16*mS + g + ((cr >= 2) ? 8 : 0);
                int col = 16*nH + 8*j + 2*t4 + (cr & 1);
                int sq = qt*64 + row, sk = kt*FKT + col;
                float vv = sacc[j][cr]*iscale;
                if (sk > sq || mk[col] == 0) vv = -1e30f;
                Ps[row*36 + col] = vv;
            }
        }
        __syncthreads();

        if (tid < 64){
            int r = tid;
            float mo = mrow[r], mx = mo;
            #pragma unroll 8
            for (int kk = 0; kk < FKT; kk++) mx = fmaxf(mx, Ps[r*36+kk]);
            float sc = __expf(mo - mx);
            float ssum = 0.f;
            #pragma unroll 8
            for (int kk = 0; kk < FKT; kk++){
                float p = __expf(Ps[r*36+kk] - mx);
                ssum += p;
                Ps[r*36+kk] = tf32f(p);
            }
            lrow[r] = lrow[r]*sc + ssum;
            mrow[r] = mx;
            srow[r] = sc;
        }
        __syncthreads();

        {
            float sc0 = srow[16*mS + g];
            float sc1 = srow[16*mS + g + 8];
            #pragma unroll
            for (int j = 0; j < 8; j++){
                oacc[j][0] *= sc0; oacc[j][1] *= sc0;
                oacc[j][2] *= sc1; oacc[j][3] *= sc1;
            }
        }
        #pragma unroll
        for (int ks = 0; ks < 4; ++ks){
            int k0 = ks*8;
            uint32_t a[4];
            int r = 16*mS;
            a[0] = __float_as_uint(Ps[(r+g  )*36 + k0+t4  ]);
            a[1] = __float_as_uint(Ps[(r+g+8)*36 + k0+t4  ]);
            a[2] = __float_as_uint(Ps[(r+g  )*36 + k0+t4+4]);
            a[3] = __float_as_uint(Ps[(r+g+8)*36 + k0+t4+4]);
            #pragma unroll
            for (int j = 0; j < 8; j++){
                int c = 64*nH + 8*j + g;
                uint32_t bfr[2];
                bfr[0] = __float_as_uint(Vs[(k0+t4  )*136 + c]);
                bfr[1] = __float_as_uint(Vs[(k0+t4+4)*136 + c]);
                mma_tf32(oacc[j], a, bfr);
            }
        }
    }

    #pragma unroll
    for (int j = 0; j < 8; j++){
        #pragma unroll
        for (int half_ = 0; half_ < 2; half_++){
            int row = 16*mS + g + (half_ ? 8 : 0);
            int col = 64*nH + 8*j + 2*t4;
            int sq = qt*64 + row;
            float inv = 1.f / lrow[row];
            __half2 o2 = __floats2half2_rn(oacc[j][half_*2+0]*inv, oacc[j][half_*2+1]*inv);
            *(__half2*)&O[(((long long)(b*SEQ + sq))*NHEAD + h)*HEADD + col] = o2;
        }
    }
}

// ---------------- gate + top2 (raw fp32) ----------------
__global__ __launch_bounds__(256)
void gate_kernel(const float* __restrict__ x2, const float* __restrict__ gw,
                 int* __restrict__ e01, float* __restrict__ w01){
    long long t = blockIdx.x;
    const float* xr = x2 + t*HDIM;
    float part[NEXP];
    #pragma unroll
    for (int e = 0; e < NEXP; e++) part[e] = 0.f;
    for (int hh = threadIdx.x; hh < HDIM; hh += 256){
        float xv = xr[hh];
        const float* gp = gw + (long long)hh*NEXP;
        #pragma unroll
        for (int e = 0; e < NEXP; e++) part[e] += xv*gp[e];
    }
    __shared__ float red[8][NEXP];
    #pragma unroll
    for (int e = 0; e < NEXP; e++){
        float v = part[e];
        #pragma unroll
        for (int o = 16; o; o >>= 1) v += __shfl_xor_sync(0xffffffffu, v, o);
        if ((threadIdx.x & 31) == 0) red[threadIdx.x >> 5][e] = v;
    }
    __syncthreads();
    if (threadIdx.x == 0){
        float lg[NEXP];
        #pragma unroll
        for (int e = 0; e < NEXP; e++){
            float s = 0.f;
            #pragma unroll
            for (int w8 = 0; w8 < 8; w8++) s += red[w8][e];
            lg[e] = s;
        }
        int b0 = 0;
        #pragma unroll
        for (int e = 1; e < NEXP; e++) if (lg[e] > lg[b0]) b0 = e;
        int b1 = -1;
        #pragma unroll
        for (int e = 0; e < NEXP; e++)
            if (e != b0 && (b1 < 0 || lg[e] > lg[b1])) b1 = e;
        float t0 = 1.f / (1.f + expf(lg[b1] - lg[b0]));
        e01[2*t] = b0; e01[2*t+1] = b1;
        w01[2*t] = t0; w01[2*t+1] = 1.f - t0;
    }
}

// ---------------- routing ----------------
__global__ void route_count_kernel(const int* __restrict__ e01,
                                   int* __restrict__ counts, int* __restrict__ pos01){
    int t = blockIdx.x*blockDim.x + threadIdx.x;
    if (t < NTOK){
        pos01[2*t]   = atomicAdd(&counts[e01[2*t]],   1);
        pos01[2*t+1] = atomicAdd(&counts[e01[2*t+1]], 1);
    }
}
__global__ void route_offset_kernel(const int* __restrict__ counts, int* __restrict__ offsets){
    if (threadIdx.x == 0 && blockIdx.x == 0){
        int s = 0;
        for (int e = 0; e < NEXP; e++){ offsets[e] = s; s += counts[e]; }
    }
}
__global__ void route_scatter_kernel(const int* __restrict__ e01, const int* __restrict__ pos01,
                                     const int* __restrict__ offsets,
                                     int* __restrict__ toklist, int* __restrict__ slot01){
    int t = blockIdx.x*blockDim.x + threadIdx.x;
    if (t < NTOK){
        #pragma unroll
        for (int j = 0; j < 2; j++){
            int sl = offsets[e01[2*t+j]] + pos01[2*t+j];
            toklist[sl] = t;
            slot01[2*t+j] = sl;
        }
    }
}

// ---------------- act = silu(h1)*h3 -> half ----------------
__global__ __launch_bounds__(256)
void silu_mul_kernel(const float* __restrict__ h13, __half* __restrict__ act){
    long long n = (long long)NSLOT*FFN;
    for (long long i = blockIdx.x*256LL + threadIdx.x; i < n; i += gridDim.x*256LL){
        long long slot = i >> 12;          // /FFN
        int f = (int)(i & (FFN-1));
        float v  = h13[slot*(2*FFN) + f];
        float v3 = h13[slot*(2*FFN) + FFN + f];
        act[i] = __float2half(v / (1.f + expf(-v)) * v3);
    }
}

// ---------------- final combine ----------------
__global__ __launch_bounds__(256)
void combine_kernel(const float* __restrict__ h, const float* __restrict__ eo,
                    const int* __restrict__ slot01, const float* __restrict__ w01,
                    float* __restrict__ out){
    long long idx = blockIdx.x*256LL + threadIdx.x;
    if (idx >= (long long)NTOK*HDIM) return;
    int t = (int)(idx >> 11);
    int c = (int)(idx & 2047);
    float v = h[idx];
    v += w01[2*t]   * eo[(long long)slot01[2*t]  *HDIM + c];
    v += w01[2*t+1] * eo[(long long)slot01[2*t+1]*HDIM + c];
    out[idx] = v;
}

// ---------------- launch ----------------
extern "C" void kernel_launch(void* const* d_in, const int* in_sizes, int n_in,
                              void* d_out, int out_size){
    const float* hidden = (const float*)d_in[0];
    const int*   amask  = (const int*)  d_in[1];
    const int*   posids = (const int*)  d_in[2];
    const float* ln1w = (const float*)d_in[3];
    const float* ln1b = (const float*)d_in[4];
    const float* ln2w = (const float*)d_in[5];
    const float* ln2b = (const float*)d_in[6];
    const float* wq = (const float*)d_in[7];
    const float* bq = (const float*)d_in[8];
    const float* wk = (const float*)d_in[9];
    const float* bk = (const float*)d_in[10];
    const float* wv = (const float*)d_in[11];
    const float* bv = (const float*)d_in[12];
    const float* wo = (const float*)d_in[13];
    const float* bo = (const float*)d_in[14];
    const float* gatew = (const float*)d_in[15];
    const float* w1 = (const float*)d_in[16];
    const float* w2 = (const float*)d_in[17];
    const float* w3 = (const float*)d_in[18];
    float* out = (float*)d_out;

    __half *xln1h, *qkvh, *attnh, *xln2h, *acth, *wqkvT, *woT, *w13T, *w2T;
    float *hbuf, *xln2, *h13, *eo, *w01, *bqkv;
    int *e01, *pos01, *counts, *offsets, *toklist, *slot01;
    cudaGetSymbolAddress((void**)&xln1h, g_xln1h);
    cudaGetSymbolAddress((void**)&qkvh, g_qkvh);
    cudaGetSymbolAddress((void**)&attnh, g_attnh);
    cudaGetSymbolAddress((void**)&hbuf, g_h);
    cudaGetSymbolAddress((void**)&xln2, g_xln2);
    cudaGetSymbolAddress((void**)&xln2h, g_xln2h);
    cudaGetSymbolAddress((void**)&h13, g_h13);
    cudaGetSymbolAddress((void**)&acth, g_acth);
    cudaGetSymbolAddress((void**)&eo, g_eo);
    cudaGetSymbolAddress((void**)&wqkvT, g_wqkvT);
    cudaGetSymbolAddress((void**)&woT, g_woT);
    cudaGetSymbolAddress((void**)&w13T, g_w13T);
    cudaGetSymbolAddress((void**)&w2T, g_w2T);
    cudaGetSymbolAddress((void**)&bqkv, g_bqkv);
    cudaGetSymbolAddress((void**)&e01, g_e01);
    cudaGetSymbolAddress((void**)&w01, g_w01);
    cudaGetSymbolAddress((void**)&pos01, g_pos01);
    cudaGetSymbolAddress((void**)&counts, g_counts);
    cudaGetSymbolAddress((void**)&offsets, g_offsets);
    cudaGetSymbolAddress((void**)&toklist, g_toklist);
    cudaGetSymbolAddress((void**)&slot01, g_slot01);

    cudaFuncSetAttribute(flash_kernel, cudaFuncAttributeMaxDynamicSharedMemorySize, FL_SMEM_BYTES);
    cudaFuncSetAttribute(gemm_f16,    cudaFuncAttributeMaxDynamicSharedMemorySize, GEMM_SMEM_BYTES);

    // 0) weight prep: transpose + fp16 convert (per call; deterministic)
    transcvt<<<dim3(64, 64, 1), 256>>>(wq, wqkvT, HDIM, NHEAD*HEADD, 0, 0);
    transcvt<<<dim3(64, 16, 1), 256>>>(wk, wqkvT + (long long)NHEAD*HEADD*HDIM, HDIM, NKVH*HEADD, 0, 0);
    transcvt<<<dim3(64, 16, 1), 256>>>(wv, wqkvT + (long long)(NHEAD+NKVH)*HEADD*HDIM, HDIM, NKVH*HEADD, 0, 0);
    transcvt<<<dim3(64, 64, 1), 256>>>(wo, woT, HDIM, HDIM, 0, 0);
    transcvt<<<dim3(64, 128, NEXP), 256>>>(w1, w13T, HDIM, FFN,
                                           (long long)HDIM*FFN, (long long)2*FFN*HDIM);
    transcvt<<<dim3(64, 128, NEXP), 256>>>(w3, w13T + (long long)FFN*HDIM, HDIM, FFN,
                                           (long long)HDIM*FFN, (long long)2*FFN*HDIM);
    transcvt<<<dim3(128, 64, NEXP), 256>>>(w2, w2T, FFN, HDIM,
                                           (long long)FFN*HDIM, (long long)HDIM*FFN);
    concat_bias<<<(QKVN+255)/256, 256>>>(bq, bk, bv, bqkv);

    // 1) LN1 (half only)
    ln_kernel<<<NTOK, 256>>>(hidden, ln1w, ln1b, nullptr, xln1h);

    // 2) fused QKV projection -> half qkv
    gemm_f16<<<dim3(QKVN/256, NTOK/128, 1), 256, GEMM_SMEM_BYTES>>>(
        xln1h, HDIM, wqkvT, 0, nullptr, qkvh, QKVN, bqkv, nullptr,
        NTOK, QKVN, HDIM, nullptr, nullptr, nullptr);

    // 3) RoPE
    {
        int total = NTOK*(NHEAD+NKVH)*64;
        rope_kernel<<<(total+255)/256, 256>>>(qkvh, posids);
    }

    // 4) flash attention -> half attn
    flash_kernel<<<dim3(SEQ/64, BATCH*NHEAD), 256, FL_SMEM_BYTES>>>(qkvh, amask, attnh);

    // 5) O projection + residual -> float h
    gemm_f16<<<dim3(HDIM/256, NTOK/128, 1), 256, GEMM_SMEM_BYTES>>>(
        attnh, NHEAD*HEADD, woT, 0, hbuf, nullptr, HDIM, bo, hidden,
        NTOK, HDIM, NHEAD*HEADD, nullptr, nullptr, nullptr);

    // 6) LN2: raw float (gate) + half (GEMM A)
    ln_kernel<<<NTOK, 256>>>(hbuf, ln2w, ln2b, xln2, xln2h);
    // 7) gate + top2 from raw xln2
    gate_kernel<<<NTOK, 256>>>(xln2, gatew, e01, w01);
    // 8) routing
    cudaMemsetAsync(counts, 0, NEXP*sizeof(int));
    route_count_kernel<<<(NTOK+255)/256, 256>>>(e01, counts, pos01);
    route_offset_kernel<<<1, 32>>>(counts, offsets);
    route_scatter_kernel<<<(NTOK+255)/256, 256>>>(e01, pos01, offsets, toklist, slot01);

    // 9) expert up-projections: h13[slot] = x[tok] @ [w1|w3]^T(e)
    gemm_f16<<<dim3(2*FFN/256, NTOK/128, NEXP), 256, GEMM_SMEM_BYTES>>>(
        xln2h, HDIM, w13T, (long long)2*FFN*HDIM, h13, nullptr, 2*FFN, nullptr, nullptr,
        NTOK, 2*FFN, HDIM, toklist, counts, offsets);

    // 10) act = silu(h1)*h3 -> half
    silu_mul_kernel<<<16384, 256>>>(h13, acth);

    // 11) eo = act @ w2(e)
    gemm_f16<<<dim3(HDIM/256, NTOK/128, NEXP), 256, GEMM_SMEM_BYTES>>>(
        acth, FFN, w2T, (long long)HDIM*FFN, eo, nullptr, HDIM, nullptr, nullptr,
        NTOK, HDIM, FFN, nullptr, counts, offsets);

    // 12) out = h + top2-weighted expert outputs
    combine_kernel<<<(int)(((long long)NTOK*HDIM + 255)/256), 256>>>(hbuf, eo, slot01, w01, out);
}

// round 7
// speedup vs baseline: 1.5956x; 1.0484x over previous
#include <cuda_runtime.h>
#include <cuda_fp16.h>
#include <math.h>
#include <stdint.h>

// ---------------- problem constants ----------------
#define BATCH 2
#define SEQ   1024
#define HDIM  2048
#define NHEAD 16
#define NKVH  4
#define HEADD 128
#define FFN   4096
#define NEXP  8
#define NTOK  (BATCH*SEQ)          // 2048
#define QKVN  (NHEAD*HEADD + 2*NKVH*HEADD)   // 3072
#define NSLOT (2*NTOK)             // 4096
#define LNEPS 1e-5f

// ---------------- device scratch ----------------
__device__ __half g_xln1h[NTOK*HDIM];
__device__ __half g_qkvh [NTOK*QKVN];
__device__ __half g_attnh[NTOK*NHEAD*HEADD];
__device__ float  g_h    [NTOK*HDIM];
__device__ float  g_xln2 [NTOK*HDIM];     // raw fp32 (gate)
__device__ __half g_xln2h[NTOK*HDIM];
__device__ __half g_h13h [NSLOT*2*FFN];   // 67 MB (h1|h3 per slot, fp16)
__device__ __half g_acth [NSLOT*FFN];     // 33 MB
__device__ float  g_eo   [NSLOT*HDIM];    // 33 MB
// transposed fp16 weights [N][K]
__device__ __half g_wqkvT[QKVN*HDIM];
__device__ __half g_woT  [HDIM*HDIM];
__device__ __half g_w13T [NEXP*2*FFN*HDIM];  // 268 MB
__device__ __half g_w2T  [NEXP*HDIM*FFN];    // 134 MB
__device__ float  g_bqkv [QKVN];
// routing
__device__ int   g_e01 [NTOK*2];
__device__ float g_w01 [NTOK*2];
__device__ int   g_pos01[NTOK*2];
__device__ int   g_counts[NEXP];
__device__ int   g_offsets[NEXP];
__device__ int   g_toklist[NSLOT];
__device__ int   g_slot01[NTOK*2];

// ---------------- helpers ----------------
__device__ __forceinline__ uint32_t tf32u(float x){
    uint32_t u; asm("cvt.rna.tf32.f32 %0, %1;" : "=r"(u) : "f"(x));
    return u;
}
__device__ __forceinline__ float tf32f(float x){ return __uint_as_float(tf32u(x)); }

__device__ __forceinline__ void mma_tf32(float* c, const uint32_t* a, const uint32_t* b){
    asm volatile(
      "mma.sync.aligned.m16n8k8.row.col.f32.tf32.tf32.f32 "
      "{%0,%1,%2,%3}, {%4,%5,%6,%7}, {%8,%9}, {%0,%1,%2,%3};\n"
      : "+f"(c[0]), "+f"(c[1]), "+f"(c[2]), "+f"(c[3])
      : "r"(a[0]), "r"(a[1]), "r"(a[2]), "r"(a[3]), "r"(b[0]), "r"(b[1]));
}
__device__ __forceinline__ void mma_f16(float* c, const uint32_t* a, const uint32_t* b){
    asm volatile(
      "mma.sync.aligned.m16n8k16.row.col.f32.f16.f16.f32 "
      "{%0,%1,%2,%3}, {%4,%5,%6,%7}, {%8,%9}, {%0,%1,%2,%3};\n"
      : "+f"(c[0]), "+f"(c[1]), "+f"(c[2]), "+f"(c[3])
      : "r"(a[0]), "r"(a[1]), "r"(a[2]), "r"(a[3]), "r"(b[0]), "r"(b[1]));
}

__device__ __forceinline__ void cpa16h(__half* smem, const __half* gmem, bool pred){
    uint32_t s = (uint32_t)__cvta_generic_to_shared(smem);
    int sz = pred ? 16 : 0;
    asm volatile("cp.async.cg.shared.global [%0], [%1], 16, %2;\n"
                 :: "r"(s), "l"(gmem), "r"(sz));
}
#define CP_COMMIT() asm volatile("cp.async.commit_group;\n")
template<int N> __device__ __forceinline__ void cp_wait(){
    asm volatile("cp.async.wait_group %0;\n" :: "n"(N));
}

__device__ __forceinline__ float block_sum_256(float v){
    __shared__ float red[8];
    __shared__ float total;
    #pragma unroll
    for (int o = 16; o; o >>= 1) v += __shfl_xor_sync(0xffffffffu, v, o);
    if ((threadIdx.x & 31) == 0) red[threadIdx.x >> 5] = v;
    __syncthreads();
    if (threadIdx.x == 0){
        float s = 0.f;
        #pragma unroll
        for (int i = 0; i < 8; i++) s += red[i];
        total = s;
    }
    __syncthreads();
    float r = total;
    __syncthreads();
    return r;
}

// ---------------- bandwidth-optimized transpose+convert ----------------
// dst[n][k] = (half)src[k][n], 64x64 tiles, float4 loads, half2 stores.
__global__ __launch_bounds__(256)
void transcvt(const float* __restrict__ src, __half* __restrict__ dst,
              int K, int N, long long srcE, long long dstE){
    src += (long long)blockIdx.z * srcE;
    dst += (long long)blockIdx.z * dstE;
    __shared__ float t[64][67];            // stride 67 (odd): <=2-way conflicts both phases
    int k0 = blockIdx.x*64, n0 = blockIdx.y*64;
    int tid = threadIdx.x;
    {   // load: 64 rows x 16 float4 ; thread (ty row, tx float4-col)
        int tx = tid & 15, ty = tid >> 4;  // 16 x 16
        #pragma unroll
        for (int i = 0; i < 4; i++){
            float4 v = *(const float4*)&src[(long long)(k0 + ty + 16*i)*N + n0 + tx*4];
            float* tr = &t[ty + 16*i][tx*4];
            tr[0] = v.x; tr[1] = v.y; tr[2] = v.z; tr[3] = v.w;
        }
    }
    __syncthreads();
    {   // store: dst rows n, half2 along k ; thread (kk k-pair, ny n-row)
        int kk = tid & 31, ny = tid >> 5;  // 32 k-pairs x 8 n-rows
        #pragma unroll
        for (int i = 0; i < 8; i++){
            int n = ny + 8*i;
            __half2 h2 = __floats2half2_rn(t[2*kk][n], t[2*kk+1][n]);
            *(__half2*)&dst[(long long)(n0 + n)*K + k0 + 2*kk] = h2;
        }
    }
}

__global__ void concat_bias(const float* bq, const float* bk, const float* bv, float* dst){
    int i = blockIdx.x*256 + threadIdx.x;
    if (i < NHEAD*HEADD) dst[i] = bq[i];
    else if (i < NHEAD*HEADD + NKVH*HEADD) dst[i] = bk[i - NHEAD*HEADD];
    else if (i < QKVN) dst[i] = bv[i - NHEAD*HEADD - NKVH*HEADD];
}

// ---------------- LayerNorm: optional raw float + fp16 outputs ----------------
__global__ __launch_bounds__(256)
void ln_kernel(const float* __restrict__ x, const float* __restrict__ w,
               const float* __restrict__ b,
               float* __restrict__ yraw, __half* __restrict__ yh){
    long long row = blockIdx.x;
    const float* xr = x + row * HDIM;
    float v[8]; float s = 0.f;
    #pragma unroll
    for (int i = 0; i < 8; i++){ v[i] = xr[threadIdx.x + 256*i]; s += v[i]; }
    float mean = block_sum_256(s) * (1.f/HDIM);
    float ss = 0.f;
    #pragma unroll
    for (int i = 0; i < 8; i++){ float d = v[i]-mean; ss += d*d; }
    float var = block_sum_256(ss) * (1.f/HDIM);
    float rstd = rsqrtf(var + LNEPS);
    #pragma unroll
    for (int i = 0; i < 8; i++){
        int c = threadIdx.x + 256*i;
        float o = (v[i]-mean)*rstd*w[c] + b[c];
        if (yraw) yraw[row*HDIM + c] = o;
        yh[row*HDIM + c] = __float2half(o);
    }
}

// ---------------- fp16 tensor-core GEMM, 3-stage cp.async ----------------
// C[M,N] = A[M,K](half) @ B[K,N] with B given TRANSPOSED as BT[N][K] (half).
// Block 128x256, BK=32, 8 warps (2x4), warp tile 64x64.
#define GA_STG (128*40)           // halves per A stage (row stride 40)
#define GB_STG (256*40)           // halves per B stage
#define GB_BASE (3*GA_STG)
#define GEMM_SMEM_BYTES ((GB_BASE + 3*GB_STG)*2)

__global__ __launch_bounds__(256)
void gemm_f16(const __half* __restrict__ A, int lda,
              const __half* __restrict__ BT, long long bStride,
              float* __restrict__ Cf, __half* __restrict__ Ch, int ldc,
              const float* __restrict__ bias, const float* __restrict__ resid,
              int M, int N, int K,
              const int* __restrict__ rowidx,
              const int* __restrict__ counts,
              const int* __restrict__ offsets)
{
    extern __shared__ __half hsm[];
#define ASH(st, r, c) hsm[(st)*GA_STG + (r)*40 + (c)]
#define BSH(st, n, c) hsm[GB_BASE + (st)*GB_STG + (n)*40 + (c)]

    int e = blockIdx.z;
    int rowStart = 0, Mm = M;
    if (counts){ Mm = counts[e]; rowStart = offsets[e]; }
    int mbase = blockIdx.y * 128;
    if (mbase >= Mm) return;
    int nbase = blockIdx.x * 256;
    const __half* Bp = BT + (long long)e * bStride;

    int tid  = threadIdx.x;
    int lane = tid & 31, wid = tid >> 5;
    int warpM = wid >> 2, warpN = wid & 3;
    int g = lane >> 2, t4 = lane & 3;

    int ar = tid >> 1, hsel = tid & 1;
    bool aval = (mbase + ar < Mm);
    int arow = 0;
    if (aval) arow = rowidx ? rowidx[rowStart + mbase + ar] : (rowStart + mbase + ar);
    const __half* aptr = A + (long long)arow * lda + hsel*16;
    int bn0 = tid >> 2, bch = tid & 3;

    float acc[32][4];
    #pragma unroll
    for (int i = 0; i < 32; i++)
        #pragma unroll
        for (int j = 0; j < 4; j++) acc[i][j] = 0.f;

    int nk = K >> 5;

#define GEMM_ISSUE(KT, ST) do {                                             \
        cpa16h(&ASH(ST, ar, hsel*16),     aptr + (KT)*32,       aval);      \
        cpa16h(&ASH(ST, ar, hsel*16 + 8), aptr + (KT)*32 + 8,   aval);      \
        _Pragma("unroll")                                                   \
        for (int i = 0; i < 4; i++){                                        \
            int n = bn0 + 64*i;                                             \
            cpa16h(&BSH(ST, n, bch*8),                                      \
                   Bp + (long long)(nbase + n)*K + (KT)*32 + bch*8, true);  \
        }                                                                   \
    } while(0)

    GEMM_ISSUE(0, 0); CP_COMMIT();
    GEMM_ISSUE(1, 1); CP_COMMIT();

    int cur = 0;
    for (int kt = 0; kt < nk; ++kt){
        if (kt + 1 < nk) cp_wait<1>(); else cp_wait<0>();
        __syncthreads();
        if (kt + 2 < nk){
            int nxt = cur + 2; if (nxt >= 3) nxt -= 3;
            GEMM_ISSUE(kt+2, nxt); CP_COMMIT();
        }

        #pragma unroll
        for (int ks = 0; ks < 2; ++ks){
            int k0 = ks*16 + 2*t4;
            uint32_t af[4][4], bf[8][2];
            #pragma unroll
            for (int ma = 0; ma < 4; ma++){
                int r = warpM*64 + ma*16;
                af[ma][0] = *(const uint32_t*)&ASH(cur, r+g  , k0    );
                af[ma][1] = *(const uint32_t*)&ASH(cur, r+g+8, k0    );
                af[ma][2] = *(const uint32_t*)&ASH(cur, r+g  , k0 + 8);
                af[ma][3] = *(const uint32_t*)&ASH(cur, r+g+8, k0 + 8);
            }
            #pragma unroll
            for (int na = 0; na < 8; na++){
                int c = warpN*64 + na*8 + g;
                bf[na][0] = *(const uint32_t*)&BSH(cur, c, k0    );
                bf[na][1] = *(const uint32_t*)&BSH(cur, c, k0 + 8);
            }
            #pragma unroll
            for (int ma = 0; ma < 4; ma++)
                #pragma unroll
                for (int na = 0; na < 8; na++)
                    mma_f16(acc[ma*8+na], af[ma], bf[na]);
        }
        cur = cur + 1; if (cur >= 3) cur -= 3;
    }

    #pragma unroll
    for (int ma = 0; ma < 4; ma++){
        #pragma unroll
        for (int na = 0; na < 8; na++){
            float* a4 = acc[ma*8+na];
            #pragma unroll
            for (int half_ = 0; half_ < 2; half_++){
                int lrow = warpM*64 + ma*16 + g + (half_ ? 8 : 0);
                int gcol = nbase + warpN*64 + na*8 + 2*t4;
                int gr = mbase + lrow;
                if (gr < Mm){
                    long long orow = rowStart + gr;
                    float v0 = a4[half_*2+0];
                    float v1 = a4[half_*2+1];
                    if (bias){ v0 += bias[gcol]; v1 += bias[gcol+1]; }
                    if (resid){
                        const float* rp = &resid[orow*(long long)ldc + gcol];
                        v0 += rp[0]; v1 += rp[1];
                    }
                    if (Cf){
                        *(float2*)&Cf[orow*(long long)ldc + gcol] = make_float2(v0, v1);
                    } else {
                        *(__half2*)&Ch[orow*(long long)ldc + gcol] = __floats2half2_rn(v0, v1);
                    }
                }
            }
        }
    }
#undef ASH
#undef BSH
#undef GEMM_ISSUE
}

// ---------------- RoPE (in place on packed half qkv) ----------------
__global__ __launch_bounds__(256)
void rope_kernel(__half* __restrict__ qkv, const int* __restrict__ pos_ids){
    int idx = blockIdx.x*256 + threadIdx.x;
    const int total = NTOK*(NHEAD+NKVH)*64;
    if (idx >= total) return;
    int j    = idx & 63;
    int rest = idx >> 6;
    int head = rest % (NHEAD+NKVH);
    int t    = rest / (NHEAD+NKVH);
    __half* p;
    if (head < NHEAD) p = qkv + (long long)t*QKVN + head*HEADD;
    else              p = qkv + (long long)t*QKVN + NHEAD*HEADD + (head-NHEAD)*HEADD;
    double inv = exp((double)j * -0.21586735246819178); // -ln(1e6)/64
    float th = (float)pos_ids[t] * (float)inv;
    float sn, cs; sincosf(th, &sn, &cs);
    float x0 = __half2float(p[j]), x1 = __half2float(p[j+64]);
    p[j]    = __float2half(x0*cs - x1*sn);
    p[j+64] = __float2half(x1*cs + x0*sn);
}

// ---------------- tensor-core flash attention (tf32 math, half I/O) ----------------
#define FKT 32
#define FL_QS   0
#define FL_KS   (FL_QS + 64*132)
#define FL_VS   (FL_KS + FKT*132)
#define FL_PS   (FL_VS + FKT*136)
#define FL_MROW (FL_PS + 64*36)
#define FL_LROW (FL_MROW + 64)
#define FL_SROW (FL_LROW + 64)
#define FL_MK   (FL_SROW + 64)
#define FL_SMEM_FLOATS (FL_MK + FKT)
#define FL_SMEM_BYTES  (FL_SMEM_FLOATS*4)

__global__ __launch_bounds__(256, 2)
void flash_kernel(const __half* __restrict__ qkv, const int* __restrict__ amask,
                  __half* __restrict__ O)
{
    extern __shared__ float sm[];
    float* Qs = sm + FL_QS;
    float* Ks = sm + FL_KS;
    float* Vs = sm + FL_VS;
    float* Ps = sm + FL_PS;
    float* mrow = sm + FL_MROW;
    float* lrow = sm + FL_LROW;
    float* srow = sm + FL_SROW;
    int*   mk   = (int*)(sm + FL_MK);

    int qt = blockIdx.x;
    int bh = blockIdx.y;
    int b  = bh >> 4, h = bh & 15;
    int kvh = h >> 2;
    int tid = threadIdx.x;
    int lane = tid & 31, wid = tid >> 5;
    int g = lane >> 2, t4 = lane & 3;
    int mS = wid & 3;
    int nH = wid >> 2;

    for (int e2 = tid; e2 < 64*64; e2 += 256){
        int row = e2 >> 6; int d2 = (e2 & 63)*2;
        __half2 v = *(const __half2*)&qkv[(long long)(b*SEQ + qt*64 + row)*QKVN + h*HEADD + d2];
        Qs[row*132 + d2    ] = __half2float(v.x);
        Qs[row*132 + d2 + 1] = __half2float(v.y);
    }
    if (tid < 64){ mrow[tid] = -1e30f; lrow[tid] = 0.f; }

    float oacc[8][4];
    #pragma unroll
    for (int i = 0; i < 8; i++)
        #pragma unroll
        for (int j = 0; j < 4; j++) oacc[i][j] = 0.f;

    const float iscale = 0.08838834764831843f;

    int nkt = 2*qt + 2;
    for (int kt = 0; kt < nkt; ++kt){
        __syncthreads();
        for (int e2 = tid; e2 < FKT*64; e2 += 256){
            int kk = e2 >> 6; int d2 = (e2 & 63)*2;
            long long base = (long long)(b*SEQ + kt*FKT + kk)*QKVN + NHEAD*HEADD + kvh*HEADD;
            __half2 kv2 = *(const __half2*)&qkv[base + d2];
            Ks[kk*132 + d2    ] = __half2float(kv2.x);
            Ks[kk*132 + d2 + 1] = __half2float(kv2.y);
            __half2 vv2 = *(const __half2*)&qkv[base + NKVH*HEADD + d2];
            Vs[kk*136 + d2    ] = __half2float(vv2.x);
            Vs[kk*136 + d2 + 1] = __half2float(vv2.y);
        }
        if (tid < FKT) mk[tid] = amask[b*SEQ + kt*FKT + tid];
        __syncthreads();

        float sacc[2][4];
        #pragma unroll
        for (int i = 0; i < 2; i++)
            #pragma unroll
            for (int j = 0; j < 4; j++) sacc[i][j] = 0.f;
        #pragma unroll
        for (int ks = 0; ks < 16; ++ks){
            int k0 = ks*8;
            uint32_t a[4];
            int r = 16*mS;
            a[0] = __float_as_uint(Qs[(r+g  )*132 + k0+t4  ]);
            a[1] = __float_as_uint(Qs[(r+g+8)*132 + k0+t4  ]);
            a[2] = __float_as_uint(Qs[(r+g  )*132 + k0+t4+4]);
            a[3] = __float_as_uint(Qs[(r+g+8)*132 + k0+t4+4]);
            #pragma unroll
            for (int j = 0; j < 2; j++){
                int c = 16*nH + 8*j + g;
                uint32_t bfr[2];
                bfr[0] = __float_as_uint(Ks[c*132 + k0+t4  ]);
                bfr[1] = __float_as_uint(Ks[c*132 + k0+t4+4]);
                mma_tf32(sacc[j], a, bfr);
            }
        }
        #pragma unroll
        for (int j = 0; j < 2; j++){
            #pragma unroll
            for (int cr = 0; cr < 4; cr++){
                int row = 16*mS + g + ((cr >= 2) ? 8 : 0);
                int col = 16*nH + 8*j + 2*t4 + (cr & 1);
                int sq = qt*64 + row, sk = kt*FKT + col;
                float vv = sacc[j][cr]*iscale;
                if (sk > sq || mk[col] == 0) vv = -1e30f;
                Ps[row*36 + col] = vv;
            }
        }
        __syncthreads();

        if (tid < 64){
            int r = tid;
            float mo = mrow[r], mx = mo;
            #pragma unroll 8
            for (int kk = 0; kk < FKT; kk++) mx = fmaxf(mx, Ps[r*36+kk]);
            float sc = __expf(mo - mx);
            float ssum = 0.f;
            #pragma unroll 8
            for (int kk = 0; kk < FKT; kk++){
                float p = __expf(Ps[r*36+kk] - mx);
                ssum += p;
                Ps[r*36+kk] = tf32f(p);
            }
            lrow[r] = lrow[r]*sc + ssum;
            mrow[r] = mx;
            srow[r] = sc;
        }
        __syncthreads();

        {
            float sc0 = srow[16*mS + g];
            float sc1 = srow[16*mS + g + 8];
            #pragma unroll
            for (int j = 0; j < 8; j++){
                oacc[j][0] *= sc0; oacc[j][1] *= sc0;
                oacc[j][2] *= sc1; oacc[j][3] *= sc1;
            }
        }
        #pragma unroll
        for (int ks = 0; ks < 4; ++ks){
            int k0 = ks*8;
            uint32_t a[4];
            int r = 16*mS;
            a[0] = __float_as_uint(Ps[(r+g  )*36 + k0+t4  ]);
            a[1] = __float_as_uint(Ps[(r+g+8)*36 + k0+t4  ]);
            a[2] = __float_as_uint(Ps[(r+g  )*36 + k0+t4+4]);
            a[3] = __float_as_uint(Ps[(r+g+8)*36 + k0+t4+4]);
            #pragma unroll
            for (int j = 0; j < 8; j++){
                int c = 64*nH + 8*j + g;
                uint32_t bfr[2];
                bfr[0] = __float_as_uint(Vs[(k0+t4  )*136 + c]);
                bfr[1] = __float_as_uint(Vs[(k0+t4+4)*136 + c]);
                mma_tf32(oacc[j], a, bfr);
            }
        }
    }

    #pragma unroll
    for (int j = 0; j < 8; j++){
        #pragma unroll
        for (int half_ = 0; half_ < 2; half_++){
            int row = 16*mS + g + (half_ ? 8 : 0);
            int col = 64*nH + 8*j + 2*t4;
            int sq = qt*64 + row;
            float inv = 1.f / lrow[row];
            __half2 o2 = __floats2half2_rn(oacc[j][half_*2+0]*inv, oacc[j][half_*2+1]*inv);
            *(__half2*)&O[(((long long)(b*SEQ + sq))*NHEAD + h)*HEADD + col] = o2;
        }
    }
}

// ---------------- gate + top2 (raw fp32) ----------------
__global__ __launch_bounds__(256)
void gate_kernel(const float* __restrict__ x2, const float* __restrict__ gw,
                 int* __restrict__ e01, float* __restrict__ w01){
    long long t = blockIdx.x;
    const float* xr = x2 + t*HDIM;
    float part[NEXP];
    #pragma unroll
    for (int e = 0; e < NEXP; e++) part[e] = 0.f;
    for (int hh = threadIdx.x; hh < HDIM; hh += 256){
        float xv = xr[hh];
        const float* gp = gw + (long long)hh*NEXP;
        #pragma unroll
        for (int e = 0; e < NEXP; e++) part[e] += xv*gp[e];
    }
    __shared__ float red[8][NEXP];
    #pragma unroll
    for (int e = 0; e < NEXP; e++){
        float v = part[e];
        #pragma unroll
        for (int o = 16; o; o >>= 1) v += __shfl_xor_sync(0xffffffffu, v, o);
        if ((threadIdx.x & 31) == 0) red[threadIdx.x >> 5][e] = v;
    }
    __syncthreads();
    if (threadIdx.x == 0){
        float lg[NEXP];
        #pragma unroll
        for (int e = 0; e < NEXP; e++){
            float s = 0.f;
            #pragma unroll
            for (int w8 = 0; w8 < 8; w8++) s += red[w8][e];
            lg[e] = s;
        }
        int b0 = 0;
        #pragma unroll
        for (int e = 1; e < NEXP; e++) if (lg[e] > lg[b0]) b0 = e;
        int b1 = -1;
        #pragma unroll
        for (int e = 0; e < NEXP; e++)
            if (e != b0 && (b1 < 0 || lg[e] > lg[b1])) b1 = e;
        float t0 = 1.f / (1.f + expf(lg[b1] - lg[b0]));
        e01[2*t] = b0; e01[2*t+1] = b1;
        w01[2*t] = t0; w01[2*t+1] = 1.f - t0;
    }
}

// ---------------- routing ----------------
__global__ void route_count_kernel(const int* __restrict__ e01,
                                   int* __restrict__ counts, int* __restrict__ pos01){
    int t = blockIdx.x*blockDim.x + threadIdx.x;
    if (t < NTOK){
        pos01[2*t]   = atomicAdd(&counts[e01[2*t]],   1);
        pos01[2*t+1] = atomicAdd(&counts[e01[2*t+1]], 1);
    }
}
__global__ void route_offset_kernel(const int* __restrict__ counts, int* __restrict__ offsets){
    if (threadIdx.x == 0 && blockIdx.x == 0){
        int s = 0;
        for (int e = 0; e < NEXP; e++){ offsets[e] = s; s += counts[e]; }
    }
}
__global__ void route_scatter_kernel(const int* __restrict__ e01, const int* __restrict__ pos01,
                                     const int* __restrict__ offsets,
                                     int* __restrict__ toklist, int* __restrict__ slot01){
    int t = blockIdx.x*blockDim.x + threadIdx.x;
    if (t < NTOK){
        #pragma unroll
        for (int j = 0; j < 2; j++){
            int sl = offsets[e01[2*t+j]] + pos01[2*t+j];
            toklist[sl] = t;
            slot01[2*t+j] = sl;
        }
    }
}

// ---------------- act = silu(h1)*h3 (half2 vectorized) ----------------
__global__ __launch_bounds__(256)
void silu_mul_kernel(const __half* __restrict__ h13, __half* __restrict__ act){
    long long n2 = (long long)NSLOT*FFN/2;
    for (long long i = blockIdx.x*256LL + threadIdx.x; i < n2; i += gridDim.x*256LL){
        long long slot = i >> 11;          // /(FFN/2)
        int f2 = (int)(i & (FFN/2 - 1));
        __half2 a = *(const __half2*)&h13[slot*(2*FFN) + f2*2];
        __half2 c = *(const __half2*)&h13[slot*(2*FFN) + FFN + f2*2];
        float v0 = __half2float(a.x), v1 = __half2float(a.y);
        float u0 = __half2float(c.x), u1 = __half2float(c.y);
        float r0 = v0 / (1.f + expf(-v0)) * u0;
        float r1 = v1 / (1.f + expf(-v1)) * u1;
        *(__half2*)&act[i*2] = __floats2half2_rn(r0, r1);
    }
}

// ---------------- final combine ----------------
__global__ __launch_bounds__(256)
void combine_kernel(const float* __restrict__ h, const float* __restrict__ eo,
                    const int* __restrict__ slot01, const float* __restrict__ w01,
                    float* __restrict__ out){
    long long idx = blockIdx.x*256LL + threadIdx.x;
    if (idx >= (long long)NTOK*HDIM) return;
    int t = (int)(idx >> 11);
    int c = (int)(idx & 2047);
    float v = h[idx];
    v += w01[2*t]   * eo[(long long)slot01[2*t]  *HDIM + c];
    v += w01[2*t+1] * eo[(long long)slot01[2*t+1]*HDIM + c];
    out[idx] = v;
}

// ---------------- launch ----------------
extern "C" void kernel_launch(void* const* d_in, const int* in_sizes, int n_in,
                              void* d_out, int out_size){
    const float* hidden = (const float*)d_in[0];
    const int*   amask  = (const int*)  d_in[1];
    const int*   posids = (const int*)  d_in[2];
    const float* ln1w = (const float*)d_in[3];
    const float* ln1b = (const float*)d_in[4];
    const float* ln2w = (const float*)d_in[5];
    const float* ln2b = (const float*)d_in[6];
    const float* wq = (const float*)d_in[7];
    const float* bq = (const float*)d_in[8];
    const float* wk = (const float*)d_in[9];
    const float* bk = (const float*)d_in[10];
    const float* wv = (const float*)d_in[11];
    const float* bv = (const float*)d_in[12];
    const float* wo = (const float*)d_in[13];
    const float* bo = (const float*)d_in[14];
    const float* gatew = (const float*)d_in[15];
    const float* w1 = (const float*)d_in[16];
    const float* w2 = (const float*)d_in[17];
    const float* w3 = (const float*)d_in[18];
    float* out = (float*)d_out;

    __half *xln1h, *qkvh, *attnh, *xln2h, *h13h, *acth, *wqkvT, *woT, *w13T, *w2T;
    float *hbuf, *xln2, *eo, *w01, *bqkv;
    int *e01, *pos01, *counts, *offsets, *toklist, *slot01;
    cudaGetSymbolAddress((void**)&xln1h, g_xln1h);
    cudaGetSymbolAddress((void**)&qkvh, g_qkvh);
    cudaGetSymbolAddress((void**)&attnh, g_attnh);
    cudaGetSymbolAddress((void**)&hbuf, g_h);
    cudaGetSymbolAddress((void**)&xln2, g_xln2);
    cudaGetSymbolAddress((void**)&xln2h, g_xln2h);
    cudaGetSymbolAddress((void**)&h13h, g_h13h);
    cudaGetSymbolAddress((void**)&acth, g_acth);
    cudaGetSymbolAddress((void**)&eo, g_eo);
    cudaGetSymbolAddress((void**)&wqkvT, g_wqkvT);
    cudaGetSymbolAddress((void**)&woT, g_woT);
    cudaGetSymbolAddress((void**)&w13T, g_w13T);
    cudaGetSymbolAddress((void**)&w2T, g_w2T);
    cudaGetSymbolAddress((void**)&bqkv, g_bqkv);
    cudaGetSymbolAddress((void**)&e01, g_e01);
    cudaGetSymbolAddress((void**)&w01, g_w01);
    cudaGetSymbolAddress((void**)&pos01, g_pos01);
    cudaGetSymbolAddress((void**)&counts, g_counts);
    cudaGetSymbolAddress((void**)&offsets, g_offsets);
    cudaGetSymbolAddress((void**)&toklist, g_toklist);
    cudaGetSymbolAddress((void**)&slot01, g_slot01);

    cudaFuncSetAttribute(flash_kernel, cudaFuncAttributeMaxDynamicSharedMemorySize, FL_SMEM_BYTES);
    cudaFuncSetAttribute(gemm_f16,    cudaFuncAttributeMaxDynamicSharedMemorySize, GEMM_SMEM_BYTES);

    // 0) weight prep: transpose + fp16 convert (64x64 tiles)
    transcvt<<<dim3(32, 32, 1), 256>>>(wq, wqkvT, HDIM, NHEAD*HEADD, 0, 0);
    transcvt<<<dim3(32,  8, 1), 256>>>(wk, wqkvT + (long long)NHEAD*HEADD*HDIM, HDIM, NKVH*HEADD, 0, 0);
    transcvt<<<dim3(32,  8, 1), 256>>>(wv, wqkvT + (long long)(NHEAD+NKVH)*HEADD*HDIM, HDIM, NKVH*HEADD, 0, 0);
    transcvt<<<dim3(32, 32, 1), 256>>>(wo, woT, HDIM, HDIM, 0, 0);
    transcvt<<<dim3(32, 64, NEXP), 256>>>(w1, w13T, HDIM, FFN,
                                          (long long)HDIM*FFN, (long long)2*FFN*HDIM);
    transcvt<<<dim3(32, 64, NEXP), 256>>>(w3, w13T + (long long)FFN*HDIM, HDIM, FFN,
                                          (long long)HDIM*FFN, (long long)2*FFN*HDIM);
    transcvt<<<dim3(64, 32, NEXP), 256>>>(w2, w2T, FFN, HDIM,
                                          (long long)FFN*HDIM, (long long)HDIM*FFN);
    concat_bias<<<(QKVN+255)/256, 256>>>(bq, bk, bv, bqkv);

    // 1) LN1 (half only)
    ln_kernel<<<NTOK, 256>>>(hidden, ln1w, ln1b, nullptr, xln1h);

    // 2) fused QKV projection -> half qkv
    gemm_f16<<<dim3(QKVN/256, NTOK/128, 1), 256, GEMM_SMEM_BYTES>>>(
        xln1h, HDIM, wqkvT, 0, nullptr, qkvh, QKVN, bqkv, nullptr,
        NTOK, QKVN, HDIM, nullptr, nullptr, nullptr);

    // 3) RoPE
    {
        int total = NTOK*(NHEAD+NKVH)*64;
        rope_kernel<<<(total+255)/256, 256>>>(qkvh, posids);
    }

    // 4) flash attention -> half attn
    flash_kernel<<<dim3(SEQ/64, BATCH*NHEAD), 256, FL_SMEM_BYTES>>>(qkvh, amask, attnh);

    // 5) O projection + residual -> float h
    gemm_f16<<<dim3(HDIM/256, NTOK/128, 1), 256, GEMM_SMEM_BYTES>>>(
        attnh, NHEAD*HEADD, woT, 0, hbuf, nullptr, HDIM, bo, hidden,
        NTOK, HDIM, NHEAD*HEADD, nullptr, nullptr, nullptr);

    // 6) LN2: raw float (gate) + half (GEMM A)
    ln_kernel<<<NTOK, 256>>>(hbuf, ln2w, ln2b, xln2, xln2h);
    // 7) gate + top2 from raw xln2
    gate_kernel<<<NTOK, 256>>>(xln2, gatew, e01, w01);
    // 8) routing
    cudaMemsetAsync(counts, 0, NEXP*sizeof(int));
    route_count_kernel<<<(NTOK+255)/256, 256>>>(e01, counts, pos01);
    route_offset_kernel<<<1, 32>>>(counts, offsets);
    route_scatter_kernel<<<(NTOK+255)/256, 256>>>(e01, pos01, offsets, toklist, slot01);

    // 9) expert up-projections: h13[slot] = x[tok] @ [w1|w3]^T(e)  -> fp16
    gemm_f16<<<dim3(2*FFN/256, NTOK/128, NEXP), 256, GEMM_SMEM_BYTES>>>(
        xln2h, HDIM, w13T, (long long)2*FFN*HDIM, nullptr, h13h, 2*FFN, nullptr, nullptr,
        NTOK, 2*FFN, HDIM, toklist, counts, offsets);

    // 10) act = silu(h1)*h3 -> half
    silu_mul_kernel<<<8192, 256>>>(h13h, acth);

    // 11) eo = act @ w2(e)
    gemm_f16<<<dim3(HDIM/256, NTOK/128, NEXP), 256, GEMM_SMEM_BYTES>>>(
        acth, FFN, w2T, (long long)HDIM*FFN, eo, nullptr, HDIM, nullptr, nullptr,
        NTOK, HDIM, FFN, nullptr, counts, offsets);

    // 12) out = h + top2-weighted expert outputs
    combine_kernel<<<(int)(((long long)NTOK*HDIM + 255)/256), 256>>>(hbuf, eo, slot01, w01, out);
}

// round 8
// speedup vs baseline: 1.6913x; 1.0600x over previous
#include <cuda_runtime.h>
#include <cuda_fp16.h>
#include <math.h>
#include <stdint.h>

// ---------------- problem constants ----------------
#define BATCH 2
#define SEQ   1024
#define HDIM  2048
#define NHEAD 16
#define NKVH  4
#define HEADD 128
#define FFN   4096
#define NEXP  8
#define NTOK  (BATCH*SEQ)          // 2048
#define QKVN  (NHEAD*HEADD + 2*NKVH*HEADD)   // 3072
#define NSLOT (2*NTOK)             // 4096
#define LNEPS 1e-5f

// ---------------- device scratch ----------------
__device__ __half g_xln1h[NTOK*HDIM];
__device__ __half g_qkvh [NTOK*QKVN];
__device__ __half g_attnh[NTOK*NHEAD*HEADD];
__device__ float  g_h    [NTOK*HDIM];
__device__ float  g_xln2 [NTOK*HDIM];     // raw fp32 (gate)
__device__ __half g_xln2h[NTOK*HDIM];
__device__ __half g_h13h [NSLOT*2*FFN];
__device__ __half g_acth [NSLOT*FFN];
__device__ float  g_eo   [NSLOT*HDIM];
// fp16 weights, ORIGINAL [K][N] layout (no transpose)
__device__ __half g_wqh [HDIM*NHEAD*HEADD];
__device__ __half g_wkh [HDIM*NKVH*HEADD];
__device__ __half g_wvh [HDIM*NKVH*HEADD];
__device__ __half g_woh [HDIM*HDIM];
__device__ __half g_w1h [NEXP*HDIM*FFN];
__device__ __half g_w3h [NEXP*HDIM*FFN];
__device__ __half g_w2h [NEXP*FFN*HDIM];
__device__ float  g_bqkv[QKVN];
// routing
__device__ int   g_e01 [NTOK*2];
__device__ float g_w01 [NTOK*2];
__device__ int   g_pos01[NTOK*2];
__device__ int   g_counts[NEXP];
__device__ int   g_offsets[NEXP];
__device__ int   g_toklist[NSLOT];
__device__ int   g_slot01[NTOK*2];

// ---------------- helpers ----------------
__device__ __forceinline__ uint32_t tf32u(float x){
    uint32_t u; asm("cvt.rna.tf32.f32 %0, %1;" : "=r"(u) : "f"(x));
    return u;
}
__device__ __forceinline__ float tf32f(float x){ return __uint_as_float(tf32u(x)); }

__device__ __forceinline__ void mma_tf32(float* c, const uint32_t* a, const uint32_t* b){
    asm volatile(
      "mma.sync.aligned.m16n8k8.row.col.f32.tf32.tf32.f32 "
      "{%0,%1,%2,%3}, {%4,%5,%6,%7}, {%8,%9}, {%0,%1,%2,%3};\n"
      : "+f"(c[0]), "+f"(c[1]), "+f"(c[2]), "+f"(c[3])
      : "r"(a[0]), "r"(a[1]), "r"(a[2]), "r"(a[3]), "r"(b[0]), "r"(b[1]));
}
__device__ __forceinline__ void mma_f16(float* c, const uint32_t* a, const uint32_t* b){
    asm volatile(
      "mma.sync.aligned.m16n8k16.row.col.f32.f16.f16.f32 "
      "{%0,%1,%2,%3}, {%4,%5,%6,%7}, {%8,%9}, {%0,%1,%2,%3};\n"
      : "+f"(c[0]), "+f"(c[1]), "+f"(c[2]), "+f"(c[3])
      : "r"(a[0]), "r"(a[1]), "r"(a[2]), "r"(a[3]), "r"(b[0]), "r"(b[1]));
}
__device__ __forceinline__ void ldsm_x4_t(uint32_t& r0, uint32_t& r1, uint32_t& r2, uint32_t& r3,
                                          uint32_t addr){
    asm volatile("ldmatrix.sync.aligned.m8n8.x4.trans.shared.b16 {%0,%1,%2,%3}, [%4];"
                 : "=r"(r0), "=r"(r1), "=r"(r2), "=r"(r3) : "r"(addr));
}

__device__ __forceinline__ void cpa16h(__half* smem, const __half* gmem, bool pred){
    uint32_t s = (uint32_t)__cvta_generic_to_shared(smem);
    int sz = pred ? 16 : 0;
    asm volatile("cp.async.cg.shared.global [%0], [%1], 16, %2;\n"
                 :: "r"(s), "l"(gmem), "r"(sz));
}
#define CP_COMMIT() asm volatile("cp.async.commit_group;\n")
template<int N> __device__ __forceinline__ void cp_wait(){
    asm volatile("cp.async.wait_group %0;\n" :: "n"(N));
}

__device__ __forceinline__ float block_sum_256(float v){
    __shared__ float red[8];
    __shared__ float total;
    #pragma unroll
    for (int o = 16; o; o >>= 1) v += __shfl_xor_sync(0xffffffffu, v, o);
    if ((threadIdx.x & 31) == 0) red[threadIdx.x >> 5] = v;
    __syncthreads();
    if (threadIdx.x == 0){
        float s = 0.f;
        #pragma unroll
        for (int i = 0; i < 8; i++) s += red[i];
        total = s;
    }
    __syncthreads();
    float r = total;
    __syncthreads();
    return r;
}

// ---------------- streaming fp32 -> fp16 convert (no transpose) ----------------
__global__ __launch_bounds__(256)
void cvt16(const float4* __restrict__ src, uint4* __restrict__ dst, long long n8){
    for (long long i = blockIdx.x*256LL + threadIdx.x; i < n8; i += gridDim.x*256LL){
        float4 v0 = src[2*i], v1 = src[2*i+1];
        __half2 a = __floats2half2_rn(v0.x, v0.y);
        __half2 b = __floats2half2_rn(v0.z, v0.w);
        __half2 c = __floats2half2_rn(v1.x, v1.y);
        __half2 d = __floats2half2_rn(v1.z, v1.w);
        uint4 o;
        o.x = *(uint32_t*)&a; o.y = *(uint32_t*)&b;
        o.z = *(uint32_t*)&c; o.w = *(uint32_t*)&d;
        dst[i] = o;
    }
}

__global__ void concat_bias(const float* bq, const float* bk, const float* bv, float* dst){
    int i = blockIdx.x*256 + threadIdx.x;
    if (i < NHEAD*HEADD) dst[i] = bq[i];
    else if (i < NHEAD*HEADD + NKVH*HEADD) dst[i] = bk[i - NHEAD*HEADD];
    else if (i < QKVN) dst[i] = bv[i - NHEAD*HEADD - NKVH*HEADD];
}

// ---------------- LayerNorm: optional raw float + fp16 outputs ----------------
__global__ __launch_bounds__(256)
void ln_kernel(const float* __restrict__ x, const float* __restrict__ w,
               const float* __restrict__ b,
               float* __restrict__ yraw, __half* __restrict__ yh){
    long long row = blockIdx.x;
    const float* xr = x + row * HDIM;
    float v[8]; float s = 0.f;
    #pragma unroll
    for (int i = 0; i < 8; i++){ v[i] = xr[threadIdx.x + 256*i]; s += v[i]; }
    float mean = block_sum_256(s) * (1.f/HDIM);
    float ss = 0.f;
    #pragma unroll
    for (int i = 0; i < 8; i++){ float d = v[i]-mean; ss += d*d; }
    float var = block_sum_256(ss) * (1.f/HDIM);
    float rstd = rsqrtf(var + LNEPS);
    #pragma unroll
    for (int i = 0; i < 8; i++){
        int c = threadIdx.x + 256*i;
        float o = (v[i]-mean)*rstd*w[c] + b[c];
        if (yraw) yraw[row*HDIM + c] = o;
        yh[row*HDIM + c] = __float2half(o);
    }
}

// ---------------- fp16 GEMM: B in natural [K][N], fragments via ldmatrix.trans ----------------
struct GemmSegs {
    int end[3];             // cumulative global-N boundaries
    const __half* B[3];     // base pointers (expert 0)
    int ldb[3];             // row stride (halves) of each B
};

#define GA_STG (128*40)           // halves per A stage
#define GB_STG (32*264)           // halves per B stage (32 k-rows x (256+8))
#define GB_BASE (3*GA_STG)
#define GEMM_SMEM_BYTES ((GB_BASE + 3*GB_STG)*2)

__global__ __launch_bounds__(256)
void gemm_f16(const __half* __restrict__ A, int lda,
              GemmSegs segs, long long bStride,
              float* __restrict__ Cf, __half* __restrict__ Ch, int ldc,
              const float* __restrict__ bias, const float* __restrict__ resid,
              int M, int K,
              const int* __restrict__ rowidx,
              const int* __restrict__ counts,
              const int* __restrict__ offsets)
{
    extern __shared__ __half hsm[];
#define ASH(st, r, c) hsm[(st)*GA_STG + (r)*40 + (c)]
#define BSH(st, k, c) hsm[GB_BASE + (st)*GB_STG + (k)*264 + (c)]

    int e = blockIdx.z;
    int rowStart = 0, Mm = M;
    if (counts){ Mm = counts[e]; rowStart = offsets[e]; }
    int mbase = blockIdx.y * 128;
    if (mbase >= Mm) return;
    int nbase = blockIdx.x * 256;

    int s = 0;
    if (nbase >= segs.end[0]) s = 1;
    if (nbase >= segs.end[1]) s = 2;
    int segStart = (s == 0) ? 0 : segs.end[s-1];
    int ln = nbase - segStart;
    const __half* Bp = segs.B[s] + (long long)e * bStride + ln;
    int ldb = segs.ldb[s];

    int tid  = threadIdx.x;
    int lane = tid & 31, wid = tid >> 5;
    int warpM = wid >> 2, warpN = wid & 3;
    int g = lane >> 2, t4 = lane & 3;

    // A loads
    int ar = tid >> 1, hsel = tid & 1;
    bool aval = (mbase + ar < Mm);
    int arow = 0;
    if (aval) arow = rowidx ? rowidx[rowStart + mbase + ar] : (rowStart + mbase + ar);
    const __half* aptr = A + (long long)arow * lda + hsel*16;
    // B loads: 32 k-rows x 32 chunks(16B); thread: row tid>>3, chunks (tid&7)+8i
    int brow = tid >> 3, bch = tid & 7;

    // ldmatrix per-lane offset (bytes within a B stage)
    int k_off = (lane & 7) + 8*((lane >> 3) & 1);
    int c_off = warpN*64 + 8*((lane >> 4) & 1);
    uint32_t bsm0 = (uint32_t)__cvta_generic_to_shared(hsm) + GB_BASE*2
                  + (uint32_t)(k_off*264 + c_off)*2;

    float acc[32][4];
    #pragma unroll
    for (int i = 0; i < 32; i++)
        #pragma unroll
        for (int j = 0; j < 4; j++) acc[i][j] = 0.f;

    int nk = K >> 5;

#define GEMM_ISSUE(KT, ST) do {                                               \
        cpa16h(&ASH(ST, ar, hsel*16),     aptr + (KT)*32,     aval);          \
        cpa16h(&ASH(ST, ar, hsel*16 + 8), aptr + (KT)*32 + 8, aval);          \
        _Pragma("unroll")                                                     \
        for (int i = 0; i < 4; i++){                                          \
            int c8 = (bch + 8*i)*8;                                           \
            cpa16h(&BSH(ST, brow, c8),                                        \
                   Bp + (long long)((KT)*32 + brow)*ldb + c8, true);          \
        }                                                                     \
    } while(0)

    GEMM_ISSUE(0, 0); CP_COMMIT();
    GEMM_ISSUE(1, 1); CP_COMMIT();

    int cur = 0;
    for (int kt = 0; kt < nk; ++kt){
        if (kt + 1 < nk) cp_wait<1>(); else cp_wait<0>();
        __syncthreads();
        if (kt + 2 < nk){
            int nxt = cur + 2; if (nxt >= 3) nxt -= 3;
            GEMM_ISSUE(kt+2, nxt); CP_COMMIT();
        }

        #pragma unroll
        for (int ks = 0; ks < 2; ++ks){
            int k0 = ks*16 + 2*t4;
            uint32_t af[4][4], bf[8][2];
            #pragma unroll
            for (int ma = 0; ma < 4; ma++){
                int r = warpM*64 + ma*16;
                af[ma][0] = *(const uint32_t*)&ASH(cur, r+g  , k0    );
                af[ma][1] = *(const uint32_t*)&ASH(cur, r+g+8, k0    );
                af[ma][2] = *(const uint32_t*)&ASH(cur, r+g  , k0 + 8);
                af[ma][3] = *(const uint32_t*)&ASH(cur, r+g+8, k0 + 8);
            }
            uint32_t badr = bsm0 + (uint32_t)cur*(GB_STG*2) + (uint32_t)(ks*16*264*2);
            #pragma unroll
            for (int p = 0; p < 4; p++){
                ldsm_x4_t(bf[2*p][0], bf[2*p][1], bf[2*p+1][0], bf[2*p+1][1],
                          badr + (uint32_t)(p*16*2));
            }
            #pragma unroll
            for (int ma = 0; ma < 4; ma++)
                #pragma unroll
                for (int na = 0; na < 8; na++)
                    mma_f16(acc[ma*8+na], af[ma], bf[na]);
        }
        cur = cur + 1; if (cur >= 3) cur -= 3;
    }

    #pragma unroll
    for (int ma = 0; ma < 4; ma++){
        #pragma unroll
        for (int na = 0; na < 8; na++){
            float* a4 = acc[ma*8+na];
            #pragma unroll
            for (int half_ = 0; half_ < 2; half_++){
                int lrow = warpM*64 + ma*16 + g + (half_ ? 8 : 0);
                int gcol = nbase + warpN*64 + na*8 + 2*t4;
                int gr = mbase + lrow;
                if (gr < Mm){
                    long long orow = rowStart + gr;
                    float v0 = a4[half_*2+0];
                    float v1 = a4[half_*2+1];
                    if (bias){ v0 += bias[gcol]; v1 += bias[gcol+1]; }
                    if (resid){
                        const float* rp = &resid[orow*(long long)ldc + gcol];
                        v0 += rp[0]; v1 += rp[1];
                    }
                    if (Cf){
                        *(float2*)&Cf[orow*(long long)ldc + gcol] = make_float2(v0, v1);
                    } else {
                        *(__half2*)&Ch[orow*(long long)ldc + gcol] = __floats2half2_rn(v0, v1);
                    }
                }
            }
        }
    }
#undef ASH
#undef BSH
#undef GEMM_ISSUE
}

// ---------------- RoPE (in place on packed half qkv) ----------------
__global__ __launch_bounds__(256)
void rope_kernel(__half* __restrict__ qkv, const int* __restrict__ pos_ids){
    int idx = blockIdx.x*256 + threadIdx.x;
    const int total = NTOK*(NHEAD+NKVH)*64;
    if (idx >= total) return;
    int j    = idx & 63;
    int rest = idx >> 6;
    int head = rest % (NHEAD+NKVH);
    int t    = rest / (NHEAD+NKVH);
    __half* p;
    if (head < NHEAD) p = qkv + (long long)t*QKVN + head*HEADD;
    else              p = qkv + (long long)t*QKVN + NHEAD*HEADD + (head-NHEAD)*HEADD;
    double inv = exp((double)j * -0.21586735246819178); // -ln(1e6)/64
    float th = (float)pos_ids[t] * (float)inv;
    float sn, cs; sincosf(th, &sn, &cs);
    float x0 = __half2float(p[j]), x1 = __half2float(p[j+64]);
    p[j]    = __float2half(x0*cs - x1*sn);
    p[j+64] = __float2half(x1*cs + x0*sn);
}

// ---------------- tensor-core flash attention (tf32 math, half I/O) ----------------
#define FKT 32
#define FL_QS   0
#define FL_KS   (FL_QS + 64*132)
#define FL_VS   (FL_KS + FKT*132)
#define FL_PS   (FL_VS + FKT*136)
#define FL_MROW (FL_PS + 64*36)
#define FL_LROW (FL_MROW + 64)
#define FL_SROW (FL_LROW + 64)
#define FL_MK   (FL_SROW + 64)
#define FL_SMEM_FLOATS (FL_MK + FKT)
#define FL_SMEM_BYTES  (FL_SMEM_FLOATS*4)

__global__ __launch_bounds__(256, 2)
void flash_kernel(const __half* __restrict__ qkv, const int* __restrict__ amask,
                  __half* __restrict__ O)
{
    extern __shared__ float sm[];
    float* Qs = sm + FL_QS;
    float* Ks = sm + FL_KS;
    float* Vs = sm + FL_VS;
    float* Ps = sm + FL_PS;
    float* mrow = sm + FL_MROW;
    float* lrow = sm + FL_LROW;
    float* srow = sm + FL_SROW;
    int*   mk   = (int*)(sm + FL_MK);

    int qt = blockIdx.x;
    int bh = blockIdx.y;
    int b  = bh >> 4, h = bh & 15;
    int kvh = h >> 2;
    int tid = threadIdx.x;
    int lane = tid & 31, wid = tid >> 5;
    int g = lane >> 2, t4 = lane & 3;
    int mS = wid & 3;
    int nH = wid >> 2;

    for (int e2 = tid; e2 < 64*64; e2 += 256){
        int row = e2 >> 6; int d2 = (e2 & 63)*2;
        __half2 v = *(const __half2*)&qkv[(long long)(b*SEQ + qt*64 + row)*QKVN + h*HEADD + d2];
        Qs[row*132 + d2    ] = __half2float(v.x);
        Qs[row*132 + d2 + 1] = __half2float(v.y);
    }
    if (tid < 64){ mrow[tid] = -1e30f; lrow[tid] = 0.f; }

    float oacc[8][4];
    #pragma unroll
    for (int i = 0; i < 8; i++)
        #pragma unroll
        for (int j = 0; j < 4; j++) oacc[i][j] = 0.f;

    const float iscale = 0.08838834764831843f;

    int nkt = 2*qt + 2;
    for (int kt = 0; kt < nkt; ++kt){
        __syncthreads();
        for (int e2 = tid; e2 < FKT*64; e2 += 256){
            int kk = e2 >> 6; int d2 = (e2 & 63)*2;
            long long base = (long long)(b*SEQ + kt*FKT + kk)*QKVN + NHEAD*HEADD + kvh*HEADD;
            __half2 kv2 = *(const __half2*)&qkv[base + d2];
            Ks[kk*132 + d2    ] = __half2float(kv2.x);
            Ks[kk*132 + d2 + 1] = __half2float(kv2.y);
            __half2 vv2 = *(const __half2*)&qkv[base + NKVH*HEADD + d2];
            Vs[kk*136 + d2    ] = __half2float(vv2.x);
            Vs[kk*136 + d2 + 1] = __half2float(vv2.y);
        }
        if (tid < FKT) mk[tid] = amask[b*SEQ + kt*FKT + tid];
        __syncthreads();

        float sacc[2][4];
        #pragma unroll
        for (int i = 0; i < 2; i++)
            #pragma unroll
            for (int j = 0; j < 4; j++) sacc[i][j] = 0.f;
        #pragma unroll
        for (int ks = 0; ks < 16; ++ks){
            int k0 = ks*8;
            uint32_t a[4];
            int r = 16*mS;
            a[0] = __float_as_uint(Qs[(r+g  )*132 + k0+t4  ]);
            a[1] = __float_as_uint(Qs[(r+g+8)*132 + k0+t4  ]);
            a[2] = __float_as_uint(Qs[(r+g  )*132 + k0+t4+4]);
            a[3] = __float_as_uint(Qs[(r+g+8)*132 + k0+t4+4]);
            #pragma unroll
            for (int j = 0; j < 2; j++){
                int c = 16*nH + 8*j + g;
                uint32_t bfr[2];
                bfr[0] = __float_as_uint(Ks[c*132 + k0+t4  ]);
                bfr[1] = __float_as_uint(Ks[c*132 + k0+t4+4]);
                mma_tf32(sacc[j], a, bfr);
            }
        }
        #pragma unroll
        for (int j = 0; j < 2; j++){
            #pragma unroll
            for (int cr = 0; cr < 4; cr++){
                int row = 16*mS + g + ((cr >= 2) ? 8 : 0);
                int col = 16*nH + 8*j + 2*t4 + (cr & 1);
                int sq = qt*64 + row, sk = kt*FKT + col;
                float vv = sacc[j][cr]*iscale;
                if (sk > sq || mk[col] == 0) vv = -1e30f;
                Ps[row*36 + col] = vv;
            }
        }
        __syncthreads();

        if (tid < 64){
            int r = tid;
            float mo = mrow[r], mx = mo;
            #pragma unroll 8
            for (int kk = 0; kk < FKT; kk++) mx = fmaxf(mx, Ps[r*36+kk]);
            float sc = __expf(mo - mx);
            float ssum = 0.f;
            #pragma unroll 8
            for (int kk = 0; kk < FKT; kk++){
                float p = __expf(Ps[r*36+kk] - mx);
                ssum += p;
                Ps[r*36+kk] = tf32f(p);
            }
            lrow[r] = lrow[r]*sc + ssum;
            mrow[r] = mx;
            srow[r] = sc;
        }
        __syncthreads();

        {
            float sc0 = srow[16*mS + g];
            float sc1 = srow[16*mS + g + 8];
            #pragma unroll
            for (int j = 0; j < 8; j++){
                oacc[j][0] *= sc0; oacc[j][1] *= sc0;
                oacc[j][2] *= sc1; oacc[j][3] *= sc1;
            }
        }
        #pragma unroll
        for (int ks = 0; ks < 4; ++ks){
            int k0 = ks*8;
            uint32_t a[4];
            int r = 16*mS;
            a[0] = __float_as_uint(Ps[(r+g  )*36 + k0+t4  ]);
            a[1] = __float_as_uint(Ps[(r+g+8)*36 + k0+t4  ]);
            a[2] = __float_as_uint(Ps[(r+g  )*36 + k0+t4+4]);
            a[3] = __float_as_uint(Ps[(r+g+8)*36 + k0+t4+4]);
            #pragma unroll
            for (int j = 0; j < 8; j++){
                int c = 64*nH + 8*j + g;
                uint32_t bfr[2];
                bfr[0] = __float_as_uint(Vs[(k0+t4  )*136 + c]);
                bfr[1] = __float_as_uint(Vs[(k0+t4+4)*136 + c]);
                mma_tf32(oacc[j], a, bfr);
            }
        }
    }

    #pragma unroll
    for (int j = 0; j < 8; j++){
        #pragma unroll
        for (int half_ = 0; half_ < 2; half_++){
            int row = 16*mS + g + (half_ ? 8 : 0);
            int col = 64*nH + 8*j + 2*t4;
            int sq = qt*64 + row;
            float inv = 1.f / lrow[row];
            __half2 o2 = __floats2half2_rn(oacc[j][half_*2+0]*inv, oacc[j][half_*2+1]*inv);
            *(__half2*)&O[(((long long)(b*SEQ + sq))*NHEAD + h)*HEADD + col] = o2;
        }
    }
}

// ---------------- gate + top2 (raw fp32) ----------------
__global__ __launch_bounds__(256)
void gate_kernel(const float* __restrict__ x2, const float* __restrict__ gw,
                 int* __restrict__ e01, float* __restrict__ w01){
    long long t = blockIdx.x;
    const float* xr = x2 + t*HDIM;
    float part[NEXP];
    #pragma unroll
    for (int e = 0; e < NEXP; e++) part[e] = 0.f;
    for (int hh = threadIdx.x; hh < HDIM; hh += 256){
        float xv = xr[hh];
        const float* gp = gw + (long long)hh*NEXP;
        #pragma unroll
        for (int e = 0; e < NEXP; e++) part[e] += xv*gp[e];
    }
    __shared__ float red[8][NEXP];
    #pragma unroll
    for (int e = 0; e < NEXP; e++){
        float v = part[e];
        #pragma unroll
        for (int o = 16; o; o >>= 1) v += __shfl_xor_sync(0xffffffffu, v, o);
        if ((threadIdx.x & 31) == 0) red[threadIdx.x >> 5][e] = v;
    }
    __syncthreads();
    if (threadIdx.x == 0){
        float lg[NEXP];
        #pragma unroll
        for (int e = 0; e < NEXP; e++){
            float s = 0.f;
            #pragma unroll
            for (int w8 = 0; w8 < 8; w8++) s += red[w8][e];
            lg[e] = s;
        }
        int b0 = 0;
        #pragma unroll
        for (int e = 1; e < NEXP; e++) if (lg[e] > lg[b0]) b0 = e;
        int b1 = -1;
        #pragma unroll
        for (int e = 0; e < NEXP; e++)
            if (e != b0 && (b1 < 0 || lg[e] > lg[b1])) b1 = e;
        float t0 = 1.f / (1.f + expf(lg[b1] - lg[b0]));
        e01[2*t] = b0; e01[2*t+1] = b1;
        w01[2*t] = t0; w01[2*t+1] = 1.f - t0;
    }
}

// ---------------- routing ----------------
__global__ void route_count_kernel(const int* __restrict__ e01,
                                   int* __restrict__ counts, int* __restrict__ pos01){
    int t = blockIdx.x*blockDim.x + threadIdx.x;
    if (t < NTOK){
        pos01[2*t]   = atomicAdd(&counts[e01[2*t]],   1);
        pos01[2*t+1] = atomicAdd(&counts[e01[2*t+1]], 1);
    }
}
__global__ void route_offset_kernel(const int* __restrict__ counts, int* __restrict__ offsets){
    if (threadIdx.x == 0 && blockIdx.x == 0){
        int s = 0;
        for (int e = 0; e < NEXP; e++){ offsets[e] = s; s += counts[e]; }
    }
}
__global__ void route_scatter_kernel(const int* __restrict__ e01, const int* __restrict__ pos01,
                                     const int* __restrict__ offsets,
                                     int* __restrict__ toklist, int* __restrict__ slot01){
    int t = blockIdx.x*blockDim.x + threadIdx.x;
    if (t < NTOK){
        #pragma unroll
        for (int j = 0; j < 2; j++){
            int sl = offsets[e01[2*t+j]] + pos01[2*t+j];
            toklist[sl] = t;
            slot01[2*t+j] = sl;
        }
    }
}

// ---------------- act = silu(h1)*h3 (half2 vectorized) ----------------
__global__ __launch_bounds__(256)
void silu_mul_kernel(const __half* __restrict__ h13, __half* __restrict__ act){
    long long n2 = (long long)NSLOT*FFN/2;
    for (long long i = blockIdx.x*256LL + threadIdx.x; i < n2; i += gridDim.x*256LL){
        long long slot = i >> 11;
        int f2 = (int)(i & (FFN/2 - 1));
        __half2 a = *(const __half2*)&h13[slot*(2*FFN) + f2*2];
        __half2 c = *(const __half2*)&h13[slot*(2*FFN) + FFN + f2*2];
        float v0 = __half2float(a.x), v1 = __half2float(a.y);
        float u0 = __half2float(c.x), u1 = __half2float(c.y);
        float r0 = v0 / (1.f + expf(-v0)) * u0;
        float r1 = v1 / (1.f + expf(-v1)) * u1;
        *(__half2*)&act[i*2] = __floats2half2_rn(r0, r1);
    }
}

// ---------------- final combine ----------------
__global__ __launch_bounds__(256)
void combine_kernel(const float* __restrict__ h, const float* __restrict__ eo,
                    const int* __restrict__ slot01, const float* __restrict__ w01,
                    float* __restrict__ out){
    long long idx = blockIdx.x*256LL + threadIdx.x;
    if (idx >= (long long)NTOK*HDIM) return;
    int t = (int)(idx >> 11);
    int c = (int)(idx & 2047);
    float v = h[idx];
    v += w01[2*t]   * eo[(long long)slot01[2*t]  *HDIM + c];
    v += w01[2*t+1] * eo[(long long)slot01[2*t+1]*HDIM + c];
    out[idx] = v;
}

// ---------------- launch ----------------
extern "C" void kernel_launch(void* const* d_in, const int* in_sizes, int n_in,
                              void* d_out, int out_size){
    const float* hidden = (const float*)d_in[0];
    const int*   amask  = (const int*)  d_in[1];
    const int*   posids = (const int*)  d_in[2];
    const float* ln1w = (const float*)d_in[3];
    const float* ln1b = (const float*)d_in[4];
    const float* ln2w = (const float*)d_in[5];
    const float* ln2b = (const float*)d_in[6];
    const float* wq = (const float*)d_in[7];
    const float* bq = (const float*)d_in[8];
    const float* wk = (const float*)d_in[9];
    const float* bk = (const float*)d_in[10];
    const float* wv = (const float*)d_in[11];
    const float* bv = (const float*)d_in[12];
    const float* wo = (const float*)d_in[13];
    const float* bo = (const float*)d_in[14];
    const float* gatew = (const float*)d_in[15];
    const float* w1 = (const float*)d_in[16];
    const float* w2 = (const float*)d_in[17];
    const float* w3 = (const float*)d_in[18];
    float* out = (float*)d_out;

    __half *xln1h, *qkvh, *attnh, *xln2h, *h13h, *acth;
    __half *wqh, *wkh, *wvh, *woh, *w1h, *w3h, *w2h;
    float *hbuf, *xln2, *eo, *w01, *bqkv;
    int *e01, *pos01, *counts, *offsets, *toklist, *slot01;
    cudaGetSymbolAddress((void**)&xln1h, g_xln1h);
    cudaGetSymbolAddress((void**)&qkvh, g_qkvh);
    cudaGetSymbolAddress((void**)&attnh, g_attnh);
    cudaGetSymbolAddress((void**)&hbuf, g_h);
    cudaGetSymbolAddress((void**)&xln2, g_xln2);
    cudaGetSymbolAddress((void**)&xln2h, g_xln2h);
    cudaGetSymbolAddress((void**)&h13h, g_h13h);
    cudaGetSymbolAddress((void**)&acth, g_acth);
    cudaGetSymbolAddress((void**)&eo, g_eo);
    cudaGetSymbolAddress((void**)&wqh, g_wqh);
    cudaGetSymbolAddress((void**)&wkh, g_wkh);
    cudaGetSymbolAddress((void**)&wvh, g_wvh);
    cudaGetSymbolAddress((void**)&woh, g_woh);
    cudaGetSymbolAddress((void**)&w1h, g_w1h);
    cudaGetSymbolAddress((void**)&w3h, g_w3h);
    cudaGetSymbolAddress((void**)&w2h, g_w2h);
    cudaGetSymbolAddress((void**)&bqkv, g_bqkv);
    cudaGetSymbolAddress((void**)&e01, g_e01);
    cudaGetSymbolAddress((void**)&w01, g_w01);
    cudaGetSymbolAddress((void**)&pos01, g_pos01);
    cudaGetSymbolAddress((void**)&counts, g_counts);
    cudaGetSymbolAddress((void**)&offsets, g_offsets);
    cudaGetSymbolAddress((void**)&toklist, g_toklist);
    cudaGetSymbolAddress((void**)&slot01, g_slot01);

    cudaFuncSetAttribute(flash_kernel, cudaFuncAttributeMaxDynamicSharedMemorySize, FL_SMEM_BYTES);
    cudaFuncSetAttribute(gemm_f16,    cudaFuncAttributeMaxDynamicSharedMemorySize, GEMM_SMEM_BYTES);

    // 0) weight prep: pure streaming fp32 -> fp16 (no transpose)
    {
        auto cvt = [&](const float* s, __half* d, long long n){
            long long n8 = n >> 3;
            int blocks = (int)((n8 + 255) / 256);
            if (blocks > 32768) blocks = 32768;
            cvt16<<<blocks, 256>>>((const float4*)s, (uint4*)d, n8);
        };
        cvt(wq, wqh, (long long)HDIM*NHEAD*HEADD);
        cvt(wk, wkh, (long long)HDIM*NKVH*HEADD);
        cvt(wv, wvh, (long long)HDIM*NKVH*HEADD);
        cvt(wo, woh, (long long)HDIM*HDIM);
        cvt(w1, w1h, (long long)NEXP*HDIM*FFN);
        cvt(w3, w3h, (long long)NEXP*HDIM*FFN);
        cvt(w2, w2h, (long long)NEXP*FFN*HDIM);
    }
    concat_bias<<<(QKVN+255)/256, 256>>>(bq, bk, bv, bqkv);

    // 1) LN1 (half only)
    ln_kernel<<<NTOK, 256>>>(hidden, ln1w, ln1b, nullptr, xln1h);

    // 2) fused QKV projection -> half qkv
    {
        GemmSegs sg;
        sg.end[0] = NHEAD*HEADD; sg.end[1] = NHEAD*HEADD + NKVH*HEADD; sg.end[2] = QKVN;
        sg.B[0] = wqh; sg.B[1] = wkh; sg.B[2] = wvh;
        sg.ldb[0] = NHEAD*HEADD; sg.ldb[1] = NKVH*HEADD; sg.ldb[2] = NKVH*HEADD;
        gemm_f16<<<dim3(QKVN/256, NTOK/128, 1), 256, GEMM_SMEM_BYTES>>>(
            xln1h, HDIM, sg, 0, nullptr, qkvh, QKVN, bqkv, nullptr,
            NTOK, HDIM, nullptr, nullptr, nullptr);
    }

    // 3) RoPE
    {
        int total = NTOK*(NHEAD+NKVH)*64;
        rope_kernel<<<(total+255)/256, 256>>>(qkvh, posids);
    }

    // 4) flash attention -> half attn
    flash_kernel<<<dim3(SEQ/64, BATCH*NHEAD), 256, FL_SMEM_BYTES>>>(qkvh, amask, attnh);

    // 5) O projection + residual -> float h
    {
        GemmSegs sg;
        sg.end[0] = HDIM; sg.end[1] = HDIM; sg.end[2] = HDIM;
        sg.B[0] = woh; sg.B[1] = woh; sg.B[2] = woh;
        sg.ldb[0] = HDIM; sg.ldb[1] = HDIM; sg.ldb[2] = HDIM;
        gemm_f16<<<dim3(HDIM/256, NTOK/128, 1), 256, GEMM_SMEM_BYTES>>>(
            attnh, NHEAD*HEADD, sg, 0, hbuf, nullptr, HDIM, bo, hidden,
            NTOK, NHEAD*HEADD, nullptr, nullptr, nullptr);
    }

    // 6) LN2: raw float (gate) + half (GEMM A)
    ln_kernel<<<NTOK, 256>>>(hbuf, ln2w, ln2b, xln2, xln2h);
    // 7) gate + top2 from raw xln2
    gate_kernel<<<NTOK, 256>>>(xln2, gatew, e01, w01);
    // 8) routing
    cudaMemsetAsync(counts, 0, NEXP*sizeof(int));
    route_count_kernel<<<(NTOK+255)/256, 256>>>(e01, counts, pos01);
    route_offset_kernel<<<1, 32>>>(counts, offsets);
    route_scatter_kernel<<<(NTOK+255)/256, 256>>>(e01, pos01, offsets, toklist, slot01);

    // 9) expert up-projections: h13[slot] = x[tok] @ [w1 | w3](e) -> fp16
    {
        GemmSegs sg;
        sg.end[0] = FFN; sg.end[1] = 2*FFN; sg.end[2] = 2*FFN;
        sg.B[0] = w1h; sg.B[1] = w3h; sg.B[2] = w3h;
        sg.ldb[0] = FFN; sg.ldb[1] = FFN; sg.ldb[2] = FFN;
        gemm_f16<<<dim3(2*FFN/256, NTOK/128, NEXP), 256, GEMM_SMEM_BYTES>>>(
            xln2h, HDIM, sg, (long long)HDIM*FFN, nullptr, h13h, 2*FFN, nullptr, nullptr,
            NTOK, HDIM, toklist, counts, offsets);
    }

    // 10) act = silu(h1)*h3 -> half
    silu_mul_kernel<<<8192, 256>>>(h13h, acth);

    // 11) eo = act @ w2(e)
    {
        GemmSegs sg;
        sg.end[0] = HDIM; sg.end[1] = HDIM; sg.end[2] = HDIM;
        sg.B[0] = w2h; sg.B[1] = w2h; sg.B[2] = w2h;
        sg.ldb[0] = HDIM; sg.ldb[1] = HDIM; sg.ldb[2] = HDIM;
        gemm_f16<<<dim3(HDIM/256, NTOK/128, NEXP), 256, GEMM_SMEM_BYTES>>>(
            acth, FFN, sg, (long long)FFN*HDIM, eo, nullptr, HDIM, nullptr, nullptr,
            NTOK, FFN, nullptr, counts, offsets);
    }

    // 12) out = h + top2-weighted expert outputs
    combine_kernel<<<(int)(((long long)NTOK*HDIM + 255)/256), 256>>>(hbuf, eo, slot01, w01, out);
}